// round 5
// baseline (speedup 1.0000x reference)
#include <cuda_runtime.h>
#include <cuda_bf16.h>
#include <cstdint>

// ---------------- problem constants ----------------
constexpr int CH = 128, HEADS = 4, HD = 32, NTOK = 64;
constexpr int NWIN = 4096;
constexpr long long MROWS = 262144;   // 4096 windows * 64 tokens
constexpr int HID = 512;

// ---------------- scratch (static device globals) ----------------
__device__ __align__(16) float g_q   [MROWS * CH];
__device__ __align__(16) float g_k   [MROWS * CH];
__device__ __align__(16) float g_v   [MROWS * CH];
__device__ __align__(16) float g_bias[HEADS * NTOK * NTOK];
__device__ __align__(16) float g_attn[MROWS * CH];
__device__ __align__(16) float g_x1  [MROWS * CH];
__device__ __align__(16) __nv_bfloat16 g_hid[MROWS * HID];
// transposed weights [N, K]
__device__ __align__(16) float g_wqkv_t[384 * 128];
__device__ __align__(16) float g_wproj_t[128 * 128];
__device__ __align__(16) float g_w1_t  [512 * 128];
__device__ __align__(16) float g_w2_t  [128 * 512];

__device__ __forceinline__ uint32_t f2tf32(float f) {
    uint32_t u;
    asm("cvt.rna.tf32.f32 %0, %1;" : "=r"(u) : "f"(f));
    return u;
}
__device__ __forceinline__ float4 cvt4(float4 v) {
    float4 o;
    o.x = __uint_as_float(f2tf32(v.x));
    o.y = __uint_as_float(f2tf32(v.y));
    o.z = __uint_as_float(f2tf32(v.z));
    o.w = __uint_as_float(f2tf32(v.w));
    return o;
}
#define MMA_TF32(acc, a, b) \
    asm volatile("mma.sync.aligned.m16n8k8.row.col.f32.tf32.tf32.f32 " \
        "{%0,%1,%2,%3}, {%4,%5,%6,%7}, {%8,%9}, {%0,%1,%2,%3};" \
        : "+f"((acc)[0]), "+f"((acc)[1]), "+f"((acc)[2]), "+f"((acc)[3]) \
        : "r"((a)[0]), "r"((a)[1]), "r"((a)[2]), "r"((a)[3]), "r"((b)[0]), "r"((b)[1]))

// ---------------- relative position bias ----------------
__global__ void bias_kernel(const float* __restrict__ table)
{
    int q = blockIdx.x, k = threadIdx.x;
    int qd = q >> 4, qh = (q >> 2) & 3, qw = q & 3;
    int kd = k >> 4, kh = (k >> 2) & 3, kw = k & 3;
    int idx = (qh - kh + 3) * 49 + (qd - kd + 3) * 7 + (qw - kw + 3);
    #pragma unroll
    for (int h = 0; h < HEADS; h++)
        g_bias[h * 4096 + q * 64 + k] = table[idx * HEADS + h];
}

// ---------------- weight transpose: dst[N,K] = src[K,N] ----------------
__global__ void transpose_kernel(const float* __restrict__ src, float* __restrict__ dst, int K, int N)
{
    __shared__ float tile[32][33];
    int n0 = blockIdx.x * 32, k0 = blockIdx.y * 32;
    int tx = threadIdx.x, ty = threadIdx.y;
    tile[ty][tx] = src[(size_t)(k0 + ty) * N + n0 + tx];
    __syncthreads();
    dst[(size_t)(n0 + ty) * K + k0 + tx] = tile[tx][ty];
}

// ---------------- A-tile loaders (fill As[128][132] with tf32 values) ----------------
// warp-per-row LN loaders: 8 warps x 16 rows
struct Ln1ShiftLoader {
    const float *x, *sc, *bi;
    __device__ void load(float* As, int row0, int tid) const {
        int wid = tid >> 5, lane = tid & 31;
        float4 g4 = ((const float4*)sc)[lane];
        float4 b4 = ((const float4*)bi)[lane];
        #pragma unroll
        for (int i = 0; i < 16; i++) {
            int r = wid * 16 + i;
            int m = row0 + r;
            int t = m & 63, win = m >> 6;
            int b = win >> 11, widx = win & 2047;
            int wd = widx >> 8, wh = (widx >> 4) & 15, ww = widx & 15;
            int td = t >> 4, th = (t >> 2) & 3, tw = t & 3;
            int d = (wd*4 + td + 2) & 31;
            int h = (wh*4 + th + 2) & 63;
            int w = (ww*4 + tw + 2) & 63;
            float4 v = ((const float4*)(x + (size_t)(((b*32 + d)*64 + h)*64 + w) * CH))[lane];
            float s  = v.x + v.y + v.z + v.w;
            float ss = v.x*v.x + v.y*v.y + v.z*v.z + v.w*v.w;
            #pragma unroll
            for (int o = 16; o; o >>= 1) {
                s  += __shfl_xor_sync(0xffffffffu, s,  o);
                ss += __shfl_xor_sync(0xffffffffu, ss, o);
            }
            float mean = s * (1.0f/128.0f);
            float var  = ss * (1.0f/128.0f) - mean*mean;
            float rr = rsqrtf(var + 1e-6f);
            float4 o4;
            o4.x = (v.x - mean)*rr*g4.x + b4.x;
            o4.y = (v.y - mean)*rr*g4.y + b4.y;
            o4.z = (v.z - mean)*rr*g4.z + b4.z;
            o4.w = (v.w - mean)*rr*g4.w + b4.w;
            *(float4*)(As + r * 132 + lane * 4) = cvt4(o4);
        }
    }
};
struct Ln2Loader {
    const float *src, *sc, *bi;
    __device__ void load(float* As, int row0, int tid) const {
        int wid = tid >> 5, lane = tid & 31;
        float4 g4 = ((const float4*)sc)[lane];
        float4 b4 = ((const float4*)bi)[lane];
        #pragma unroll
        for (int i = 0; i < 16; i++) {
            int r = wid * 16 + i;
            float4 v = ((const float4*)(src + (size_t)(row0 + r) * CH))[lane];
            float s  = v.x + v.y + v.z + v.w;
            float ss = v.x*v.x + v.y*v.y + v.z*v.z + v.w*v.w;
            #pragma unroll
            for (int o = 16; o; o >>= 1) {
                s  += __shfl_xor_sync(0xffffffffu, s,  o);
                ss += __shfl_xor_sync(0xffffffffu, ss, o);
            }
            float mean = s * (1.0f/128.0f);
            float var  = ss * (1.0f/128.0f) - mean*mean;
            float rr = rsqrtf(var + 1e-6f);
            float4 o4;
            o4.x = (v.x - mean)*rr*g4.x + b4.x;
            o4.y = (v.y - mean)*rr*g4.y + b4.y;
            o4.z = (v.z - mean)*rr*g4.z + b4.z;
            o4.w = (v.w - mean)*rr*g4.w + b4.w;
            *(float4*)(As + r * 132 + lane * 4) = cvt4(o4);
        }
    }
};
struct PlainLoader {
    const float* src;
    __device__ void load(float* As, int row0, int tid) const {
        #pragma unroll
        for (int i = 0; i < 16; i++) {
            int idx = tid + i * 256;
            int r = idx >> 5, c = (idx & 31) * 4;
            *(float4*)(As + r * 132 + c) =
                cvt4(*(const float4*)(src + (size_t)(row0 + r) * CH + c));
        }
    }
};

// ---------------- epilogues ----------------
struct QkvEpi {
    __device__ void operator()(int m, int n, float v) const {
        int sel = n >> 7, c = n & 127;
        int head = c >> 5, e = c & 31;
        int win = m >> 6, t = m & 63;
        size_t o = (((size_t)win * HEADS + head) * NTOK + t) * HD + e;
        if (sel == 0)      g_q[o] = v * 0.17677669529663687f;
        else if (sel == 1) g_k[o] = v;
        else               g_v[o] = v;
    }
};
struct ProjEpi {
    const float* x; const float* pb;
    __device__ void operator()(int m, int n, float v) const {
        int win = m >> 6, t = m & 63;
        int b = win >> 11, widx = win & 2047;
        int wd = widx >> 8, wh = (widx >> 4) & 15, ww = widx & 15;
        int td = t >> 4, th = (t >> 2) & 3, tw = t & 3;
        int d = (wd*4 + td + 2) & 31;
        int h = (wh*4 + th + 2) & 63;
        int w = (ww*4 + tw + 2) & 63;
        size_t o = (size_t)(((b*32 + d)*64 + h)*64 + w) * CH + n;
        g_x1[o] = v + pb[n] + x[o];
    }
};
struct Mlp1Epi {
    const float* b1;
    __device__ void operator()(int m, int n, float v) const {
        float u = v + b1[n];
        float z2 = 1.5957691216057308f * (u + 0.044715f * u * u * u);
        float sig = 1.0f / (1.0f + __expf(-z2));
        g_hid[(size_t)m * HID + n] = __float2bfloat16(u * sig);
    }
};
struct Mlp2Epi {
    const float* b2; float* out;
    __device__ void operator()(int m, int n, float v) const {
        size_t o = (size_t)m * CH + n;
        out[o] = v + b2[n] + g_x1[o];
    }
};

// ---------------- single-shot K=128 tf32 GEMM with fused A-loader ----------------
// C[128 x 128] tile; full A (128x128) and B (128x128) staged once in smem.
// grid: (NTILES, ROWBLK) — x fastest so A tile / LN gather is L2-shared.
template<class ALd, class Epi>
__global__ __launch_bounds__(256, 1) void gemm_k128(ALd ald, const float* __restrict__ BT, Epi epi)
{
    extern __shared__ float sm[];
    float* As = sm;              // 128 x 132
    float* Bs = sm + 128 * 132;  // 128 x 132
    const int tid = threadIdx.x;
    const int wid = tid >> 5, lane = tid & 31;
    const int row0 = blockIdx.y * 128, col0 = blockIdx.x * 128;
    const int wm0 = (wid >> 1) * 32, wn0 = (wid & 1) * 64;
    const int g = lane >> 2, tg = lane & 3;

    // stage A (with fused LN / gather) and B
    ald.load(As, row0, tid);
    #pragma unroll
    for (int i = 0; i < 16; i++) {
        int idx = tid + i * 256;
        int r = idx >> 5, c = (idx & 31) * 4;
        *(float4*)(Bs + r * 132 + c) =
            cvt4(*(const float4*)(BT + (size_t)(col0 + r) * CH + c));
    }
    __syncthreads();

    float acc[2][8][4];
    #pragma unroll
    for (int mt = 0; mt < 2; mt++)
        #pragma unroll
        for (int nt = 0; nt < 8; nt++)
            #pragma unroll
            for (int c = 0; c < 4; c++) acc[mt][nt][c] = 0.0f;

    #pragma unroll
    for (int ks = 0; ks < 16; ks++) {
        const int kk = ks * 8;
        uint32_t a[2][4], b[8][2];
        #pragma unroll
        for (int mt = 0; mt < 2; mt++) {
            int r = wm0 + mt * 16;
            a[mt][0] = __float_as_uint(As[(r + g    ) * 132 + kk + tg    ]);
            a[mt][1] = __float_as_uint(As[(r + g + 8) * 132 + kk + tg    ]);
            a[mt][2] = __float_as_uint(As[(r + g    ) * 132 + kk + tg + 4]);
            a[mt][3] = __float_as_uint(As[(r + g + 8) * 132 + kk + tg + 4]);
        }
        #pragma unroll
        for (int nt = 0; nt < 8; nt++) {
            int n = wn0 + nt * 8 + g;
            b[nt][0] = __float_as_uint(Bs[n * 132 + kk + tg    ]);
            b[nt][1] = __float_as_uint(Bs[n * 132 + kk + tg + 4]);
        }
        #pragma unroll
        for (int mt = 0; mt < 2; mt++)
            #pragma unroll
            for (int nt = 0; nt < 8; nt++)
                MMA_TF32(acc[mt][nt], a[mt], b[nt]);
    }
    __syncthreads();

    // epilogue staging (reuse smem)
    float* st = sm;
    #pragma unroll
    for (int mt = 0; mt < 2; mt++)
        #pragma unroll
        for (int nt = 0; nt < 8; nt++) {
            int r = wm0 + mt * 16;
            int c = wn0 + nt * 8 + tg * 2;
            *(float2*)(st + (r + g    ) * 132 + c) = make_float2(acc[mt][nt][0], acc[mt][nt][1]);
            *(float2*)(st + (r + g + 8) * 132 + c) = make_float2(acc[mt][nt][2], acc[mt][nt][3]);
        }
    __syncthreads();
    #pragma unroll
    for (int i = 0; i < 64; i++) {
        int idx = tid + i * 256;
        int m = idx >> 7, n = idx & 127;
        epi(row0 + m, col0 + n, st[m * 132 + n]);
    }
}

// ---------------- K=512 pipelined GEMM with bf16 A (MLP2) ----------------
__global__ __launch_bounds__(256, 2) void gemm_mlp2(
    const __nv_bfloat16* __restrict__ A, const float* __restrict__ BT, Mlp2Epi epi)
{
    extern __shared__ float sm[];
    const int tid = threadIdx.x;
    const int wid = tid >> 5, lane = tid & 31;
    const int row0 = blockIdx.y * 128, col0 = blockIdx.x * 128;
    const int wm0 = (wid >> 1) * 32, wn0 = (wid & 1) * 64;
    const int g = lane >> 2, tg = lane & 3;
    constexpr int KTOT = 512;

    float acc[2][8][4];
    #pragma unroll
    for (int mt = 0; mt < 2; mt++)
        #pragma unroll
        for (int nt = 0; nt < 8; nt++)
            #pragma unroll
            for (int c = 0; c < 4; c++) acc[mt][nt][c] = 0.0f;

    float4 ra[4], rb[4];
    auto loadG = [&](int kc) {
        const __nv_bfloat16* pA = A + (size_t)row0 * KTOT + kc * 32;
        const float* pB = BT + (size_t)col0 * KTOT + kc * 32;
        #pragma unroll
        for (int i = 0; i < 4; i++) {
            int idx = tid + i * 256;
            int r = idx >> 3, c = (idx & 7) * 4;
            const __nv_bfloat162* pa2 = (const __nv_bfloat162*)(pA + (size_t)r * KTOT + c);
            float2 f0 = __bfloat1622float2(pa2[0]);
            float2 f1 = __bfloat1622float2(pa2[1]);
            ra[i] = make_float4(f0.x, f0.y, f1.x, f1.y);
            rb[i] = *(const float4*)(pB + (size_t)r * KTOT + c);
        }
    };
    auto storeS = [&](int buf) {
        float* As_ = sm + buf * 9216;
        float* Bs_ = As_ + 4608;
        #pragma unroll
        for (int i = 0; i < 4; i++) {
            int idx = tid + i * 256;
            int r = idx >> 3, c = (idx & 7) * 4;
            *(float4*)(As_ + r * 36 + c) = ra[i];          // bf16 values are exact in tf32
            *(float4*)(Bs_ + r * 36 + c) = cvt4(rb[i]);
        }
    };
    auto compute = [&](int buf) {
        const float* As_ = sm + buf * 9216;
        const float* Bs_ = As_ + 4608;
        #pragma unroll
        for (int ks = 0; ks < 4; ks++) {
            const int kk = ks * 8;
            uint32_t a[2][4], b[8][2];
            #pragma unroll
            for (int mt = 0; mt < 2; mt++) {
                int r = wm0 + mt * 16;
                a[mt][0] = __float_as_uint(As_[(r + g    ) * 36 + kk + tg    ]);
                a[mt][1] = __float_as_uint(As_[(r + g + 8) * 36 + kk + tg    ]);
                a[mt][2] = __float_as_uint(As_[(r + g    ) * 36 + kk + tg + 4]);
                a[mt][3] = __float_as_uint(As_[(r + g + 8) * 36 + kk + tg + 4]);
            }
            #pragma unroll
            for (int nt = 0; nt < 8; nt++) {
                int n = wn0 + nt * 8 + g;
                b[nt][0] = __float_as_uint(Bs_[n * 36 + kk + tg    ]);
                b[nt][1] = __float_as_uint(Bs_[n * 36 + kk + tg + 4]);
            }
            #pragma unroll
            for (int mt = 0; mt < 2; mt++)
                #pragma unroll
                for (int nt = 0; nt < 8; nt++)
                    MMA_TF32(acc[mt][nt], a[mt], b[nt]);
        }
    };

    constexpr int NKC = KTOT / 32;
    loadG(0);
    storeS(0);
    __syncthreads();
    #pragma unroll
    for (int kc = 0; kc < NKC; kc++) {
        if (kc + 1 < NKC) loadG(kc + 1);
        compute(kc & 1);
        __syncthreads();
        if (kc + 1 < NKC) {
            storeS((kc + 1) & 1);
            __syncthreads();
        }
    }

    float* st = sm;
    #pragma unroll
    for (int mt = 0; mt < 2; mt++)
        #pragma unroll
        for (int nt = 0; nt < 8; nt++) {
            int r = wm0 + mt * 16;
            int c = wn0 + nt * 8 + tg * 2;
            *(float2*)(st + (r + g    ) * 132 + c) = make_float2(acc[mt][nt][0], acc[mt][nt][1]);
            *(float2*)(st + (r + g + 8) * 132 + c) = make_float2(acc[mt][nt][2], acc[mt][nt][3]);
        }
    __syncthreads();
    #pragma unroll
    for (int i = 0; i < 64; i++) {
        int idx = tid + i * 256;
        int m = idx >> 7, n = idx & 127;
        epi(row0 + m, col0 + n, st[m * 132 + n]);
    }
}

// ---------------- attention (tensor core): one block per window ----------------
__global__ __launch_bounds__(256) void attn_mma_kernel(const float* __restrict__ mask)
{
    extern __shared__ float s[];
    float* Qs = s;             // [4][64][32] xor-swizzled
    float* Ks = s + 8192;
    float* Vt = s + 16384;     // [4][32][64] dim-major
    float* Ms = s + 24576;     // [64][64]

    const int win = blockIdx.x;
    const int tid = threadIdx.x;
    const int wid = tid >> 5, lane = tid & 31;
    const int head = wid >> 1;
    const int r0 = (wid & 1) * 32;
    const int g = lane >> 2, tg = lane & 3;

    const float4* bq = (const float4*)(g_q + (size_t)win * 8192);
    const float4* bk = (const float4*)(g_k + (size_t)win * 8192);
    const float4* bv = (const float4*)(g_v + (size_t)win * 8192);
    #pragma unroll
    for (int i = 0; i < 8; i++) {
        int f = tid + i * 256;
        int h = f >> 9;
        int tok = (f >> 3) & 63;
        int q4 = (f & 7) * 4;
        int sw = (tok & 7) << 2;
        *(float4*)(Qs + h*2048 + tok*32 + (q4 ^ sw)) = cvt4(bq[f]);
        *(float4*)(Ks + h*2048 + tok*32 + (q4 ^ sw)) = cvt4(bk[f]);
        float4 vv = cvt4(bv[f]);
        float va[4] = {vv.x, vv.y, vv.z, vv.w};
        #pragma unroll
        for (int j = 0; j < 4; j++) {
            int d = q4 + j;
            Vt[h*2048 + d*64 + (tok ^ ((d & 7) << 2))] = va[j];
        }
    }
    const float4* mrow = (const float4*)(mask + (size_t)(win & 2047) * 4096);
    #pragma unroll
    for (int i = 0; i < 4; i++) {
        int f = tid + i * 256;
        int r = f >> 4, c4 = (f & 15) * 4;
        *(float4*)(Ms + r*64 + (c4 ^ ((r & 7) << 2))) = mrow[f];
    }
    __syncthreads();

    const float* Qh = Qs + head * 2048;
    const float* Kh = Ks + head * 2048;
    const float* Vh = Vt + head * 2048;

    float sc[2][8][4];
    #pragma unroll
    for (int mt = 0; mt < 2; mt++)
        #pragma unroll
        for (int nt = 0; nt < 8; nt++)
            #pragma unroll
            for (int c = 0; c < 4; c++) sc[mt][nt][c] = 0.0f;

    #pragma unroll
    for (int ks = 0; ks < 4; ks++) {
        const int kk = ks * 8;
        uint32_t a[2][4], b[8][2];
        #pragma unroll
        for (int mt = 0; mt < 2; mt++) {
            int ra_ = r0 + mt*16 + g, rb_ = ra_ + 8;
            a[mt][0] = __float_as_uint(Qh[ra_*32 + ((kk+tg  ) ^ ((ra_&7)<<2))]);
            a[mt][1] = __float_as_uint(Qh[rb_*32 + ((kk+tg  ) ^ ((rb_&7)<<2))]);
            a[mt][2] = __float_as_uint(Qh[ra_*32 + ((kk+tg+4) ^ ((ra_&7)<<2))]);
            a[mt][3] = __float_as_uint(Qh[rb_*32 + ((kk+tg+4) ^ ((rb_&7)<<2))]);
        }
        #pragma unroll
        for (int nt = 0; nt < 8; nt++) {
            int n = nt*8 + g;
            b[nt][0] = __float_as_uint(Kh[n*32 + ((kk+tg  ) ^ ((n&7)<<2))]);
            b[nt][1] = __float_as_uint(Kh[n*32 + ((kk+tg+4) ^ ((n&7)<<2))]);
        }
        #pragma unroll
        for (int mt = 0; mt < 2; mt++)
            #pragma unroll
            for (int nt = 0; nt < 8; nt++)
                MMA_TF32(sc[mt][nt], a[mt], b[nt]);
    }

    const float* brow = g_bias + head * 4096;
    float rs[2][2] = {{0.f, 0.f}, {0.f, 0.f}};
    #pragma unroll
    for (int mt = 0; mt < 2; mt++) {
        int ra_ = r0 + mt*16 + g, rb_ = ra_ + 8;
        #pragma unroll
        for (int nt = 0; nt < 8; nt++) {
            int c0 = nt*8 + 2*tg;
            float2 ba = *(const float2*)(brow + ra_*64 + c0);
            float2 bb = *(const float2*)(brow + rb_*64 + c0);
            float2 ma = *(const float2*)(Ms + ra_*64 + (c0 ^ ((ra_&7)<<2)));
            float2 mb = *(const float2*)(Ms + rb_*64 + (c0 ^ ((rb_&7)<<2)));
            float e0 = __expf(sc[mt][nt][0] + ba.x + ma.x);
            float e1 = __expf(sc[mt][nt][1] + ba.y + ma.y);
            float e2 = __expf(sc[mt][nt][2] + bb.x + mb.x);
            float e3 = __expf(sc[mt][nt][3] + bb.y + mb.y);
            rs[mt][0] += e0 + e1;
            rs[mt][1] += e2 + e3;
            sc[mt][nt][0] = __uint_as_float(f2tf32(e0));
            sc[mt][nt][1] = __uint_as_float(f2tf32(e1));
            sc[mt][nt][2] = __uint_as_float(f2tf32(e2));
            sc[mt][nt][3] = __uint_as_float(f2tf32(e3));
        }
    }
    float inv[2][2];
    #pragma unroll
    for (int mt = 0; mt < 2; mt++) {
        #pragma unroll
        for (int hh = 0; hh < 2; hh++) {
            float v = rs[mt][hh];
            v += __shfl_xor_sync(0xffffffffu, v, 1);
            v += __shfl_xor_sync(0xffffffffu, v, 2);
            inv[mt][hh] = 1.0f / v;
        }
    }

    float oa[2][4][4];
    #pragma unroll
    for (int mt = 0; mt < 2; mt++)
        #pragma unroll
        for (int nt = 0; nt < 4; nt++)
            #pragma unroll
            for (int c = 0; c < 4; c++) oa[mt][nt][c] = 0.0f;

    const int src0 = (lane & ~3) | (tg >> 1);
    const int src2 = (lane & ~3) | (2 + (tg >> 1));
    const bool odd = (tg & 1);
    #pragma unroll
    for (int ks = 0; ks < 8; ks++) {
        uint32_t pa[2][4];
        #pragma unroll
        for (int mt = 0; mt < 2; mt++) {
            float c0 = sc[mt][ks][0], c1 = sc[mt][ks][1];
            float c2 = sc[mt][ks][2], c3 = sc[mt][ks][3];
            float v00 = __shfl_sync(0xffffffffu, c0, src0);
            float v01 = __shfl_sync(0xffffffffu, c1, src0);
            float v10 = __shfl_sync(0xffffffffu, c2, src0);
            float v11 = __shfl_sync(0xffffffffu, c3, src0);
            float v20 = __shfl_sync(0xffffffffu, c0, src2);
            float v21 = __shfl_sync(0xffffffffu, c1, src2);
            float v30 = __shfl_sync(0xffffffffu, c2, src2);
            float v31 = __shfl_sync(0xffffffffu, c3, src2);
            pa[mt][0] = __float_as_uint(odd ? v01 : v00);
            pa[mt][1] = __float_as_uint(odd ? v11 : v10);
            pa[mt][2] = __float_as_uint(odd ? v21 : v20);
            pa[mt][3] = __float_as_uint(odd ? v31 : v30);
        }
        uint32_t vb[4][2];
        #pragma unroll
        for (int nt = 0; nt < 4; nt++) {
            int n = nt*8 + g;
            vb[nt][0] = __float_as_uint(Vh[n*64 + ((ks*8+tg  ) ^ ((n&7)<<2))]);
            vb[nt][1] = __float_as_uint(Vh[n*64 + ((ks*8+tg+4) ^ ((n&7)<<2))]);
        }
        #pragma unroll
        for (int mt = 0; mt < 2; mt++)
            #pragma unroll
            for (int nt = 0; nt < 4; nt++)
                MMA_TF32(oa[mt][nt], pa[mt], vb[nt]);
    }

    #pragma unroll
    for (int mt = 0; mt < 2; mt++) {
        int ra_ = r0 + mt*16 + g;
        #pragma unroll
        for (int nt = 0; nt < 4; nt++) {
            int c0 = head*32 + nt*8 + 2*tg;
            float* orow = g_attn + ((size_t)win*64 + ra_)*128 + c0;
            *(float2*)orow = make_float2(oa[mt][nt][0]*inv[mt][0], oa[mt][nt][1]*inv[mt][0]);
            *(float2*)(orow + 8*128) = make_float2(oa[mt][nt][2]*inv[mt][1], oa[mt][nt][3]*inv[mt][1]);
        }
    }
}

// ---------------- launcher ----------------
extern "C" void kernel_launch(void* const* d_in, const int* in_sizes, int n_in,
                              void* d_out, int out_size)
{
    const float* x       = (const float*)d_in[0];
    const float* mask    = (const float*)d_in[1];
    const float* n1s     = (const float*)d_in[2];
    const float* n1b     = (const float*)d_in[3];
    const float* qkv_w   = (const float*)d_in[4];
    const float* table   = (const float*)d_in[5];
    const float* proj_w  = (const float*)d_in[6];
    const float* proj_b  = (const float*)d_in[7];
    const float* n2s     = (const float*)d_in[8];
    const float* n2b     = (const float*)d_in[9];
    const float* mlp_w1  = (const float*)d_in[10];
    const float* mlp_b1  = (const float*)d_in[11];
    const float* mlp_w2  = (const float*)d_in[12];
    const float* mlp_b2  = (const float*)d_in[13];
    float* out = (float*)d_out;

    float *p_attn, *p_x1;
    __nv_bfloat16* p_hid;
    float *p_wqkv_t, *p_wproj_t, *p_w1_t, *p_w2_t;
    cudaGetSymbolAddress((void**)&p_attn,   g_attn);
    cudaGetSymbolAddress((void**)&p_x1,     g_x1);
    cudaGetSymbolAddress((void**)&p_hid,    g_hid);
    cudaGetSymbolAddress((void**)&p_wqkv_t, g_wqkv_t);
    cudaGetSymbolAddress((void**)&p_wproj_t,g_wproj_t);
    cudaGetSymbolAddress((void**)&p_w1_t,   g_w1_t);
    cudaGetSymbolAddress((void**)&p_w2_t,   g_w2_t);

    const int K128_DSM = 2 * 128 * 132 * 4;   // 135168 B
    cudaFuncSetAttribute(gemm_k128<Ln1ShiftLoader, QkvEpi>, cudaFuncAttributeMaxDynamicSharedMemorySize, K128_DSM);
    cudaFuncSetAttribute(gemm_k128<PlainLoader,   ProjEpi>, cudaFuncAttributeMaxDynamicSharedMemorySize, K128_DSM);
    cudaFuncSetAttribute(gemm_k128<Ln2Loader,     Mlp1Epi>, cudaFuncAttributeMaxDynamicSharedMemorySize, K128_DSM);
    const int M2_DSM = 73728;
    cudaFuncSetAttribute(gemm_mlp2, cudaFuncAttributeMaxDynamicSharedMemorySize, M2_DSM);
    const int ADSM = 28672 * 4;   // 112 KB
    cudaFuncSetAttribute(attn_mma_kernel, cudaFuncAttributeMaxDynamicSharedMemorySize, ADSM);

    const int ROWBLK = (int)(MROWS / 128);  // 2048

    transpose_kernel<<<dim3(12, 4),  dim3(32, 32)>>>(qkv_w,  p_wqkv_t, 128, 384);
    transpose_kernel<<<dim3(4, 4),   dim3(32, 32)>>>(proj_w, p_wproj_t, 128, 128);
    transpose_kernel<<<dim3(16, 4),  dim3(32, 32)>>>(mlp_w1, p_w1_t,   128, 512);
    transpose_kernel<<<dim3(4, 16),  dim3(32, 32)>>>(mlp_w2, p_w2_t,   512, 128);
    bias_kernel<<<64, 64>>>(table);

    // 1. QKV projection with fused LN1 + cyclic shift + window partition
    gemm_k128<Ln1ShiftLoader, QkvEpi><<<dim3(3, ROWBLK), 256, K128_DSM>>>(
        Ln1ShiftLoader{x, n1s, n1b}, p_wqkv_t, QkvEpi{});
    // 2. windowed attention (tensor core)
    attn_mma_kernel<<<NWIN, 256, ADSM>>>(mask);
    // 3. output projection + window reverse + roll + residual
    gemm_k128<PlainLoader, ProjEpi><<<dim3(1, ROWBLK), 256, K128_DSM>>>(
        PlainLoader{p_attn}, p_wproj_t, ProjEpi{x, proj_b});
    // 4. MLP up with fused LN2, GELU epilogue (bf16 hidden)
    gemm_k128<Ln2Loader, Mlp1Epi><<<dim3(4, ROWBLK), 256, K128_DSM>>>(
        Ln2Loader{p_x1, n2s, n2b}, p_w1_t, Mlp1Epi{mlp_b1});
    // 5. MLP down + residual -> out
    gemm_mlp2<<<dim3(1, ROWBLK), 256, M2_DSM>>>(p_hid, p_w2_t, Mlp2Epi{mlp_b2, out});
}

// round 6
// speedup vs baseline: 1.7933x; 1.7933x over previous
#include <cuda_runtime.h>
#include <cuda_bf16.h>
#include <cstdint>

// ---------------- problem constants ----------------
constexpr int CH = 128, HEADS = 4, HD = 32, NTOK = 64;
constexpr int NWIN = 4096;
constexpr long long MROWS = 262144;   // 4096 windows * 64 tokens
constexpr int HID = 512;

// ---------------- scratch (static device globals) ----------------
__device__ __align__(16) float g_xw  [MROWS * CH];
__device__ __align__(16) __nv_bfloat16 g_q   [MROWS * CH];
__device__ __align__(16) __nv_bfloat16 g_k   [MROWS * CH];
__device__ __align__(16) __nv_bfloat16 g_v   [MROWS * CH];
__device__ __align__(16) float g_bias[HEADS * NTOK * NTOK];
__device__ __align__(16) __nv_bfloat16 g_attn[MROWS * CH];
__device__ __align__(16) float g_x1  [MROWS * CH];
__device__ __align__(16) float g_xn2 [MROWS * CH];
__device__ __align__(16) __nv_bfloat16 g_hid [MROWS * HID];
// transposed weights [N, K]
__device__ __align__(16) float g_wqkv_t[384 * 128];
__device__ __align__(16) float g_wproj_t[128 * 128];
__device__ __align__(16) float g_w1_t  [512 * 128];
__device__ __align__(16) float g_w2_t  [128 * 512];

__device__ __forceinline__ uint32_t f2tf32(float f) {
    uint32_t u;
    asm("cvt.rna.tf32.f32 %0, %1;" : "=r"(u) : "f"(f));
    return u;
}
__device__ __forceinline__ float4 cvt4(float4 v) {
    float4 o;
    o.x = __uint_as_float(f2tf32(v.x));
    o.y = __uint_as_float(f2tf32(v.y));
    o.z = __uint_as_float(f2tf32(v.z));
    o.w = __uint_as_float(f2tf32(v.w));
    return o;
}
#define MMA_TF32(acc, a, b) \
    asm volatile("mma.sync.aligned.m16n8k8.row.col.f32.tf32.tf32.f32 " \
        "{%0,%1,%2,%3}, {%4,%5,%6,%7}, {%8,%9}, {%0,%1,%2,%3};" \
        : "+f"((acc)[0]), "+f"((acc)[1]), "+f"((acc)[2]), "+f"((acc)[3]) \
        : "r"((a)[0]), "r"((a)[1]), "r"((a)[2]), "r"((a)[3]), "r"((b)[0]), "r"((b)[1]))

// generic 4-element A load (fp32 or bf16 -> float4)
__device__ __forceinline__ float4 loadA4(const float* p) { return *(const float4*)p; }
__device__ __forceinline__ float4 loadA4(const __nv_bfloat16* p) {
    const __nv_bfloat162* q = (const __nv_bfloat162*)p;
    float2 a = __bfloat1622float2(q[0]);
    float2 b = __bfloat1622float2(q[1]);
    return make_float4(a.x, a.y, b.x, b.y);
}
__device__ __forceinline__ void unpack8(uint4 u, float* f) {
    const __nv_bfloat162* p = (const __nv_bfloat162*)&u;
    #pragma unroll
    for (int j = 0; j < 4; j++) {
        float2 t = __bfloat1622float2(p[j]);
        f[2*j] = t.x; f[2*j+1] = t.y;
    }
}

// ---------------- LN1 + cyclic shift + window partition ----------------
__global__ __launch_bounds__(256) void ln1_shift_kernel(
    const float* __restrict__ x, const float* __restrict__ sc, const float* __restrict__ bi)
{
    int warp = (blockIdx.x * 256 + threadIdx.x) >> 5;
    int lane = threadIdx.x & 31;
    int t = warp & 63, win = warp >> 6;
    int b = win >> 11, widx = win & 2047;
    int wd = widx >> 8, wh = (widx >> 4) & 15, ww = widx & 15;
    int td = t >> 4, th = (t >> 2) & 3, tw = t & 3;
    int d = (wd*4 + td + 2) & 31;
    int h = (wh*4 + th + 2) & 63;
    int w = (ww*4 + tw + 2) & 63;
    const float4* src = (const float4*)(x + ((size_t)(((b*32 + d)*64 + h)*64 + w)) * CH);
    float4 v = src[lane];
    float s  = v.x + v.y + v.z + v.w;
    float ss = v.x*v.x + v.y*v.y + v.z*v.z + v.w*v.w;
    #pragma unroll
    for (int o = 16; o; o >>= 1) {
        s  += __shfl_xor_sync(0xffffffffu, s,  o);
        ss += __shfl_xor_sync(0xffffffffu, ss, o);
    }
    float mean = s * (1.0f/128.0f);
    float var  = ss * (1.0f/128.0f) - mean*mean;
    float r = rsqrtf(var + 1e-6f);
    float4 g4 = ((const float4*)sc)[lane];
    float4 b4 = ((const float4*)bi)[lane];
    float4 o4;
    o4.x = (v.x - mean)*r*g4.x + b4.x;
    o4.y = (v.y - mean)*r*g4.y + b4.y;
    o4.z = (v.z - mean)*r*g4.z + b4.z;
    o4.w = (v.w - mean)*r*g4.w + b4.w;
    ((float4*)(g_xw + (size_t)warp * CH))[lane] = o4;
}

// ---------------- LN2 ----------------
__global__ __launch_bounds__(256) void ln2_kernel(
    const float* __restrict__ sc, const float* __restrict__ bi)
{
    int warp = (blockIdx.x * 256 + threadIdx.x) >> 5;
    int lane = threadIdx.x & 31;
    float4 v = ((const float4*)(g_x1 + (size_t)warp * CH))[lane];
    float s  = v.x + v.y + v.z + v.w;
    float ss = v.x*v.x + v.y*v.y + v.z*v.z + v.w*v.w;
    #pragma unroll
    for (int o = 16; o; o >>= 1) {
        s  += __shfl_xor_sync(0xffffffffu, s,  o);
        ss += __shfl_xor_sync(0xffffffffu, ss, o);
    }
    float mean = s * (1.0f/128.0f);
    float var  = ss * (1.0f/128.0f) - mean*mean;
    float r = rsqrtf(var + 1e-6f);
    float4 g4 = ((const float4*)sc)[lane];
    float4 b4 = ((const float4*)bi)[lane];
    float4 o4;
    o4.x = (v.x - mean)*r*g4.x + b4.x;
    o4.y = (v.y - mean)*r*g4.y + b4.y;
    o4.z = (v.z - mean)*r*g4.z + b4.z;
    o4.w = (v.w - mean)*r*g4.w + b4.w;
    ((float4*)(g_xn2 + (size_t)warp * CH))[lane] = o4;
}

// ---------------- relative position bias ----------------
__global__ void bias_kernel(const float* __restrict__ table)
{
    int q = blockIdx.x, k = threadIdx.x;
    int qd = q >> 4, qh = (q >> 2) & 3, qw = q & 3;
    int kd = k >> 4, kh = (k >> 2) & 3, kw = k & 3;
    int idx = (qh - kh + 3) * 49 + (qd - kd + 3) * 7 + (qw - kw + 3);
    #pragma unroll
    for (int h = 0; h < HEADS; h++)
        g_bias[h * 4096 + q * 64 + k] = table[idx * HEADS + h];
}

// ---------------- weight transpose: dst[N,K] = src[K,N] ----------------
__global__ void transpose_kernel(const float* __restrict__ src, float* __restrict__ dst, int K, int N)
{
    __shared__ float tile[32][33];
    int n0 = blockIdx.x * 32, k0 = blockIdx.y * 32;
    int tx = threadIdx.x, ty = threadIdx.y;
    tile[ty][tx] = src[(size_t)(k0 + ty) * N + n0 + tx];
    __syncthreads();
    dst[(size_t)(n0 + ty) * K + k0 + tx] = tile[tx][ty];
}

// ---------------- epilogues ----------------
struct QkvEpi {
    __device__ void operator()(int m, int n, float v) const {
        int sel = n >> 7, c = n & 127;
        int head = c >> 5, e = c & 31;
        int win = m >> 6, t = m & 63;
        size_t o = (((size_t)win * HEADS + head) * NTOK + t) * HD + e;
        if (sel == 0)      g_q[o] = __float2bfloat16(v * 0.17677669529663687f);
        else if (sel == 1) g_k[o] = __float2bfloat16(v);
        else               g_v[o] = __float2bfloat16(v);
    }
};
struct ProjEpi {
    const float* x; const float* pb;
    __device__ void operator()(int m, int n, float v) const {
        int win = m >> 6, t = m & 63;
        int b = win >> 11, widx = win & 2047;
        int wd = widx >> 8, wh = (widx >> 4) & 15, ww = widx & 15;
        int td = t >> 4, th = (t >> 2) & 3, tw = t & 3;
        int d = (wd*4 + td + 2) & 31;
        int h = (wh*4 + th + 2) & 63;
        int w = (ww*4 + tw + 2) & 63;
        size_t o = (size_t)(((b*32 + d)*64 + h)*64 + w) * CH + n;
        g_x1[o] = v + pb[n] + x[o];
    }
};
struct Mlp1Epi {
    const float* b1;
    __device__ void operator()(int m, int n, float v) const {
        float u = v + b1[n];
        float z2 = 1.5957691216057308f * (u + 0.044715f * u * u * u);
        float sig = 1.0f / (1.0f + __expf(-z2));
        g_hid[(size_t)m * HID + n] = __float2bfloat16(u * sig);
    }
};
struct Mlp2Epi {
    const float* b2; float* out;
    __device__ void operator()(int m, int n, float v) const {
        size_t o = (size_t)m * CH + n;
        out[o] = v + b2[n] + g_x1[o];
    }
};

// ---------------- tf32 mma.sync GEMM (A: fp32 or bf16) ----------------
// grid: (NTILES, ROWBLK) — x fastest so the A tile is L2-shared across N-tiles.
template<int KTOT, class AT, class Epi>
__global__ __launch_bounds__(256, 2) void gemm_mma(
    const AT* __restrict__ A, const float* __restrict__ BT, Epi epi)
{
    extern __shared__ float sm[];   // 18432 floats
    const int tid = threadIdx.x;
    const int wid = tid >> 5, lane = tid & 31;
    const int row0 = blockIdx.y * 128, col0 = blockIdx.x * 128;
    const int wm0 = (wid >> 1) * 32, wn0 = (wid & 1) * 64;
    const int g = lane >> 2, tg = lane & 3;

    float acc[2][8][4];
    #pragma unroll
    for (int mt = 0; mt < 2; mt++)
        #pragma unroll
        for (int nt = 0; nt < 8; nt++)
            #pragma unroll
            for (int c = 0; c < 4; c++) acc[mt][nt][c] = 0.0f;

    float4 ra[4], rb[4];
    auto loadG = [&](int kc) {
        const AT* pA = A + (size_t)row0 * KTOT + kc * 32;
        const float* pB = BT + (size_t)col0 * KTOT + kc * 32;
        #pragma unroll
        for (int i = 0; i < 4; i++) {
            int idx = tid + i * 256;
            int r = idx >> 3, c = (idx & 7) * 4;
            ra[i] = loadA4(pA + (size_t)r * KTOT + c);
            rb[i] = *(const float4*)(pB + (size_t)r * KTOT + c);
        }
    };
    auto storeS = [&](int buf) {
        float* As_ = sm + buf * 9216;
        float* Bs_ = As_ + 4608;
        #pragma unroll
        for (int i = 0; i < 4; i++) {
            int idx = tid + i * 256;
            int r = idx >> 3, c = (idx & 7) * 4;
            *(float4*)(As_ + r * 36 + c) = cvt4(ra[i]);
            *(float4*)(Bs_ + r * 36 + c) = cvt4(rb[i]);
        }
    };
    auto compute = [&](int buf) {
        const float* As_ = sm + buf * 9216;
        const float* Bs_ = As_ + 4608;
        #pragma unroll
        for (int ks = 0; ks < 4; ks++) {
            const int kk = ks * 8;
            uint32_t a[2][4], b[8][2];
            #pragma unroll
            for (int mt = 0; mt < 2; mt++) {
                int r = wm0 + mt * 16;
                a[mt][0] = __float_as_uint(As_[(r + g    ) * 36 + kk + tg    ]);
                a[mt][1] = __float_as_uint(As_[(r + g + 8) * 36 + kk + tg    ]);
                a[mt][2] = __float_as_uint(As_[(r + g    ) * 36 + kk + tg + 4]);
                a[mt][3] = __float_as_uint(As_[(r + g + 8) * 36 + kk + tg + 4]);
            }
            #pragma unroll
            for (int nt = 0; nt < 8; nt++) {
                int n = wn0 + nt * 8 + g;
                b[nt][0] = __float_as_uint(Bs_[n * 36 + kk + tg    ]);
                b[nt][1] = __float_as_uint(Bs_[n * 36 + kk + tg + 4]);
            }
            #pragma unroll
            for (int mt = 0; mt < 2; mt++)
                #pragma unroll
                for (int nt = 0; nt < 8; nt++)
                    MMA_TF32(acc[mt][nt], a[mt], b[nt]);
        }
    };

    constexpr int NKC = KTOT / 32;
    loadG(0);
    storeS(0);
    __syncthreads();
    #pragma unroll
    for (int kc = 0; kc < NKC; kc++) {
        if (kc + 1 < NKC) loadG(kc + 1);
        compute(kc & 1);
        __syncthreads();
        if (kc + 1 < NKC) {
            storeS((kc + 1) & 1);
            __syncthreads();
        }
    }

    float* st = sm;   // 128 x 132
    #pragma unroll
    for (int mt = 0; mt < 2; mt++)
        #pragma unroll
        for (int nt = 0; nt < 8; nt++) {
            int r = wm0 + mt * 16;
            int c = wn0 + nt * 8 + tg * 2;
            *(float2*)(st + (r + g    ) * 132 + c) = make_float2(acc[mt][nt][0], acc[mt][nt][1]);
            *(float2*)(st + (r + g + 8) * 132 + c) = make_float2(acc[mt][nt][2], acc[mt][nt][3]);
        }
    __syncthreads();
    #pragma unroll
    for (int i = 0; i < 64; i++) {
        int idx = tid + i * 256;
        int m = idx >> 7, n = idx & 127;
        epi(row0 + m, col0 + n, st[m * 132 + n]);
    }
}

// ---------------- attention (tensor core): one block per window ----------------
// 256 threads = 8 warps; warp w: head = w/2, query rows r0 = (w&1)*32.
__global__ __launch_bounds__(256) void attn_mma_kernel(const float* __restrict__ mask)
{
    extern __shared__ float s[];
    float* Qs = s;             // [4][64][32] xor-swizzled
    float* Ks = s + 8192;
    float* Vt = s + 16384;     // [4][32][64] dim-major
    float* Ms = s + 24576;     // [64][64]

    const int win = blockIdx.x;
    const int tid = threadIdx.x;
    const int wid = tid >> 5, lane = tid & 31;
    const int head = wid >> 1;
    const int r0 = (wid & 1) * 32;
    const int g = lane >> 2, tg = lane & 3;

    // ---- fill smem from bf16 global (uint4 = 8 elems) ----
    const uint4* bq = (const uint4*)(g_q + (size_t)win * 8192);
    const uint4* bk = (const uint4*)(g_k + (size_t)win * 8192);
    const uint4* bv = (const uint4*)(g_v + (size_t)win * 8192);
    #pragma unroll
    for (int i = 0; i < 4; i++) {
        int f = tid + i * 256;        // 0..1023
        int h = f >> 8;
        int rem = f & 255;
        int tok = rem >> 2;
        int q8 = (rem & 3) * 8;
        int sw = (tok & 7) << 2;
        float qf[8], kf[8], vf[8];
        unpack8(bq[f], qf);
        unpack8(bk[f], kf);
        unpack8(bv[f], vf);
        *(float4*)(Qs + h*2048 + tok*32 + ((q8  ) ^ sw)) = make_float4(qf[0], qf[1], qf[2], qf[3]);
        *(float4*)(Qs + h*2048 + tok*32 + ((q8+4) ^ sw)) = make_float4(qf[4], qf[5], qf[6], qf[7]);
        *(float4*)(Ks + h*2048 + tok*32 + ((q8  ) ^ sw)) = make_float4(kf[0], kf[1], kf[2], kf[3]);
        *(float4*)(Ks + h*2048 + tok*32 + ((q8+4) ^ sw)) = make_float4(kf[4], kf[5], kf[6], kf[7]);
        #pragma unroll
        for (int j = 0; j < 8; j++) {
            int d = q8 + j;
            Vt[h*2048 + d*64 + (tok ^ ((d & 7) << 2))] = vf[j];
        }
    }
    const float4* mrow = (const float4*)(mask + (size_t)(win & 2047) * 4096);
    #pragma unroll
    for (int i = 0; i < 4; i++) {
        int f = tid + i * 256;
        int r = f >> 4, c4 = (f & 15) * 4;
        *(float4*)(Ms + r*64 + (c4 ^ ((r & 7) << 2))) = mrow[f];
    }
    __syncthreads();

    const float* Qh = Qs + head * 2048;
    const float* Kh = Ks + head * 2048;
    const float* Vh = Vt + head * 2048;

    float sc[2][8][4];
    #pragma unroll
    for (int mt = 0; mt < 2; mt++)
        #pragma unroll
        for (int nt = 0; nt < 8; nt++)
            #pragma unroll
            for (int c = 0; c < 4; c++) sc[mt][nt][c] = 0.0f;

    #pragma unroll
    for (int ks = 0; ks < 4; ks++) {
        const int kk = ks * 8;
        uint32_t a[2][4], b[8][2];
        #pragma unroll
        for (int mt = 0; mt < 2; mt++) {
            int ra_ = r0 + mt*16 + g, rb_ = ra_ + 8;
            a[mt][0] = __float_as_uint(Qh[ra_*32 + ((kk+tg  ) ^ ((ra_&7)<<2))]);
            a[mt][1] = __float_as_uint(Qh[rb_*32 + ((kk+tg  ) ^ ((rb_&7)<<2))]);
            a[mt][2] = __float_as_uint(Qh[ra_*32 + ((kk+tg+4) ^ ((ra_&7)<<2))]);
            a[mt][3] = __float_as_uint(Qh[rb_*32 + ((kk+tg+4) ^ ((rb_&7)<<2))]);
        }
        #pragma unroll
        for (int nt = 0; nt < 8; nt++) {
            int n = nt*8 + g;
            b[nt][0] = __float_as_uint(Kh[n*32 + ((kk+tg  ) ^ ((n&7)<<2))]);
            b[nt][1] = __float_as_uint(Kh[n*32 + ((kk+tg+4) ^ ((n&7)<<2))]);
        }
        #pragma unroll
        for (int mt = 0; mt < 2; mt++)
            #pragma unroll
            for (int nt = 0; nt < 8; nt++)
                MMA_TF32(sc[mt][nt], a[mt], b[nt]);
    }

    const float* brow = g_bias + head * 4096;
    float rs[2][2] = {{0.f, 0.f}, {0.f, 0.f}};
    #pragma unroll
    for (int mt = 0; mt < 2; mt++) {
        int ra_ = r0 + mt*16 + g, rb_ = ra_ + 8;
        #pragma unroll
        for (int nt = 0; nt < 8; nt++) {
            int c0 = nt*8 + 2*tg;
            float2 ba = *(const float2*)(brow + ra_*64 + c0);
            float2 bb = *(const float2*)(brow + rb_*64 + c0);
            float2 ma = *(const float2*)(Ms + ra_*64 + (c0 ^ ((ra_&7)<<2)));
            float2 mb = *(const float2*)(Ms + rb_*64 + (c0 ^ ((rb_&7)<<2)));
            float e0 = __expf(sc[mt][nt][0] + ba.x + ma.x);
            float e1 = __expf(sc[mt][nt][1] + ba.y + ma.y);
            float e2 = __expf(sc[mt][nt][2] + bb.x + mb.x);
            float e3 = __expf(sc[mt][nt][3] + bb.y + mb.y);
            rs[mt][0] += e0 + e1;
            rs[mt][1] += e2 + e3;
            sc[mt][nt][0] = __uint_as_float(f2tf32(e0));
            sc[mt][nt][1] = __uint_as_float(f2tf32(e1));
            sc[mt][nt][2] = __uint_as_float(f2tf32(e2));
            sc[mt][nt][3] = __uint_as_float(f2tf32(e3));
        }
    }
    float inv[2][2];
    #pragma unroll
    for (int mt = 0; mt < 2; mt++) {
        #pragma unroll
        for (int hh = 0; hh < 2; hh++) {
            float v = rs[mt][hh];
            v += __shfl_xor_sync(0xffffffffu, v, 1);
            v += __shfl_xor_sync(0xffffffffu, v, 2);
            inv[mt][hh] = 1.0f / v;
        }
    }

    float oa[2][4][4];
    #pragma unroll
    for (int mt = 0; mt < 2; mt++)
        #pragma unroll
        for (int nt = 0; nt < 4; nt++)
            #pragma unroll
            for (int c = 0; c < 4; c++) oa[mt][nt][c] = 0.0f;

    const int src0 = (lane & ~3) | (tg >> 1);
    const int src2 = (lane & ~3) | (2 + (tg >> 1));
    const bool odd = (tg & 1);
    #pragma unroll
    for (int ks = 0; ks < 8; ks++) {
        uint32_t pa[2][4];
        #pragma unroll
        for (int mt = 0; mt < 2; mt++) {
            float c0 = sc[mt][ks][0], c1 = sc[mt][ks][1];
            float c2 = sc[mt][ks][2], c3 = sc[mt][ks][3];
            float v00 = __shfl_sync(0xffffffffu, c0, src0);
            float v01 = __shfl_sync(0xffffffffu, c1, src0);
            float v10 = __shfl_sync(0xffffffffu, c2, src0);
            float v11 = __shfl_sync(0xffffffffu, c3, src0);
            float v20 = __shfl_sync(0xffffffffu, c0, src2);
            float v21 = __shfl_sync(0xffffffffu, c1, src2);
            float v30 = __shfl_sync(0xffffffffu, c2, src2);
            float v31 = __shfl_sync(0xffffffffu, c3, src2);
            pa[mt][0] = __float_as_uint(odd ? v01 : v00);
            pa[mt][1] = __float_as_uint(odd ? v11 : v10);
            pa[mt][2] = __float_as_uint(odd ? v21 : v20);
            pa[mt][3] = __float_as_uint(odd ? v31 : v30);
        }
        uint32_t vb[4][2];
        #pragma unroll
        for (int nt = 0; nt < 4; nt++) {
            int n = nt*8 + g;
            vb[nt][0] = __float_as_uint(Vh[n*64 + ((ks*8+tg  ) ^ ((n&7)<<2))]);
            vb[nt][1] = __float_as_uint(Vh[n*64 + ((ks*8+tg+4) ^ ((n&7)<<2))]);
        }
        #pragma unroll
        for (int mt = 0; mt < 2; mt++)
            #pragma unroll
            for (int nt = 0; nt < 4; nt++)
                MMA_TF32(oa[mt][nt], pa[mt], vb[nt]);
    }

    #pragma unroll
    for (int mt = 0; mt < 2; mt++) {
        int ra_ = r0 + mt*16 + g;
        #pragma unroll
        for (int nt = 0; nt < 4; nt++) {
            int c0 = head*32 + nt*8 + 2*tg;
            __nv_bfloat162* o0 = (__nv_bfloat162*)(g_attn + ((size_t)win*64 + ra_)*128 + c0);
            __nv_bfloat162* o1 = (__nv_bfloat162*)(g_attn + ((size_t)win*64 + ra_ + 8)*128 + c0);
            *o0 = __floats2bfloat162_rn(oa[mt][nt][0]*inv[mt][0], oa[mt][nt][1]*inv[mt][0]);
            *o1 = __floats2bfloat162_rn(oa[mt][nt][2]*inv[mt][1], oa[mt][nt][3]*inv[mt][1]);
        }
    }
}

// ---------------- launcher ----------------
extern "C" void kernel_launch(void* const* d_in, const int* in_sizes, int n_in,
                              void* d_out, int out_size)
{
    const float* x       = (const float*)d_in[0];
    const float* mask    = (const float*)d_in[1];
    const float* n1s     = (const float*)d_in[2];
    const float* n1b     = (const float*)d_in[3];
    const float* qkv_w   = (const float*)d_in[4];
    const float* table   = (const float*)d_in[5];
    const float* proj_w  = (const float*)d_in[6];
    const float* proj_b  = (const float*)d_in[7];
    const float* n2s     = (const float*)d_in[8];
    const float* n2b     = (const float*)d_in[9];
    const float* mlp_w1  = (const float*)d_in[10];
    const float* mlp_b1  = (const float*)d_in[11];
    const float* mlp_w2  = (const float*)d_in[12];
    const float* mlp_b2  = (const float*)d_in[13];
    float* out = (float*)d_out;

    float *p_xw, *p_xn2;
    __nv_bfloat16 *p_hid, *p_attn;
    float *p_wqkv_t, *p_wproj_t, *p_w1_t, *p_w2_t;
    cudaGetSymbolAddress((void**)&p_xw,     g_xw);
    cudaGetSymbolAddress((void**)&p_xn2,    g_xn2);
    cudaGetSymbolAddress((void**)&p_hid,    g_hid);
    cudaGetSymbolAddress((void**)&p_attn,   g_attn);
    cudaGetSymbolAddress((void**)&p_wqkv_t, g_wqkv_t);
    cudaGetSymbolAddress((void**)&p_wproj_t,g_wproj_t);
    cudaGetSymbolAddress((void**)&p_w1_t,   g_w1_t);
    cudaGetSymbolAddress((void**)&p_w2_t,   g_w2_t);

    const int DSM = 73728;
    cudaFuncSetAttribute((void*)gemm_mma<128, float, QkvEpi>,          cudaFuncAttributeMaxDynamicSharedMemorySize, DSM);
    cudaFuncSetAttribute((void*)gemm_mma<128, __nv_bfloat16, ProjEpi>, cudaFuncAttributeMaxDynamicSharedMemorySize, DSM);
    cudaFuncSetAttribute((void*)gemm_mma<128, float, Mlp1Epi>,         cudaFuncAttributeMaxDynamicSharedMemorySize, DSM);
    cudaFuncSetAttribute((void*)gemm_mma<512, __nv_bfloat16, Mlp2Epi>, cudaFuncAttributeMaxDynamicSharedMemorySize, DSM);
    const int ADSM = 28672 * 4;   // 112 KB
    cudaFuncSetAttribute(attn_mma_kernel, cudaFuncAttributeMaxDynamicSharedMemorySize, ADSM);

    const int ROWBLK = (int)(MROWS / 128);  // 2048

    transpose_kernel<<<dim3(12, 4),  dim3(32, 32)>>>(qkv_w,  p_wqkv_t, 128, 384);
    transpose_kernel<<<dim3(4, 4),   dim3(32, 32)>>>(proj_w, p_wproj_t, 128, 128);
    transpose_kernel<<<dim3(16, 4),  dim3(32, 32)>>>(mlp_w1, p_w1_t,   128, 512);
    transpose_kernel<<<dim3(4, 16),  dim3(32, 32)>>>(mlp_w2, p_w2_t,   512, 128);
    bias_kernel<<<64, 64>>>(table);

    // 1. LN1 + shift + window partition
    ln1_shift_kernel<<<(int)(MROWS / 8), 256>>>(x, n1s, n1b);
    // 2. QKV projection (q pre-scaled, bf16 out)
    gemm_mma<128, float, QkvEpi><<<dim3(3, ROWBLK), 256, DSM>>>(p_xw, p_wqkv_t, QkvEpi{});
    // 3. windowed attention (tensor core, bf16 in/out)
    attn_mma_kernel<<<NWIN, 256, ADSM>>>(mask);
    // 4. output projection + window reverse + roll + residual
    gemm_mma<128, __nv_bfloat16, ProjEpi><<<dim3(1, ROWBLK), 256, DSM>>>(p_attn, p_wproj_t, ProjEpi{x, proj_b});
    // 5. LN2
    ln2_kernel<<<(int)(MROWS / 8), 256>>>(n2s, n2b);
    // 6. MLP up + GELU (bf16 hidden)
    gemm_mma<128, float, Mlp1Epi><<<dim3(4, ROWBLK), 256, DSM>>>(p_xn2, p_w1_t, Mlp1Epi{mlp_b1});
    // 7. MLP down + residual -> out
    gemm_mma<512, __nv_bfloat16, Mlp2Epi><<<dim3(1, ROWBLK), 256, DSM>>>(p_hid, p_w2_t, Mlp2Epi{mlp_b2, out});
}

// round 7
// speedup vs baseline: 2.3802x; 1.3273x over previous
#include <cuda_runtime.h>
#include <cuda_bf16.h>
#include <cstdint>

// ---------------- problem constants ----------------
constexpr int CH = 128, HEADS = 4, HD = 32, NTOK = 64;
constexpr int NWIN = 4096;
constexpr long long MROWS = 262144;   // 4096 windows * 64 tokens
constexpr int HID = 512;

// ---------------- scratch (static device globals) ----------------
__device__ __align__(16) float g_xw  [MROWS * CH];
__device__ __align__(16) __nv_bfloat16 g_q   [MROWS * CH];
__device__ __align__(16) __nv_bfloat16 g_k   [MROWS * CH];
__device__ __align__(16) __nv_bfloat16 g_v   [MROWS * CH];
__device__ __align__(16) float g_bias[HEADS * NTOK * NTOK];
__device__ __align__(16) __nv_bfloat16 g_attn[MROWS * CH];
__device__ __align__(16) float g_x1  [MROWS * CH];
__device__ __align__(16) float g_xn2 [MROWS * CH];
__device__ __align__(16) __nv_bfloat16 g_hid [MROWS * HID];
// transposed bf16 weights [N, K]
__device__ __align__(16) __nv_bfloat16 g_wqkv_t[384 * 128];
__device__ __align__(16) __nv_bfloat16 g_wproj_t[128 * 128];
__device__ __align__(16) __nv_bfloat16 g_w1_t  [512 * 128];
__device__ __align__(16) __nv_bfloat16 g_w2_t  [128 * 512];

__device__ __forceinline__ uint32_t packbf(float lo, float hi) {
    __nv_bfloat162 h = __floats2bfloat162_rn(lo, hi);
    return *(uint32_t*)&h;
}
__device__ __forceinline__ uint32_t lds32(const __nv_bfloat16* p) {
    return *(const uint32_t*)p;
}
#define MMA_BF16(acc, a, b) \
    asm volatile("mma.sync.aligned.m16n8k16.row.col.f32.bf16.bf16.f32 " \
        "{%0,%1,%2,%3}, {%4,%5,%6,%7}, {%8,%9}, {%0,%1,%2,%3};" \
        : "+f"((acc)[0]), "+f"((acc)[1]), "+f"((acc)[2]), "+f"((acc)[3]) \
        : "r"((a)[0]), "r"((a)[1]), "r"((a)[2]), "r"((a)[3]), "r"((b)[0]), "r"((b)[1]))

// 8-element A loads -> raw bf16x8 (uint4)
__device__ __forceinline__ uint4 loadA8(const __nv_bfloat16* p) { return *(const uint4*)p; }
__device__ __forceinline__ uint4 loadA8(const float* p) {
    float4 f0 = *(const float4*)p;
    float4 f1 = *(const float4*)(p + 4);
    uint4 u;
    u.x = packbf(f0.x, f0.y); u.y = packbf(f0.z, f0.w);
    u.z = packbf(f1.x, f1.y); u.w = packbf(f1.z, f1.w);
    return u;
}

// ---------------- LN1 + cyclic shift + window partition ----------------
__global__ __launch_bounds__(256) void ln1_shift_kernel(
    const float* __restrict__ x, const float* __restrict__ sc, const float* __restrict__ bi)
{
    int warp = (blockIdx.x * 256 + threadIdx.x) >> 5;
    int lane = threadIdx.x & 31;
    int t = warp & 63, win = warp >> 6;
    int b = win >> 11, widx = win & 2047;
    int wd = widx >> 8, wh = (widx >> 4) & 15, ww = widx & 15;
    int td = t >> 4, th = (t >> 2) & 3, tw = t & 3;
    int d = (wd*4 + td + 2) & 31;
    int h = (wh*4 + th + 2) & 63;
    int w = (ww*4 + tw + 2) & 63;
    const float4* src = (const float4*)(x + ((size_t)(((b*32 + d)*64 + h)*64 + w)) * CH);
    float4 v = src[lane];
    float s  = v.x + v.y + v.z + v.w;
    float ss = v.x*v.x + v.y*v.y + v.z*v.z + v.w*v.w;
    #pragma unroll
    for (int o = 16; o; o >>= 1) {
        s  += __shfl_xor_sync(0xffffffffu, s,  o);
        ss += __shfl_xor_sync(0xffffffffu, ss, o);
    }
    float mean = s * (1.0f/128.0f);
    float var  = ss * (1.0f/128.0f) - mean*mean;
    float r = rsqrtf(var + 1e-6f);
    float4 g4 = ((const float4*)sc)[lane];
    float4 b4 = ((const float4*)bi)[lane];
    float4 o4;
    o4.x = (v.x - mean)*r*g4.x + b4.x;
    o4.y = (v.y - mean)*r*g4.y + b4.y;
    o4.z = (v.z - mean)*r*g4.z + b4.z;
    o4.w = (v.w - mean)*r*g4.w + b4.w;
    ((float4*)(g_xw + (size_t)warp * CH))[lane] = o4;
}

// ---------------- LN2 ----------------
__global__ __launch_bounds__(256) void ln2_kernel(
    const float* __restrict__ sc, const float* __restrict__ bi)
{
    int warp = (blockIdx.x * 256 + threadIdx.x) >> 5;
    int lane = threadIdx.x & 31;
    float4 v = ((const float4*)(g_x1 + (size_t)warp * CH))[lane];
    float s  = v.x + v.y + v.z + v.w;
    float ss = v.x*v.x + v.y*v.y + v.z*v.z + v.w*v.w;
    #pragma unroll
    for (int o = 16; o; o >>= 1) {
        s  += __shfl_xor_sync(0xffffffffu, s,  o);
        ss += __shfl_xor_sync(0xffffffffu, ss, o);
    }
    float mean = s * (1.0f/128.0f);
    float var  = ss * (1.0f/128.0f) - mean*mean;
    float r = rsqrtf(var + 1e-6f);
    float4 g4 = ((const float4*)sc)[lane];
    float4 b4 = ((const float4*)bi)[lane];
    float4 o4;
    o4.x = (v.x - mean)*r*g4.x + b4.x;
    o4.y = (v.y - mean)*r*g4.y + b4.y;
    o4.z = (v.z - mean)*r*g4.z + b4.z;
    o4.w = (v.w - mean)*r*g4.w + b4.w;
    ((float4*)(g_xn2 + (size_t)warp * CH))[lane] = o4;
}

// ---------------- relative position bias ----------------
__global__ void bias_kernel(const float* __restrict__ table)
{
    int q = blockIdx.x, k = threadIdx.x;
    int qd = q >> 4, qh = (q >> 2) & 3, qw = q & 3;
    int kd = k >> 4, kh = (k >> 2) & 3, kw = k & 3;
    int idx = (qh - kh + 3) * 49 + (qd - kd + 3) * 7 + (qw - kw + 3);
    #pragma unroll
    for (int h = 0; h < HEADS; h++)
        g_bias[h * 4096 + q * 64 + k] = table[idx * HEADS + h];
}

// ---------------- weight transpose to bf16: dst[N,K] = bf16(src[K,N]) ----------------
__global__ void transpose_kernel(const float* __restrict__ src, __nv_bfloat16* __restrict__ dst, int K, int N)
{
    __shared__ float tile[32][33];
    int n0 = blockIdx.x * 32, k0 = blockIdx.y * 32;
    int tx = threadIdx.x, ty = threadIdx.y;
    tile[ty][tx] = src[(size_t)(k0 + ty) * N + n0 + tx];
    __syncthreads();
    dst[(size_t)(n0 + ty) * K + k0 + tx] = __float2bfloat16(tile[tx][ty]);
}

// ---------------- epilogues ----------------
struct QkvEpi {
    __device__ void operator()(int m, int n, float v) const {
        int sel = n >> 7, c = n & 127;
        int head = c >> 5, e = c & 31;
        int win = m >> 6, t = m & 63;
        size_t o = (((size_t)win * HEADS + head) * NTOK + t) * HD + e;
        if (sel == 0)      g_q[o] = __float2bfloat16(v * 0.17677669529663687f);
        else if (sel == 1) g_k[o] = __float2bfloat16(v);
        else               g_v[o] = __float2bfloat16(v);
    }
};
struct ProjEpi {
    const float* x; const float* pb;
    __device__ void operator()(int m, int n, float v) const {
        int win = m >> 6, t = m & 63;
        int b = win >> 11, widx = win & 2047;
        int wd = widx >> 8, wh = (widx >> 4) & 15, ww = widx & 15;
        int td = t >> 4, th = (t >> 2) & 3, tw = t & 3;
        int d = (wd*4 + td + 2) & 31;
        int h = (wh*4 + th + 2) & 63;
        int w = (ww*4 + tw + 2) & 63;
        size_t o = (size_t)(((b*32 + d)*64 + h)*64 + w) * CH + n;
        g_x1[o] = v + pb[n] + x[o];
    }
};
struct Mlp1Epi {
    const float* b1;
    __device__ void operator()(int m, int n, float v) const {
        float u = v + b1[n];
        float z2 = 1.5957691216057308f * (u + 0.044715f * u * u * u);
        float sig = 1.0f / (1.0f + __expf(-z2));
        g_hid[(size_t)m * HID + n] = __float2bfloat16(u * sig);
    }
};
struct Mlp2Epi {
    const float* b2; float* out;
    __device__ void operator()(int m, int n, float v) const {
        size_t o = (size_t)m * CH + n;
        out[o] = v + b2[n] + g_x1[o];
    }
};

// ---------------- bf16 m16n8k16 GEMM ----------------
// C tile [128x128] = A[row0.., KTOT] @ BT[col0.., KTOT]^T ; BK = 32 bf16, double-buffered.
// smem tile stride 40 bf16 (80 B) -> conflict-free fragment LDS.
// grid: (NTILES, ROWBLK) — x fastest so the A tile is L2-shared across N-tiles.
template<int KTOT, class AT, class Epi>
__global__ __launch_bounds__(256, 2) void gemm_bf16(
    const AT* __restrict__ A, const __nv_bfloat16* __restrict__ BT, Epi epi)
{
    extern __shared__ char smraw[];
    __nv_bfloat16* sm = (__nv_bfloat16*)smraw;   // [2] x (As 128*40 + Bs 128*40)
    const int tid = threadIdx.x;
    const int wid = tid >> 5, lane = tid & 31;
    const int row0 = blockIdx.y * 128, col0 = blockIdx.x * 128;
    const int wm0 = (wid >> 1) * 32, wn0 = (wid & 1) * 64;
    const int g = lane >> 2, tg = lane & 3;

    float acc[2][8][4];
    #pragma unroll
    for (int mt = 0; mt < 2; mt++)
        #pragma unroll
        for (int nt = 0; nt < 8; nt++)
            #pragma unroll
            for (int c = 0; c < 4; c++) acc[mt][nt][c] = 0.0f;

    uint4 ra[2], rb[2];
    auto loadG = [&](int kc) {
        #pragma unroll
        for (int i = 0; i < 2; i++) {
            int idx = tid + i * 256;           // 0..511
            int r = idx >> 2, c8 = (idx & 3) * 8;
            ra[i] = loadA8(A + (size_t)(row0 + r) * KTOT + kc * 32 + c8);
            rb[i] = *(const uint4*)(BT + (size_t)(col0 + r) * KTOT + kc * 32 + c8);
        }
    };
    auto storeS = [&](int buf) {
        __nv_bfloat16* As_ = sm + buf * 10240;
        __nv_bfloat16* Bs_ = As_ + 5120;
        #pragma unroll
        for (int i = 0; i < 2; i++) {
            int idx = tid + i * 256;
            int r = idx >> 2, c8 = (idx & 3) * 8;
            *(uint4*)(As_ + r * 40 + c8) = ra[i];
            *(uint4*)(Bs_ + r * 40 + c8) = rb[i];
        }
    };
    auto compute = [&](int buf) {
        const __nv_bfloat16* As_ = sm + buf * 10240;
        const __nv_bfloat16* Bs_ = As_ + 5120;
        #pragma unroll
        for (int ks = 0; ks < 2; ks++) {
            const int kk = ks * 16;
            uint32_t a[2][4], b[8][2];
            #pragma unroll
            for (int mt = 0; mt < 2; mt++) {
                int r = wm0 + mt * 16;
                a[mt][0] = lds32(As_ + (r + g    ) * 40 + kk + 2*tg    );
                a[mt][1] = lds32(As_ + (r + g + 8) * 40 + kk + 2*tg    );
                a[mt][2] = lds32(As_ + (r + g    ) * 40 + kk + 2*tg + 8);
                a[mt][3] = lds32(As_ + (r + g + 8) * 40 + kk + 2*tg + 8);
            }
            #pragma unroll
            for (int nt = 0; nt < 8; nt++) {
                int n = wn0 + nt * 8 + g;
                b[nt][0] = lds32(Bs_ + n * 40 + kk + 2*tg    );
                b[nt][1] = lds32(Bs_ + n * 40 + kk + 2*tg + 8);
            }
            #pragma unroll
            for (int mt = 0; mt < 2; mt++)
                #pragma unroll
                for (int nt = 0; nt < 8; nt++)
                    MMA_BF16(acc[mt][nt], a[mt], b[nt]);
        }
    };

    constexpr int NKC = KTOT / 32;
    loadG(0);
    storeS(0);
    __syncthreads();
    #pragma unroll
    for (int kc = 0; kc < NKC; kc++) {
        if (kc + 1 < NKC) loadG(kc + 1);
        compute(kc & 1);
        __syncthreads();
        if (kc + 1 < NKC) {
            storeS((kc + 1) & 1);
            __syncthreads();
        }
    }

    // epilogue: stage fp32 C to smem, then coalesced epi
    float* st = (float*)smraw;   // 128 x 132
    #pragma unroll
    for (int mt = 0; mt < 2; mt++)
        #pragma unroll
        for (int nt = 0; nt < 8; nt++) {
            int r = wm0 + mt * 16;
            int c = wn0 + nt * 8 + tg * 2;
            *(float2*)(st + (r + g    ) * 132 + c) = make_float2(acc[mt][nt][0], acc[mt][nt][1]);
            *(float2*)(st + (r + g + 8) * 132 + c) = make_float2(acc[mt][nt][2], acc[mt][nt][3]);
        }
    __syncthreads();
    #pragma unroll
    for (int i = 0; i < 64; i++) {
        int idx = tid + i * 256;
        int m = idx >> 7, n = idx & 127;
        epi(row0 + m, col0 + n, st[m * 132 + n]);
    }
}

// ---------------- attention (bf16 m16n8k16): one block per window ----------------
// 256 threads = 8 warps; warp w: head = w/2, query rows r0 = (w&1)*32.
// P fragments pack directly from softmax C-frags (no shuffles).
__global__ __launch_bounds__(256) void attn_bf16_kernel(const float* __restrict__ mask)
{
    extern __shared__ char smraw[];
    __nv_bfloat16* Qs = (__nv_bfloat16*)smraw;                 // [4][64][40]
    __nv_bfloat16* Ks = Qs + 10240;                            // [4][64][40]
    __nv_bfloat16* Vt = Ks + 10240;                            // [4][32][72] dim-major
    float* Ms = (float*)(smraw + 59392);                       // [64][68]

    const int win = blockIdx.x;
    const int tid = threadIdx.x;
    const int wid = tid >> 5, lane = tid & 31;
    const int head = wid >> 1;
    const int r0 = (wid & 1) * 32;
    const int g = lane >> 2, tg = lane & 3;

    // ---- fill smem (raw bf16 copies; V scattered dim-major) ----
    const uint4* bq = (const uint4*)(g_q + (size_t)win * 8192);
    const uint4* bk = (const uint4*)(g_k + (size_t)win * 8192);
    const uint4* bv = (const uint4*)(g_v + (size_t)win * 8192);
    #pragma unroll
    for (int i = 0; i < 4; i++) {
        int f = tid + i * 256;        // 0..1023
        int h = f >> 8;
        int tok = (f >> 2) & 63;
        int q8 = (f & 3) * 8;
        *(uint4*)(Qs + h*2560 + tok*40 + q8) = bq[f];
        *(uint4*)(Ks + h*2560 + tok*40 + q8) = bk[f];
        uint4 vv = bv[f];
        __nv_bfloat16 tmp[8];
        *(uint4*)tmp = vv;
        #pragma unroll
        for (int j = 0; j < 8; j++)
            Vt[h*2304 + (q8 + j)*72 + tok] = tmp[j];
    }
    const float4* mrow = (const float4*)(mask + (size_t)(win & 2047) * 4096);
    #pragma unroll
    for (int i = 0; i < 4; i++) {
        int f = tid + i * 256;
        int r = f >> 4, c4 = (f & 15) * 4;
        *(float4*)(Ms + r*68 + c4) = mrow[f];
    }
    __syncthreads();

    const __nv_bfloat16* Qh = Qs + head * 2560;
    const __nv_bfloat16* Kh = Ks + head * 2560;
    const __nv_bfloat16* Vh = Vt + head * 2304;

    // ---- scores S[32x64] = Q @ K^T (K-dim = 32 -> 2 k16 iters) ----
    float sc[2][8][4];
    #pragma unroll
    for (int mt = 0; mt < 2; mt++)
        #pragma unroll
        for (int nt = 0; nt < 8; nt++)
            #pragma unroll
            for (int c = 0; c < 4; c++) sc[mt][nt][c] = 0.0f;

    #pragma unroll
    for (int ks = 0; ks < 2; ks++) {
        const int kk = ks * 16;
        uint32_t a[2][4], b[8][2];
        #pragma unroll
        for (int mt = 0; mt < 2; mt++) {
            int r = r0 + mt * 16;
            a[mt][0] = lds32(Qh + (r + g    ) * 40 + kk + 2*tg    );
            a[mt][1] = lds32(Qh + (r + g + 8) * 40 + kk + 2*tg    );
            a[mt][2] = lds32(Qh + (r + g    ) * 40 + kk + 2*tg + 8);
            a[mt][3] = lds32(Qh + (r + g + 8) * 40 + kk + 2*tg + 8);
        }
        #pragma unroll
        for (int nt = 0; nt < 8; nt++) {
            int n = nt * 8 + g;
            b[nt][0] = lds32(Kh + n * 40 + kk + 2*tg    );
            b[nt][1] = lds32(Kh + n * 40 + kk + 2*tg + 8);
        }
        #pragma unroll
        for (int mt = 0; mt < 2; mt++)
            #pragma unroll
            for (int nt = 0; nt < 8; nt++)
                MMA_BF16(sc[mt][nt], a[mt], b[nt]);
    }

    // ---- bias + mask + exp + row sums ----
    const float* brow = g_bias + head * 4096;
    float rs[2][2] = {{0.f, 0.f}, {0.f, 0.f}};
    #pragma unroll
    for (int mt = 0; mt < 2; mt++) {
        int ra_ = r0 + mt*16 + g, rb_ = ra_ + 8;
        #pragma unroll
        for (int nt = 0; nt < 8; nt++) {
            int c0 = nt*8 + 2*tg;
            float2 ba = *(const float2*)(brow + ra_*64 + c0);
            float2 bb = *(const float2*)(brow + rb_*64 + c0);
            float2 ma = *(const float2*)(Ms + ra_*68 + c0);
            float2 mb = *(const float2*)(Ms + rb_*68 + c0);
            sc[mt][nt][0] = __expf(sc[mt][nt][0] + ba.x + ma.x);
            sc[mt][nt][1] = __expf(sc[mt][nt][1] + ba.y + ma.y);
            sc[mt][nt][2] = __expf(sc[mt][nt][2] + bb.x + mb.x);
            sc[mt][nt][3] = __expf(sc[mt][nt][3] + bb.y + mb.y);
            rs[mt][0] += sc[mt][nt][0] + sc[mt][nt][1];
            rs[mt][1] += sc[mt][nt][2] + sc[mt][nt][3];
        }
    }
    float inv[2][2];
    #pragma unroll
    for (int mt = 0; mt < 2; mt++) {
        #pragma unroll
        for (int hh = 0; hh < 2; hh++) {
            float v = rs[mt][hh];
            v += __shfl_xor_sync(0xffffffffu, v, 1);
            v += __shfl_xor_sync(0xffffffffu, v, 2);
            inv[mt][hh] = 1.0f / v;
        }
    }

    // ---- O[32x32] = P @ V ; P A-frags pack directly from C-frags ----
    float oa[2][4][4];
    #pragma unroll
    for (int mt = 0; mt < 2; mt++)
        #pragma unroll
        for (int nt = 0; nt < 4; nt++)
            #pragma unroll
            for (int c = 0; c < 4; c++) oa[mt][nt][c] = 0.0f;

    #pragma unroll
    for (int ks = 0; ks < 4; ks++) {
        uint32_t pa[2][4];
        #pragma unroll
        for (int mt = 0; mt < 2; mt++) {
            pa[mt][0] = packbf(sc[mt][2*ks  ][0], sc[mt][2*ks  ][1]);
            pa[mt][1] = packbf(sc[mt][2*ks  ][2], sc[mt][2*ks  ][3]);
            pa[mt][2] = packbf(sc[mt][2*ks+1][0], sc[mt][2*ks+1][1]);
            pa[mt][3] = packbf(sc[mt][2*ks+1][2], sc[mt][2*ks+1][3]);
        }
        uint32_t vb[4][2];
        #pragma unroll
        for (int nt = 0; nt < 4; nt++) {
            int n = nt * 8 + g;   // output dim
            vb[nt][0] = lds32(Vh + n * 72 + ks*16 + 2*tg    );
            vb[nt][1] = lds32(Vh + n * 72 + ks*16 + 2*tg + 8);
        }
        #pragma unroll
        for (int mt = 0; mt < 2; mt++)
            #pragma unroll
            for (int nt = 0; nt < 4; nt++)
                MMA_BF16(oa[mt][nt], pa[mt], vb[nt]);
    }

    // ---- normalize + store (bf16) ----
    #pragma unroll
    for (int mt = 0; mt < 2; mt++) {
        int ra_ = r0 + mt*16 + g;
        #pragma unroll
        for (int nt = 0; nt < 4; nt++) {
            int c0 = head*32 + nt*8 + 2*tg;
            __nv_bfloat162* o0 = (__nv_bfloat162*)(g_attn + ((size_t)win*64 + ra_)*128 + c0);
            __nv_bfloat162* o1 = (__nv_bfloat162*)(g_attn + ((size_t)win*64 + ra_ + 8)*128 + c0);
            *o0 = __floats2bfloat162_rn(oa[mt][nt][0]*inv[mt][0], oa[mt][nt][1]*inv[mt][0]);
            *o1 = __floats2bfloat162_rn(oa[mt][nt][2]*inv[mt][1], oa[mt][nt][3]*inv[mt][1]);
        }
    }
}

// ---------------- launcher ----------------
extern "C" void kernel_launch(void* const* d_in, const int* in_sizes, int n_in,
                              void* d_out, int out_size)
{
    const float* x       = (const float*)d_in[0];
    const float* mask    = (const float*)d_in[1];
    const float* n1s     = (const float*)d_in[2];
    const float* n1b     = (const float*)d_in[3];
    const float* qkv_w   = (const float*)d_in[4];
    const float* table   = (const float*)d_in[5];
    const float* proj_w  = (const float*)d_in[6];
    const float* proj_b  = (const float*)d_in[7];
    const float* n2s     = (const float*)d_in[8];
    const float* n2b     = (const float*)d_in[9];
    const float* mlp_w1  = (const float*)d_in[10];
    const float* mlp_b1  = (const float*)d_in[11];
    const float* mlp_w2  = (const float*)d_in[12];
    const float* mlp_b2  = (const float*)d_in[13];
    float* out = (float*)d_out;

    float *p_xw, *p_xn2;
    __nv_bfloat16 *p_hid, *p_attn;
    __nv_bfloat16 *p_wqkv_t, *p_wproj_t, *p_w1_t, *p_w2_t;
    cudaGetSymbolAddress((void**)&p_xw,     g_xw);
    cudaGetSymbolAddress((void**)&p_xn2,    g_xn2);
    cudaGetSymbolAddress((void**)&p_hid,    g_hid);
    cudaGetSymbolAddress((void**)&p_attn,   g_attn);
    cudaGetSymbolAddress((void**)&p_wqkv_t, g_wqkv_t);
    cudaGetSymbolAddress((void**)&p_wproj_t,g_wproj_t);
    cudaGetSymbolAddress((void**)&p_w1_t,   g_w1_t);
    cudaGetSymbolAddress((void**)&p_w2_t,   g_w2_t);

    const int DSM = 73728;   // max(pipeline 40960, epilogue 67584) rounded up
    cudaFuncSetAttribute((void*)gemm_bf16<128, float, QkvEpi>,          cudaFuncAttributeMaxDynamicSharedMemorySize, DSM);
    cudaFuncSetAttribute((void*)gemm_bf16<128, __nv_bfloat16, ProjEpi>, cudaFuncAttributeMaxDynamicSharedMemorySize, DSM);
    cudaFuncSetAttribute((void*)gemm_bf16<128, float, Mlp1Epi>,         cudaFuncAttributeMaxDynamicSharedMemorySize, DSM);
    cudaFuncSetAttribute((void*)gemm_bf16<512, __nv_bfloat16, Mlp2Epi>, cudaFuncAttributeMaxDynamicSharedMemorySize, DSM);
    const int ADSM = 76800;  // Q 20480 + K 20480 + Vt 18432 + Ms 17408
    cudaFuncSetAttribute(attn_bf16_kernel, cudaFuncAttributeMaxDynamicSharedMemorySize, ADSM);

    const int ROWBLK = (int)(MROWS / 128);  // 2048

    transpose_kernel<<<dim3(12, 4),  dim3(32, 32)>>>(qkv_w,  p_wqkv_t, 128, 384);
    transpose_kernel<<<dim3(4, 4),   dim3(32, 32)>>>(proj_w, p_wproj_t, 128, 128);
    transpose_kernel<<<dim3(16, 4),  dim3(32, 32)>>>(mlp_w1, p_w1_t,   128, 512);
    transpose_kernel<<<dim3(4, 16),  dim3(32, 32)>>>(mlp_w2, p_w2_t,   512, 128);
    bias_kernel<<<64, 64>>>(table);

    // 1. LN1 + shift + window partition
    ln1_shift_kernel<<<(int)(MROWS / 8), 256>>>(x, n1s, n1b);
    // 2. QKV projection (q pre-scaled, bf16 out)
    gemm_bf16<128, float, QkvEpi><<<dim3(3, ROWBLK), 256, DSM>>>(p_xw, p_wqkv_t, QkvEpi{});
    // 3. windowed attention (bf16 tensor core)
    attn_bf16_kernel<<<NWIN, 256, ADSM>>>(mask);
    // 4. output projection + window reverse + roll + residual
    gemm_bf16<128, __nv_bfloat16, ProjEpi><<<dim3(1, ROWBLK), 256, DSM>>>(p_attn, p_wproj_t, ProjEpi{x, proj_b});
    // 5. LN2
    ln2_kernel<<<(int)(MROWS / 8), 256>>>(n2s, n2b);
    // 6. MLP up + GELU (bf16 hidden)
    gemm_bf16<128, float, Mlp1Epi><<<dim3(4, ROWBLK), 256, DSM>>>(p_xn2, p_w1_t, Mlp1Epi{mlp_b1});
    // 7. MLP down + residual -> out
    gemm_bf16<512, __nv_bfloat16, Mlp2Epi><<<dim3(1, ROWBLK), 256, DSM>>>(p_hid, p_w2_t, Mlp2Epi{mlp_b2, out});
}

// round 8
// speedup vs baseline: 2.8278x; 1.1880x over previous
#include <cuda_runtime.h>
#include <cuda_bf16.h>
#include <cstdint>

// ---------------- problem constants ----------------
constexpr int CH = 128, HEADS = 4, HD = 32, NTOK = 64;
constexpr int NWIN = 4096;
constexpr long long MROWS = 262144;   // 4096 windows * 64 tokens
constexpr int HID = 512;

// ---------------- scratch (static device globals) ----------------
__device__ __align__(16) __nv_bfloat16 g_xw  [MROWS * CH];
__device__ __align__(16) __nv_bfloat16 g_q   [MROWS * CH];
__device__ __align__(16) __nv_bfloat16 g_k   [MROWS * CH];
__device__ __align__(16) __nv_bfloat16 g_v   [MROWS * CH];
__device__ __align__(16) float g_bias[HEADS * NTOK * NTOK];
__device__ __align__(16) __nv_bfloat16 g_attn[MROWS * CH];
__device__ __align__(16) float g_x1  [MROWS * CH];
__device__ __align__(16) __nv_bfloat16 g_xn2 [MROWS * CH];
__device__ __align__(16) __nv_bfloat16 g_hid [MROWS * HID];
// transposed bf16 weights [N, K]
__device__ __align__(16) __nv_bfloat16 g_wqkv_t[384 * 128];
__device__ __align__(16) __nv_bfloat16 g_wproj_t[128 * 128];
__device__ __align__(16) __nv_bfloat16 g_w1_t  [512 * 128];
__device__ __align__(16) __nv_bfloat16 g_w2_t  [128 * 512];

__device__ __forceinline__ uint32_t packbf(float lo, float hi) {
    __nv_bfloat162 h = __floats2bfloat162_rn(lo, hi);
    return *(uint32_t*)&h;
}
__device__ __forceinline__ uint32_t lds32(const __nv_bfloat16* p) {
    return *(const uint32_t*)p;
}
__device__ __forceinline__ uint32_t smem_u32(const void* p) {
    uint32_t a;
    asm("{ .reg .u64 t; cvta.to.shared.u64 t, %1; cvt.u32.u64 %0, t; }" : "=r"(a) : "l"(p));
    return a;
}
__device__ __forceinline__ void cpa16(uint32_t dst, const void* src) {
    asm volatile("cp.async.cg.shared.global [%0], [%1], 16;" :: "r"(dst), "l"(src));
}
__device__ __forceinline__ void cpa_commit() { asm volatile("cp.async.commit_group;" ::: "memory"); }
template<int N> __device__ __forceinline__ void cpa_wait() {
    asm volatile("cp.async.wait_group %0;" :: "n"(N) : "memory");
}
#define MMA_BF16(acc, a, b) \
    asm volatile("mma.sync.aligned.m16n8k16.row.col.f32.bf16.bf16.f32 " \
        "{%0,%1,%2,%3}, {%4,%5,%6,%7}, {%8,%9}, {%0,%1,%2,%3};" \
        : "+f"((acc)[0]), "+f"((acc)[1]), "+f"((acc)[2]), "+f"((acc)[3]) \
        : "r"((a)[0]), "r"((a)[1]), "r"((a)[2]), "r"((a)[3]), "r"((b)[0]), "r"((b)[1]))

// ---------------- LN1 + cyclic shift + window partition (bf16 out) ----------------
__global__ __launch_bounds__(256) void ln1_shift_kernel(
    const float* __restrict__ x, const float* __restrict__ sc, const float* __restrict__ bi)
{
    int warp = (blockIdx.x * 256 + threadIdx.x) >> 5;
    int lane = threadIdx.x & 31;
    int t = warp & 63, win = warp >> 6;
    int b = win >> 11, widx = win & 2047;
    int wd = widx >> 8, wh = (widx >> 4) & 15, ww = widx & 15;
    int td = t >> 4, th = (t >> 2) & 3, tw = t & 3;
    int d = (wd*4 + td + 2) & 31;
    int h = (wh*4 + th + 2) & 63;
    int w = (ww*4 + tw + 2) & 63;
    const float4* src = (const float4*)(x + ((size_t)(((b*32 + d)*64 + h)*64 + w)) * CH);
    float4 v = src[lane];
    float s  = v.x + v.y + v.z + v.w;
    float ss = v.x*v.x + v.y*v.y + v.z*v.z + v.w*v.w;
    #pragma unroll
    for (int o = 16; o; o >>= 1) {
        s  += __shfl_xor_sync(0xffffffffu, s,  o);
        ss += __shfl_xor_sync(0xffffffffu, ss, o);
    }
    float mean = s * (1.0f/128.0f);
    float var  = ss * (1.0f/128.0f) - mean*mean;
    float r = rsqrtf(var + 1e-6f);
    float4 g4 = ((const float4*)sc)[lane];
    float4 b4 = ((const float4*)bi)[lane];
    uint2 o2;
    o2.x = packbf((v.x - mean)*r*g4.x + b4.x, (v.y - mean)*r*g4.y + b4.y);
    o2.y = packbf((v.z - mean)*r*g4.z + b4.z, (v.w - mean)*r*g4.w + b4.w);
    ((uint2*)(g_xw + (size_t)warp * CH))[lane] = o2;
}

// ---------------- relative position bias ----------------
__global__ void bias_kernel(const float* __restrict__ table)
{
    int q = blockIdx.x, k = threadIdx.x;
    int qd = q >> 4, qh = (q >> 2) & 3, qw = q & 3;
    int kd = k >> 4, kh = (k >> 2) & 3, kw = k & 3;
    int idx = (qh - kh + 3) * 49 + (qd - kd + 3) * 7 + (qw - kw + 3);
    #pragma unroll
    for (int h = 0; h < HEADS; h++)
        g_bias[h * 4096 + q * 64 + k] = table[idx * HEADS + h];
}

// ---------------- weight transpose to bf16 ----------------
__global__ void transpose_kernel(const float* __restrict__ src, __nv_bfloat16* __restrict__ dst, int K, int N)
{
    __shared__ float tile[32][33];
    int n0 = blockIdx.x * 32, k0 = blockIdx.y * 32;
    int tx = threadIdx.x, ty = threadIdx.y;
    tile[ty][tx] = src[(size_t)(k0 + ty) * N + n0 + tx];
    __syncthreads();
    dst[(size_t)(n0 + ty) * K + k0 + tx] = __float2bfloat16(tile[tx][ty]);
}

// ---------------- epilogues (apply on staged 128x132 fp32 tile) ----------------
struct QkvEpi {
    __device__ void apply(const float* st, int row0, int col0, int tid) const {
        #pragma unroll
        for (int i = 0; i < 64; i++) {
            int idx = tid + i * 256;
            int m = row0 + (idx >> 7);
            int n = col0 + (idx & 127);
            float v = st[(idx >> 7) * 132 + (idx & 127)];
            int sel = n >> 7, c = n & 127;
            int head = c >> 5, e = c & 31;
            int win = m >> 6, t = m & 63;
            size_t o = (((size_t)win * HEADS + head) * NTOK + t) * HD + e;
            if (sel == 0)      g_q[o] = __float2bfloat16(v * 0.17677669529663687f);
            else if (sel == 1) g_k[o] = __float2bfloat16(v);
            else               g_v[o] = __float2bfloat16(v);
        }
    }
};
// proj: residual add + window reverse + roll -> g_x1 (fp32), fused LN2 -> g_xn2 (bf16)
struct ProjLn2Epi {
    const float* x; const float* pb; const float* sc2; const float* bi2;
    __device__ void apply(const float* st, int row0, int col0, int tid) const {
        int wid = tid >> 5, lane = tid & 31;
        float4 pb4 = ((const float4*)pb)[lane];
        float4 g4  = ((const float4*)sc2)[lane];
        float4 b4  = ((const float4*)bi2)[lane];
        #pragma unroll
        for (int i = 0; i < 16; i++) {
            int r = wid * 16 + i;
            int m = row0 + r;
            int win = m >> 6, t = m & 63;
            int b = win >> 11, widx = win & 2047;
            int wd = widx >> 8, wh = (widx >> 4) & 15, ww = widx & 15;
            int td = t >> 4, th = (t >> 2) & 3, tw = t & 3;
            int d = (wd*4 + td + 2) & 31;
            int h = (wh*4 + th + 2) & 63;
            int w = (ww*4 + tw + 2) & 63;
            size_t ob = (size_t)(((b*32 + d)*64 + h)*64 + w) * CH;
            float4 v  = *(const float4*)(st + r * 132 + lane * 4);
            float4 xv = ((const float4*)(x + ob))[lane];
            float4 x1;
            x1.x = v.x + pb4.x + xv.x;
            x1.y = v.y + pb4.y + xv.y;
            x1.z = v.z + pb4.z + xv.z;
            x1.w = v.w + pb4.w + xv.w;
            ((float4*)(g_x1 + ob))[lane] = x1;
            float s  = x1.x + x1.y + x1.z + x1.w;
            float ss = x1.x*x1.x + x1.y*x1.y + x1.z*x1.z + x1.w*x1.w;
            #pragma unroll
            for (int o = 16; o; o >>= 1) {
                s  += __shfl_xor_sync(0xffffffffu, s,  o);
                ss += __shfl_xor_sync(0xffffffffu, ss, o);
            }
            float mean = s * (1.0f/128.0f);
            float var  = ss * (1.0f/128.0f) - mean*mean;
            float rr = rsqrtf(var + 1e-6f);
            uint2 o2;
            o2.x = packbf((x1.x - mean)*rr*g4.x + b4.x, (x1.y - mean)*rr*g4.y + b4.y);
            o2.y = packbf((x1.z - mean)*rr*g4.z + b4.z, (x1.w - mean)*rr*g4.w + b4.w);
            ((uint2*)(g_xn2 + ob))[lane] = o2;
        }
    }
};
struct Mlp1Epi {
    const float* b1;
    __device__ void apply(const float* st, int row0, int col0, int tid) const {
        #pragma unroll
        for (int i = 0; i < 64; i++) {
            int idx = tid + i * 256;
            int m = row0 + (idx >> 7);
            int n = col0 + (idx & 127);
            float v = st[(idx >> 7) * 132 + (idx & 127)];
            float u = v + b1[n];
            float z2 = 1.5957691216057308f * (u + 0.044715f * u * u * u);
            float sig = 1.0f / (1.0f + __expf(-z2));
            g_hid[(size_t)m * HID + n] = __float2bfloat16(u * sig);
        }
    }
};
struct Mlp2Epi {
    const float* b2; float* out;
    __device__ void apply(const float* st, int row0, int col0, int tid) const {
        #pragma unroll
        for (int i = 0; i < 64; i++) {
            int idx = tid + i * 256;
            int m = row0 + (idx >> 7);
            int n = col0 + (idx & 127);
            size_t o = (size_t)m * CH + n;
            out[o] = st[(idx >> 7) * 132 + (idx & 127)] + b2[n] + g_x1[o];
        }
    }
};

// ---------------- bf16 m16n8k16 GEMM with cp.async double-buffer ----------------
// C tile [128x128] = A[row0.., KTOT] @ BT[col0.., KTOT]^T ; BK = 32 bf16.
// per-buffer: As 128x40 bf16 (10240 B) + Bs 128x40 bf16 (10240 B) -> 20480 B, 2 buffers.
// grid: (NTILES, ROWBLK) — x fastest so the A tile is L2-shared across N-tiles.
template<int KTOT, class Epi>
__global__ __launch_bounds__(256, 2) void gemm_bf16(
    const __nv_bfloat16* __restrict__ A, const __nv_bfloat16* __restrict__ BT, Epi epi)
{
    extern __shared__ char smraw[];
    __nv_bfloat16* sm = (__nv_bfloat16*)smraw;
    const uint32_t smb = smem_u32(smraw);
    const int tid = threadIdx.x;
    const int wid = tid >> 5, lane = tid & 31;
    const int row0 = blockIdx.y * 128, col0 = blockIdx.x * 128;
    const int wm0 = (wid >> 1) * 32, wn0 = (wid & 1) * 64;
    const int g = lane >> 2, tg = lane & 3;

    float acc[2][8][4];
    #pragma unroll
    for (int mt = 0; mt < 2; mt++)
        #pragma unroll
        for (int nt = 0; nt < 8; nt++)
            #pragma unroll
            for (int c = 0; c < 4; c++) acc[mt][nt][c] = 0.0f;

    auto prefetch = [&](int kc, int buf) {
        uint32_t base = smb + (uint32_t)buf * 20480u;
        #pragma unroll
        for (int i = 0; i < 2; i++) {
            int idx = tid + i * 256;           // 0..511
            int r = idx >> 2, c8 = (idx & 3) * 8;
            uint32_t off = (uint32_t)(r * 40 + c8) * 2u;
            cpa16(base + off,          A  + (size_t)(row0 + r) * KTOT + kc * 32 + c8);
            cpa16(base + 10240u + off, BT + (size_t)(col0 + r) * KTOT + kc * 32 + c8);
        }
        cpa_commit();
    };
    auto compute = [&](int buf) {
        const __nv_bfloat16* As_ = sm + buf * 10240;
        const __nv_bfloat16* Bs_ = As_ + 5120;
        #pragma unroll
        for (int ks = 0; ks < 2; ks++) {
            const int kk = ks * 16;
            uint32_t a[2][4], b[8][2];
            #pragma unroll
            for (int mt = 0; mt < 2; mt++) {
                int r = wm0 + mt * 16;
                a[mt][0] = lds32(As_ + (r + g    ) * 40 + kk + 2*tg    );
                a[mt][1] = lds32(As_ + (r + g + 8) * 40 + kk + 2*tg    );
                a[mt][2] = lds32(As_ + (r + g    ) * 40 + kk + 2*tg + 8);
                a[mt][3] = lds32(As_ + (r + g + 8) * 40 + kk + 2*tg + 8);
            }
            #pragma unroll
            for (int nt = 0; nt < 8; nt++) {
                int n = wn0 + nt * 8 + g;
                b[nt][0] = lds32(Bs_ + n * 40 + kk + 2*tg    );
                b[nt][1] = lds32(Bs_ + n * 40 + kk + 2*tg + 8);
            }
            #pragma unroll
            for (int mt = 0; mt < 2; mt++)
                #pragma unroll
                for (int nt = 0; nt < 8; nt++)
                    MMA_BF16(acc[mt][nt], a[mt], b[nt]);
        }
    };

    constexpr int NKC = KTOT / 32;
    prefetch(0, 0);
    #pragma unroll
    for (int kc = 0; kc < NKC; kc++) {
        if (kc + 1 < NKC) {
            prefetch(kc + 1, (kc + 1) & 1);
            cpa_wait<1>();
        } else {
            cpa_wait<0>();
        }
        __syncthreads();
        compute(kc & 1);
        __syncthreads();
    }

    // epilogue: stage fp32 C to smem, then apply
    float* st = (float*)smraw;   // 128 x 132
    #pragma unroll
    for (int mt = 0; mt < 2; mt++)
        #pragma unroll
        for (int nt = 0; nt < 8; nt++) {
            int r = wm0 + mt * 16;
            int c = wn0 + nt * 8 + tg * 2;
            *(float2*)(st + (r + g    ) * 132 + c) = make_float2(acc[mt][nt][0], acc[mt][nt][1]);
            *(float2*)(st + (r + g + 8) * 132 + c) = make_float2(acc[mt][nt][2], acc[mt][nt][3]);
        }
    __syncthreads();
    epi.apply(st, row0, col0, tid);
}

// ---------------- attention (bf16 m16n8k16): one block per window ----------------
__global__ __launch_bounds__(256) void attn_bf16_kernel(const float* __restrict__ mask)
{
    extern __shared__ char smraw[];
    __nv_bfloat16* Qs = (__nv_bfloat16*)smraw;                 // [4][64][40]
    __nv_bfloat16* Ks = Qs + 10240;                            // [4][64][40]
    __nv_bfloat16* Vt = Ks + 10240;                            // [4][32][72] dim-major

    const int win = blockIdx.x;
    const int tid = threadIdx.x;
    const int wid = tid >> 5, lane = tid & 31;
    const int head = wid >> 1;
    const int r0 = (wid & 1) * 32;
    const int g = lane >> 2, tg = lane & 3;

    const uint4* bq = (const uint4*)(g_q + (size_t)win * 8192);
    const uint4* bk = (const uint4*)(g_k + (size_t)win * 8192);
    const uint4* bv = (const uint4*)(g_v + (size_t)win * 8192);
    #pragma unroll
    for (int i = 0; i < 4; i++) {
        int f = tid + i * 256;        // 0..1023
        int h = f >> 8;
        int tok = (f >> 2) & 63;
        int q8 = (f & 3) * 8;
        *(uint4*)(Qs + h*2560 + tok*40 + q8) = bq[f];
        *(uint4*)(Ks + h*2560 + tok*40 + q8) = bk[f];
        uint4 vv = bv[f];
        __nv_bfloat16 tmp[8];
        *(uint4*)tmp = vv;
        #pragma unroll
        for (int j = 0; j < 8; j++)
            Vt[h*2304 + (q8 + j)*72 + tok] = tmp[j];
    }
    __syncthreads();

    const __nv_bfloat16* Qh = Qs + head * 2560;
    const __nv_bfloat16* Kh = Ks + head * 2560;
    const __nv_bfloat16* Vh = Vt + head * 2304;

    float sc[2][8][4];
    #pragma unroll
    for (int mt = 0; mt < 2; mt++)
        #pragma unroll
        for (int nt = 0; nt < 8; nt++)
            #pragma unroll
            for (int c = 0; c < 4; c++) sc[mt][nt][c] = 0.0f;

    #pragma unroll
    for (int ks = 0; ks < 2; ks++) {
        const int kk = ks * 16;
        uint32_t a[2][4], b[8][2];
        #pragma unroll
        for (int mt = 0; mt < 2; mt++) {
            int r = r0 + mt * 16;
            a[mt][0] = lds32(Qh + (r + g    ) * 40 + kk + 2*tg    );
            a[mt][1] = lds32(Qh + (r + g + 8) * 40 + kk + 2*tg    );
            a[mt][2] = lds32(Qh + (r + g    ) * 40 + kk + 2*tg + 8);
            a[mt][3] = lds32(Qh + (r + g + 8) * 40 + kk + 2*tg + 8);
        }
        #pragma unroll
        for (int nt = 0; nt < 8; nt++) {
            int n = nt * 8 + g;
            b[nt][0] = lds32(Kh + n * 40 + kk + 2*tg    );
            b[nt][1] = lds32(Kh + n * 40 + kk + 2*tg + 8);
        }
        #pragma unroll
        for (int mt = 0; mt < 2; mt++)
            #pragma unroll
            for (int nt = 0; nt < 8; nt++)
                MMA_BF16(sc[mt][nt], a[mt], b[nt]);
    }

    // bias + mask (both from L2-hot global) + exp + row sums
    const float* brow = g_bias + head * 4096;
    const float* mrow = mask + (size_t)(win & 2047) * 4096;
    float rs[2][2] = {{0.f, 0.f}, {0.f, 0.f}};
    #pragma unroll
    for (int mt = 0; mt < 2; mt++) {
        int ra_ = r0 + mt*16 + g, rb_ = ra_ + 8;
        #pragma unroll
        for (int nt = 0; nt < 8; nt++) {
            int c0 = nt*8 + 2*tg;
            float2 ba = *(const float2*)(brow + ra_*64 + c0);
            float2 bb = *(const float2*)(brow + rb_*64 + c0);
            float2 ma = *(const float2*)(mrow + ra_*64 + c0);
            float2 mb = *(const float2*)(mrow + rb_*64 + c0);
            sc[mt][nt][0] = __expf(sc[mt][nt][0] + ba.x + ma.x);
            sc[mt][nt][1] = __expf(sc[mt][nt][1] + ba.y + ma.y);
            sc[mt][nt][2] = __expf(sc[mt][nt][2] + bb.x + mb.x);
            sc[mt][nt][3] = __expf(sc[mt][nt][3] + bb.y + mb.y);
            rs[mt][0] += sc[mt][nt][0] + sc[mt][nt][1];
            rs[mt][1] += sc[mt][nt][2] + sc[mt][nt][3];
        }
    }
    float inv[2][2];
    #pragma unroll
    for (int mt = 0; mt < 2; mt++) {
        #pragma unroll
        for (int hh = 0; hh < 2; hh++) {
            float v = rs[mt][hh];
            v += __shfl_xor_sync(0xffffffffu, v, 1);
            v += __shfl_xor_sync(0xffffffffu, v, 2);
            inv[mt][hh] = 1.0f / v;
        }
    }

    // O = P @ V ; P A-frags pack directly from C-frags
    float oa[2][4][4];
    #pragma unroll
    for (int mt = 0; mt < 2; mt++)
        #pragma unroll
        for (int nt = 0; nt < 4; nt++)
            #pragma unroll
            for (int c = 0; c < 4; c++) oa[mt][nt][c] = 0.0f;

    #pragma unroll
    for (int ks = 0; ks < 4; ks++) {
        uint32_t pa[2][4];
        #pragma unroll
        for (int mt = 0; mt < 2; mt++) {
            pa[mt][0] = packbf(sc[mt][2*ks  ][0], sc[mt][2*ks  ][1]);
            pa[mt][1] = packbf(sc[mt][2*ks  ][2], sc[mt][2*ks  ][3]);
            pa[mt][2] = packbf(sc[mt][2*ks+1][0], sc[mt][2*ks+1][1]);
            pa[mt][3] = packbf(sc[mt][2*ks+1][2], sc[mt][2*ks+1][3]);
        }
        uint32_t vb[4][2];
        #pragma unroll
        for (int nt = 0; nt < 4; nt++) {
            int n = nt * 8 + g;
            vb[nt][0] = lds32(Vh + n * 72 + ks*16 + 2*tg    );
            vb[nt][1] = lds32(Vh + n * 72 + ks*16 + 2*tg + 8);
        }
        #pragma unroll
        for (int mt = 0; mt < 2; mt++)
            #pragma unroll
            for (int nt = 0; nt < 4; nt++)
                MMA_BF16(oa[mt][nt], pa[mt], vb[nt]);
    }

    #pragma unroll
    for (int mt = 0; mt < 2; mt++) {
        int ra_ = r0 + mt*16 + g;
        #pragma unroll
        for (int nt = 0; nt < 4; nt++) {
            int c0 = head*32 + nt*8 + 2*tg;
            __nv_bfloat162* o0 = (__nv_bfloat162*)(g_attn + ((size_t)win*64 + ra_)*128 + c0);
            __nv_bfloat162* o1 = (__nv_bfloat162*)(g_attn + ((size_t)win*64 + ra_ + 8)*128 + c0);
            *o0 = __floats2bfloat162_rn(oa[mt][nt][0]*inv[mt][0], oa[mt][nt][1]*inv[mt][0]);
            *o1 = __floats2bfloat162_rn(oa[mt][nt][2]*inv[mt][1], oa[mt][nt][3]*inv[mt][1]);
        }
    }
}

// ---------------- launcher ----------------
extern "C" void kernel_launch(void* const* d_in, const int* in_sizes, int n_in,
                              void* d_out, int out_size)
{
    const float* x       = (const float*)d_in[0];
    const float* mask    = (const float*)d_in[1];
    const float* n1s     = (const float*)d_in[2];
    const float* n1b     = (const float*)d_in[3];
    const float* qkv_w   = (const float*)d_in[4];
    const float* table   = (const float*)d_in[5];
    const float* proj_w  = (const float*)d_in[6];
    const float* proj_b  = (const float*)d_in[7];
    const float* n2s     = (const float*)d_in[8];
    const float* n2b     = (const float*)d_in[9];
    const float* mlp_w1  = (const float*)d_in[10];
    const float* mlp_b1  = (const float*)d_in[11];
    const float* mlp_w2  = (const float*)d_in[12];
    const float* mlp_b2  = (const float*)d_in[13];
    float* out = (float*)d_out;

    __nv_bfloat16 *p_xw, *p_xn2, *p_hid, *p_attn;
    __nv_bfloat16 *p_wqkv_t, *p_wproj_t, *p_w1_t, *p_w2_t;
    cudaGetSymbolAddress((void**)&p_xw,     g_xw);
    cudaGetSymbolAddress((void**)&p_xn2,    g_xn2);
    cudaGetSymbolAddress((void**)&p_hid,    g_hid);
    cudaGetSymbolAddress((void**)&p_attn,   g_attn);
    cudaGetSymbolAddress((void**)&p_wqkv_t, g_wqkv_t);
    cudaGetSymbolAddress((void**)&p_wproj_t,g_wproj_t);
    cudaGetSymbolAddress((void**)&p_w1_t,   g_w1_t);
    cudaGetSymbolAddress((void**)&p_w2_t,   g_w2_t);

    const int DSM = 67584;   // max(pipeline 40960, epilogue 128*132*4)
    cudaFuncSetAttribute((void*)gemm_bf16<128, QkvEpi>,    cudaFuncAttributeMaxDynamicSharedMemorySize, DSM);
    cudaFuncSetAttribute((void*)gemm_bf16<128, ProjLn2Epi>,cudaFuncAttributeMaxDynamicSharedMemorySize, DSM);
    cudaFuncSetAttribute((void*)gemm_bf16<128, Mlp1Epi>,   cudaFuncAttributeMaxDynamicSharedMemorySize, DSM);
    cudaFuncSetAttribute((void*)gemm_bf16<512, Mlp2Epi>,   cudaFuncAttributeMaxDynamicSharedMemorySize, DSM);
    const int ADSM = 59392;  // Q 20480 + K 20480 + Vt 18432
    cudaFuncSetAttribute(attn_bf16_kernel, cudaFuncAttributeMaxDynamicSharedMemorySize, ADSM);

    const int ROWBLK = (int)(MROWS / 128);  // 2048

    transpose_kernel<<<dim3(12, 4),  dim3(32, 32)>>>(qkv_w,  p_wqkv_t, 128, 384);
    transpose_kernel<<<dim3(4, 4),   dim3(32, 32)>>>(proj_w, p_wproj_t, 128, 128);
    transpose_kernel<<<dim3(16, 4),  dim3(32, 32)>>>(mlp_w1, p_w1_t,   128, 512);
    transpose_kernel<<<dim3(4, 16),  dim3(32, 32)>>>(mlp_w2, p_w2_t,   512, 128);
    bias_kernel<<<64, 64>>>(table);

    // 1. LN1 + shift + window partition (bf16 out)
    ln1_shift_kernel<<<(int)(MROWS / 8), 256>>>(x, n1s, n1b);
    // 2. QKV projection (q pre-scaled, bf16 out)
    gemm_bf16<128, QkvEpi><<<dim3(3, ROWBLK), 256, DSM>>>(p_xw, p_wqkv_t, QkvEpi{});
    // 3. windowed attention (bf16 tensor core)
    attn_bf16_kernel<<<NWIN, 256, ADSM>>>(mask);
    // 4. proj + window reverse + roll + residual -> g_x1, fused LN2 -> g_xn2
    gemm_bf16<128, ProjLn2Epi><<<dim3(1, ROWBLK), 256, DSM>>>(
        p_attn, p_wproj_t, ProjLn2Epi{x, proj_b, n2s, n2b});
    // 5. MLP up + GELU (bf16 hidden)
    gemm_bf16<128, Mlp1Epi><<<dim3(4, ROWBLK), 256, DSM>>>(p_xn2, p_w1_t, Mlp1Epi{mlp_b1});
    // 6. MLP down + residual -> out
    gemm_bf16<512, Mlp2Epi><<<dim3(1, ROWBLK), 256, DSM>>>(p_hid, p_w2_t, Mlp2Epi{mlp_b2, out});
}

// round 9
// speedup vs baseline: 2.9802x; 1.0539x over previous
#include <cuda_runtime.h>
#include <cuda_bf16.h>
#include <cstdint>

// ---------------- problem constants ----------------
constexpr int CH = 128, HEADS = 4, HD = 32, NTOK = 64;
constexpr int NWIN = 4096;
constexpr long long MROWS = 262144;   // 4096 windows * 64 tokens
constexpr int HID = 512;

// ---------------- scratch (static device globals) ----------------
__device__ __align__(16) __nv_bfloat16 g_q   [MROWS * CH];
__device__ __align__(16) __nv_bfloat16 g_k   [MROWS * CH];
__device__ __align__(16) __nv_bfloat16 g_v   [MROWS * CH];
__device__ __align__(16) float g_bias[HEADS * NTOK * NTOK];
__device__ __align__(16) float g_x1  [MROWS * CH];
__device__ __align__(16) __nv_bfloat16 g_xn2 [MROWS * CH];
__device__ __align__(16) __nv_bfloat16 g_hid [MROWS * HID];
// transposed bf16 weights [N, K]
__device__ __align__(16) __nv_bfloat16 g_wqkv_t[384 * 128];
__device__ __align__(16) __nv_bfloat16 g_wproj_t[128 * 128];
__device__ __align__(16) __nv_bfloat16 g_w1_t  [512 * 128];
__device__ __align__(16) __nv_bfloat16 g_w2_t  [128 * 512];

__device__ __forceinline__ uint32_t packbf(float lo, float hi) {
    __nv_bfloat162 h = __floats2bfloat162_rn(lo, hi);
    return *(uint32_t*)&h;
}
__device__ __forceinline__ uint32_t lds32(const __nv_bfloat16* p) {
    return *(const uint32_t*)p;
}
__device__ __forceinline__ uint32_t smem_u32(const void* p) {
    uint32_t a;
    asm("{ .reg .u64 t; cvta.to.shared.u64 t, %1; cvt.u32.u64 %0, t; }" : "=r"(a) : "l"(p));
    return a;
}
__device__ __forceinline__ void cpa16(uint32_t dst, const void* src) {
    asm volatile("cp.async.cg.shared.global [%0], [%1], 16;" :: "r"(dst), "l"(src));
}
__device__ __forceinline__ void cpa_commit() { asm volatile("cp.async.commit_group;" ::: "memory"); }
template<int N> __device__ __forceinline__ void cpa_wait() {
    asm volatile("cp.async.wait_group %0;" :: "n"(N) : "memory");
}
#define MMA_BF16(acc, a, b) \
    asm volatile("mma.sync.aligned.m16n8k16.row.col.f32.bf16.bf16.f32 " \
        "{%0,%1,%2,%3}, {%4,%5,%6,%7}, {%8,%9}, {%0,%1,%2,%3};" \
        : "+f"((acc)[0]), "+f"((acc)[1]), "+f"((acc)[2]), "+f"((acc)[3]) \
        : "r"((a)[0]), "r"((a)[1]), "r"((a)[2]), "r"((a)[3]), "r"((b)[0]), "r"((b)[1]))

// ---------------- relative position bias ----------------
__global__ void bias_kernel(const float* __restrict__ table)
{
    int q = blockIdx.x, k = threadIdx.x;
    int qd = q >> 4, qh = (q >> 2) & 3, qw = q & 3;
    int kd = k >> 4, kh = (k >> 2) & 3, kw = k & 3;
    int idx = (qh - kh + 3) * 49 + (qd - kd + 3) * 7 + (qw - kw + 3);
    #pragma unroll
    for (int h = 0; h < HEADS; h++)
        g_bias[h * 4096 + q * 64 + k] = table[idx * HEADS + h];
}

// ---------------- weight transpose to bf16 ----------------
__global__ void transpose_kernel(const float* __restrict__ src, __nv_bfloat16* __restrict__ dst, int K, int N)
{
    __shared__ float tile[32][33];
    int n0 = blockIdx.x * 32, k0 = blockIdx.y * 32;
    int tx = threadIdx.x, ty = threadIdx.y;
    tile[ty][tx] = src[(size_t)(k0 + ty) * N + n0 + tx];
    __syncthreads();
    dst[(size_t)(n0 + ty) * K + k0 + tx] = __float2bfloat16(tile[tx][ty]);
}

// window mapping: row m -> gmem row base offset (after reverse+roll)
__device__ __forceinline__ size_t winrow_to_gmem(int m) {
    int t = m & 63, win = m >> 6;
    int b = win >> 11, widx = win & 2047;
    int wd = widx >> 8, wh = (widx >> 4) & 15, ww = widx & 15;
    int td = t >> 4, th = (t >> 2) & 3, tw = t & 3;
    int d = (wd*4 + td + 2) & 31;
    int h = (wh*4 + th + 2) & 63;
    int w = (ww*4 + tw + 2) & 63;
    return (size_t)(((b*32 + d)*64 + h)*64 + w) * CH;
}

// ---------------- fused LN1 + QKV GEMM ----------------
// grid (3, 2048): blockIdx.x = N-tile (q/k/v), blockIdx.y = 128-row tile.
// A (LN1'd, bf16) fully staged by warps; B fully staged via cp.async; 8 k16 iters.
__global__ __launch_bounds__(256) void qkv_fused_kernel(
    const float* __restrict__ x, const float* __restrict__ sc, const float* __restrict__ bi,
    const __nv_bfloat16* __restrict__ BT)
{
    extern __shared__ char smraw[];
    __nv_bfloat16* As = (__nv_bfloat16*)smraw;      // [128][136]
    __nv_bfloat16* Bs = As + 128 * 136;             // [128][136]
    const uint32_t smbB = smem_u32(Bs);
    const int tid = threadIdx.x;
    const int wid = tid >> 5, lane = tid & 31;
    const int row0 = blockIdx.y * 128, col0 = blockIdx.x * 128;
    const int wm0 = (wid >> 1) * 32, wn0 = (wid & 1) * 64;
    const int g = lane >> 2, tg = lane & 3;

    // B: full 128x128 tile via cp.async
    #pragma unroll
    for (int i = 0; i < 8; i++) {
        int idx = tid + i * 256;          // 0..2047
        int r = idx >> 4, c8 = (idx & 15) * 8;
        cpa16(smbB + (uint32_t)(r * 136 + c8) * 2u, BT + (size_t)(col0 + r) * 128 + c8);
    }
    cpa_commit();

    // A: warp-per-row LN1+shift gather, 16 rows/warp, 4 rows in flight
    float4 g4 = ((const float4*)sc)[lane];
    float4 b4 = ((const float4*)bi)[lane];
    #pragma unroll
    for (int i0 = 0; i0 < 16; i0 += 4) {
        float4 v[4];
        int rr[4];
        #pragma unroll
        for (int j = 0; j < 4; j++) {
            rr[j] = wid * 16 + i0 + j;
            v[j] = ((const float4*)(x + winrow_to_gmem(row0 + rr[j])))[lane];
        }
        #pragma unroll
        for (int j = 0; j < 4; j++) {
            float s  = v[j].x + v[j].y + v[j].z + v[j].w;
            float ss = v[j].x*v[j].x + v[j].y*v[j].y + v[j].z*v[j].z + v[j].w*v[j].w;
            #pragma unroll
            for (int o = 16; o; o >>= 1) {
                s  += __shfl_xor_sync(0xffffffffu, s,  o);
                ss += __shfl_xor_sync(0xffffffffu, ss, o);
            }
            float mean = s * (1.0f/128.0f);
            float var  = ss * (1.0f/128.0f) - mean*mean;
            float rq = rsqrtf(var + 1e-6f);
            uint2 o2;
            o2.x = packbf((v[j].x - mean)*rq*g4.x + b4.x, (v[j].y - mean)*rq*g4.y + b4.y);
            o2.y = packbf((v[j].z - mean)*rq*g4.z + b4.z, (v[j].w - mean)*rq*g4.w + b4.w);
            *(uint2*)(As + rr[j] * 136 + lane * 4) = o2;
        }
    }
    cpa_wait<0>();
    __syncthreads();

    float acc[2][8][4];
    #pragma unroll
    for (int mt = 0; mt < 2; mt++)
        #pragma unroll
        for (int nt = 0; nt < 8; nt++)
            #pragma unroll
            for (int c = 0; c < 4; c++) acc[mt][nt][c] = 0.0f;

    #pragma unroll
    for (int ks = 0; ks < 8; ks++) {
        const int kk = ks * 16;
        uint32_t a[2][4], b[8][2];
        #pragma unroll
        for (int mt = 0; mt < 2; mt++) {
            int r = wm0 + mt * 16;
            a[mt][0] = lds32(As + (r + g    ) * 136 + kk + 2*tg    );
            a[mt][1] = lds32(As + (r + g + 8) * 136 + kk + 2*tg    );
            a[mt][2] = lds32(As + (r + g    ) * 136 + kk + 2*tg + 8);
            a[mt][3] = lds32(As + (r + g + 8) * 136 + kk + 2*tg + 8);
        }
        #pragma unroll
        for (int nt = 0; nt < 8; nt++) {
            int n = wn0 + nt * 8 + g;
            b[nt][0] = lds32(Bs + n * 136 + kk + 2*tg    );
            b[nt][1] = lds32(Bs + n * 136 + kk + 2*tg + 8);
        }
        #pragma unroll
        for (int mt = 0; mt < 2; mt++)
            #pragma unroll
            for (int nt = 0; nt < 8; nt++)
                MMA_BF16(acc[mt][nt], a[mt], b[nt]);
    }
    __syncthreads();

    // epilogue: stage fp32, scatter q/k/v (q pre-scaled)
    float* st = (float*)smraw;   // 128 x 132
    #pragma unroll
    for (int mt = 0; mt < 2; mt++)
        #pragma unroll
        for (int nt = 0; nt < 8; nt++) {
            int r = wm0 + mt * 16;
            int c = wn0 + nt * 8 + tg * 2;
            *(float2*)(st + (r + g    ) * 132 + c) = make_float2(acc[mt][nt][0], acc[mt][nt][1]);
            *(float2*)(st + (r + g + 8) * 132 + c) = make_float2(acc[mt][nt][2], acc[mt][nt][3]);
        }
    __syncthreads();
    #pragma unroll
    for (int i = 0; i < 64; i++) {
        int idx = tid + i * 256;
        int m = row0 + (idx >> 7);
        int n = col0 + (idx & 127);
        float v = st[(idx >> 7) * 132 + (idx & 127)];
        int sel = n >> 7, c = n & 127;
        int head = c >> 5, e = c & 31;
        int win = m >> 6, t = m & 63;
        size_t o = (((size_t)win * HEADS + head) * NTOK + t) * HD + e;
        if (sel == 0)      g_q[o] = __float2bfloat16(v * 0.17677669529663687f);
        else if (sel == 1) g_k[o] = __float2bfloat16(v);
        else               g_v[o] = __float2bfloat16(v);
    }
}

// ---------------- attention + proj + residual + LN2 (one block per window) ----------------
__global__ __launch_bounds__(256) void attn_proj_kernel(
    const float* __restrict__ mask, const __nv_bfloat16* __restrict__ Wp,
    const float* __restrict__ x, const float* __restrict__ pb,
    const float* __restrict__ sc2, const float* __restrict__ bi2)
{
    extern __shared__ char smraw[];
    __nv_bfloat16* Qs  = (__nv_bfloat16*)smraw;       // [4][64][40] -> later Os [64][136]
    __nv_bfloat16* Ks  = Qs + 10240;                  // [4][64][40]
    __nv_bfloat16* Vt  = Ks + 10240;                  // [4][32][72]
    __nv_bfloat16* Wps = (__nv_bfloat16*)(smraw + 59392);  // [128][136] -> later ps [64][132] f32
    const uint32_t smbW = smem_u32(Wps);

    const int win = blockIdx.x;
    const int tid = threadIdx.x;
    const int wid = tid >> 5, lane = tid & 31;
    const int head = wid >> 1;
    const int r0 = (wid & 1) * 32;
    const int g = lane >> 2, tg = lane & 3;

    // prefetch proj weights (128x128 bf16) via cp.async
    #pragma unroll
    for (int i = 0; i < 8; i++) {
        int idx = tid + i * 256;
        int r = idx >> 4, c8 = (idx & 15) * 8;
        cpa16(smbW + (uint32_t)(r * 136 + c8) * 2u, Wp + (size_t)r * 128 + c8);
    }
    cpa_commit();

    // stage Q/K/V
    const uint4* bq = (const uint4*)(g_q + (size_t)win * 8192);
    const uint4* bk = (const uint4*)(g_k + (size_t)win * 8192);
    const uint4* bv = (const uint4*)(g_v + (size_t)win * 8192);
    #pragma unroll
    for (int i = 0; i < 4; i++) {
        int f = tid + i * 256;
        int h = f >> 8;
        int tok = (f >> 2) & 63;
        int q8 = (f & 3) * 8;
        *(uint4*)(Qs + h*2560 + tok*40 + q8) = bq[f];
        *(uint4*)(Ks + h*2560 + tok*40 + q8) = bk[f];
        uint4 vv = bv[f];
        __nv_bfloat16 tmp[8];
        *(uint4*)tmp = vv;
        #pragma unroll
        for (int j = 0; j < 8; j++)
            Vt[h*2304 + (q8 + j)*72 + tok] = tmp[j];
    }
    __syncthreads();

    const __nv_bfloat16* Qh = Qs + head * 2560;
    const __nv_bfloat16* Kh = Ks + head * 2560;
    const __nv_bfloat16* Vh = Vt + head * 2304;

    // ---- scores ----
    float scf[2][8][4];
    #pragma unroll
    for (int mt = 0; mt < 2; mt++)
        #pragma unroll
        for (int nt = 0; nt < 8; nt++)
            #pragma unroll
            for (int c = 0; c < 4; c++) scf[mt][nt][c] = 0.0f;

    #pragma unroll
    for (int ks = 0; ks < 2; ks++) {
        const int kk = ks * 16;
        uint32_t a[2][4], b[8][2];
        #pragma unroll
        for (int mt = 0; mt < 2; mt++) {
            int r = r0 + mt * 16;
            a[mt][0] = lds32(Qh + (r + g    ) * 40 + kk + 2*tg    );
            a[mt][1] = lds32(Qh + (r + g + 8) * 40 + kk + 2*tg    );
            a[mt][2] = lds32(Qh + (r + g    ) * 40 + kk + 2*tg + 8);
            a[mt][3] = lds32(Qh + (r + g + 8) * 40 + kk + 2*tg + 8);
        }
        #pragma unroll
        for (int nt = 0; nt < 8; nt++) {
            int n = nt * 8 + g;
            b[nt][0] = lds32(Kh + n * 40 + kk + 2*tg    );
            b[nt][1] = lds32(Kh + n * 40 + kk + 2*tg + 8);
        }
        #pragma unroll
        for (int mt = 0; mt < 2; mt++)
            #pragma unroll
            for (int nt = 0; nt < 8; nt++)
                MMA_BF16(scf[mt][nt], a[mt], b[nt]);
    }

    // ---- softmax (bias+mask from L2-hot global) ----
    const float* brow = g_bias + head * 4096;
    const float* mrow = mask + (size_t)(win & 2047) * 4096;
    float rs[2][2] = {{0.f, 0.f}, {0.f, 0.f}};
    #pragma unroll
    for (int mt = 0; mt < 2; mt++) {
        int ra_ = r0 + mt*16 + g, rb_ = ra_ + 8;
        #pragma unroll
        for (int nt = 0; nt < 8; nt++) {
            int c0 = nt*8 + 2*tg;
            float2 ba = *(const float2*)(brow + ra_*64 + c0);
            float2 bb = *(const float2*)(brow + rb_*64 + c0);
            float2 ma = *(const float2*)(mrow + ra_*64 + c0);
            float2 mb = *(const float2*)(mrow + rb_*64 + c0);
            scf[mt][nt][0] = __expf(scf[mt][nt][0] + ba.x + ma.x);
            scf[mt][nt][1] = __expf(scf[mt][nt][1] + ba.y + ma.y);
            scf[mt][nt][2] = __expf(scf[mt][nt][2] + bb.x + mb.x);
            scf[mt][nt][3] = __expf(scf[mt][nt][3] + bb.y + mb.y);
            rs[mt][0] += scf[mt][nt][0] + scf[mt][nt][1];
            rs[mt][1] += scf[mt][nt][2] + scf[mt][nt][3];
        }
    }
    float inv[2][2];
    #pragma unroll
    for (int mt = 0; mt < 2; mt++) {
        #pragma unroll
        for (int hh = 0; hh < 2; hh++) {
            float v = rs[mt][hh];
            v += __shfl_xor_sync(0xffffffffu, v, 1);
            v += __shfl_xor_sync(0xffffffffu, v, 2);
            inv[mt][hh] = 1.0f / v;
        }
    }

    // ---- O = P @ V ----
    float oa[2][4][4];
    #pragma unroll
    for (int mt = 0; mt < 2; mt++)
        #pragma unroll
        for (int nt = 0; nt < 4; nt++)
            #pragma unroll
            for (int c = 0; c < 4; c++) oa[mt][nt][c] = 0.0f;

    #pragma unroll
    for (int ks = 0; ks < 4; ks++) {
        uint32_t pa[2][4];
        #pragma unroll
        for (int mt = 0; mt < 2; mt++) {
            pa[mt][0] = packbf(scf[mt][2*ks  ][0], scf[mt][2*ks  ][1]);
            pa[mt][1] = packbf(scf[mt][2*ks  ][2], scf[mt][2*ks  ][3]);
            pa[mt][2] = packbf(scf[mt][2*ks+1][0], scf[mt][2*ks+1][1]);
            pa[mt][3] = packbf(scf[mt][2*ks+1][2], scf[mt][2*ks+1][3]);
        }
        uint32_t vb[4][2];
        #pragma unroll
        for (int nt = 0; nt < 4; nt++) {
            int n = nt * 8 + g;
            vb[nt][0] = lds32(Vh + n * 72 + ks*16 + 2*tg    );
            vb[nt][1] = lds32(Vh + n * 72 + ks*16 + 2*tg + 8);
        }
        #pragma unroll
        for (int mt = 0; mt < 2; mt++)
            #pragma unroll
            for (int nt = 0; nt < 4; nt++)
                MMA_BF16(oa[mt][nt], pa[mt], vb[nt]);
    }

    // ---- stage normalized O (bf16) into Qs region as Os[64][136] ----
    __syncthreads();   // everyone done reading Qs/Ks/Vt
    __nv_bfloat16* Os = Qs;
    #pragma unroll
    for (int mt = 0; mt < 2; mt++) {
        int ra_ = r0 + mt*16 + g;
        #pragma unroll
        for (int nt = 0; nt < 4; nt++) {
            int c0 = head*32 + nt*8 + 2*tg;
            *(uint32_t*)(Os + ra_*136 + c0)       = packbf(oa[mt][nt][0]*inv[mt][0], oa[mt][nt][1]*inv[mt][0]);
            *(uint32_t*)(Os + (ra_+8)*136 + c0)   = packbf(oa[mt][nt][2]*inv[mt][1], oa[mt][nt][3]*inv[mt][1]);
        }
    }
    cpa_wait<0>();
    __syncthreads();

    // ---- proj: [64x128] = Os[64x128] @ Wp^T ; warp grid 2(M) x 4(N), tile 32x32 ----
    const int pm0 = (wid & 1) * 32;
    const int pn0 = (wid >> 1) * 32;
    float pacc[2][4][4];
    #pragma unroll
    for (int mt = 0; mt < 2; mt++)
        #pragma unroll
        for (int nt = 0; nt < 4; nt++)
            #pragma unroll
            for (int c = 0; c < 4; c++) pacc[mt][nt][c] = 0.0f;

    #pragma unroll
    for (int ks = 0; ks < 8; ks++) {
        const int kk = ks * 16;
        uint32_t a[2][4], b[4][2];
        #pragma unroll
        for (int mt = 0; mt < 2; mt++) {
            int r = pm0 + mt * 16;
            a[mt][0] = lds32(Os + (r + g    ) * 136 + kk + 2*tg    );
            a[mt][1] = lds32(Os + (r + g + 8) * 136 + kk + 2*tg    );
            a[mt][2] = lds32(Os + (r + g    ) * 136 + kk + 2*tg + 8);
            a[mt][3] = lds32(Os + (r + g + 8) * 136 + kk + 2*tg + 8);
        }
        #pragma unroll
        for (int nt = 0; nt < 4; nt++) {
            int n = pn0 + nt * 8 + g;
            b[nt][0] = lds32(Wps + n * 136 + kk + 2*tg    );
            b[nt][1] = lds32(Wps + n * 136 + kk + 2*tg + 8);
        }
        #pragma unroll
        for (int mt = 0; mt < 2; mt++)
            #pragma unroll
            for (int nt = 0; nt < 4; nt++)
                MMA_BF16(pacc[mt][nt], a[mt], b[nt]);
    }
    __syncthreads();   // done reading Wps

    // ---- stage proj result fp32 into Wps region as ps[64][132] ----
    float* ps = (float*)Wps;
    #pragma unroll
    for (int mt = 0; mt < 2; mt++)
        #pragma unroll
        for (int nt = 0; nt < 4; nt++) {
            int r = pm0 + mt * 16;
            int c = pn0 + nt * 8 + tg * 2;
            *(float2*)(ps + (r + g    ) * 132 + c) = make_float2(pacc[mt][nt][0], pacc[mt][nt][1]);
            *(float2*)(ps + (r + g + 8) * 132 + c) = make_float2(pacc[mt][nt][2], pacc[mt][nt][3]);
        }
    __syncthreads();

    // ---- epilogue: residual + window reverse + roll -> g_x1, fused LN2 -> g_xn2 ----
    {
        float4 pb4 = ((const float4*)pb)[lane];
        float4 g4  = ((const float4*)sc2)[lane];
        float4 b4  = ((const float4*)bi2)[lane];
        #pragma unroll
        for (int j = 0; j < 8; j++) {
            int row = wid * 8 + j;
            size_t ob = winrow_to_gmem(win * 64 + row);
            float4 v  = *(const float4*)(ps + row * 132 + lane * 4);
            float4 xv = ((const float4*)(x + ob))[lane];
            float4 x1;
            x1.x = v.x + pb4.x + xv.x;
            x1.y = v.y + pb4.y + xv.y;
            x1.z = v.z + pb4.z + xv.z;
            x1.w = v.w + pb4.w + xv.w;
            ((float4*)(g_x1 + ob))[lane] = x1;
            float s  = x1.x + x1.y + x1.z + x1.w;
            float ss = x1.x*x1.x + x1.y*x1.y + x1.z*x1.z + x1.w*x1.w;
            #pragma unroll
            for (int o = 16; o; o >>= 1) {
                s  += __shfl_xor_sync(0xffffffffu, s,  o);
                ss += __shfl_xor_sync(0xffffffffu, ss, o);
            }
            float mean = s * (1.0f/128.0f);
            float var  = ss * (1.0f/128.0f) - mean*mean;
            float rr = rsqrtf(var + 1e-6f);
            uint2 o2;
            o2.x = packbf((x1.x - mean)*rr*g4.x + b4.x, (x1.y - mean)*rr*g4.y + b4.y);
            o2.y = packbf((x1.z - mean)*rr*g4.z + b4.z, (x1.w - mean)*rr*g4.w + b4.w);
            ((uint2*)(g_xn2 + ob))[lane] = o2;
        }
    }
}

// ---------------- epilogues for MLP GEMMs ----------------
struct Mlp1Epi {
    const float* b1;
    __device__ void apply(const float* st, int row0, int col0, int tid) const {
        #pragma unroll
        for (int i = 0; i < 64; i++) {
            int idx = tid + i * 256;
            int m = row0 + (idx >> 7);
            int n = col0 + (idx & 127);
            float v = st[(idx >> 7) * 132 + (idx & 127)];
            float u = v + b1[n];
            float z2 = 1.5957691216057308f * (u + 0.044715f * u * u * u);
            float sig = 1.0f / (1.0f + __expf(-z2));
            g_hid[(size_t)m * HID + n] = __float2bfloat16(u * sig);
        }
    }
};
struct Mlp2Epi {
    const float* b2; float* out;
    __device__ void apply(const float* st, int row0, int col0, int tid) const {
        #pragma unroll
        for (int i = 0; i < 64; i++) {
            int idx = tid + i * 256;
            int m = row0 + (idx >> 7);
            int n = col0 + (idx & 127);
            size_t o = (size_t)m * CH + n;
            out[o] = st[(idx >> 7) * 132 + (idx & 127)] + b2[n] + g_x1[o];
        }
    }
};

// ---------------- bf16 m16n8k16 GEMM with cp.async double-buffer (MLP) ----------------
template<int KTOT, class Epi>
__global__ __launch_bounds__(256, 2) void gemm_bf16(
    const __nv_bfloat16* __restrict__ A, const __nv_bfloat16* __restrict__ BT, Epi epi)
{
    extern __shared__ char smraw[];
    __nv_bfloat16* sm = (__nv_bfloat16*)smraw;
    const uint32_t smb = smem_u32(smraw);
    const int tid = threadIdx.x;
    const int wid = tid >> 5, lane = tid & 31;
    const int row0 = blockIdx.y * 128, col0 = blockIdx.x * 128;
    const int wm0 = (wid >> 1) * 32, wn0 = (wid & 1) * 64;
    const int g = lane >> 2, tg = lane & 3;

    float acc[2][8][4];
    #pragma unroll
    for (int mt = 0; mt < 2; mt++)
        #pragma unroll
        for (int nt = 0; nt < 8; nt++)
            #pragma unroll
            for (int c = 0; c < 4; c++) acc[mt][nt][c] = 0.0f;

    auto prefetch = [&](int kc, int buf) {
        uint32_t base = smb + (uint32_t)buf * 20480u;
        #pragma unroll
        for (int i = 0; i < 2; i++) {
            int idx = tid + i * 256;
            int r = idx >> 2, c8 = (idx & 3) * 8;
            uint32_t off = (uint32_t)(r * 40 + c8) * 2u;
            cpa16(base + off,          A  + (size_t)(row0 + r) * KTOT + kc * 32 + c8);
            cpa16(base + 10240u + off, BT + (size_t)(col0 + r) * KTOT + kc * 32 + c8);
        }
        cpa_commit();
    };
    auto compute = [&](int buf) {
        const __nv_bfloat16* As_ = sm + buf * 10240;
        const __nv_bfloat16* Bs_ = As_ + 5120;
        #pragma unroll
        for (int ks = 0; ks < 2; ks++) {
            const int kk = ks * 16;
            uint32_t a[2][4], b[8][2];
            #pragma unroll
            for (int mt = 0; mt < 2; mt++) {
                int r = wm0 + mt * 16;
                a[mt][0] = lds32(As_ + (r + g    ) * 40 + kk + 2*tg    );
                a[mt][1] = lds32(As_ + (r + g + 8) * 40 + kk + 2*tg    );
                a[mt][2] = lds32(As_ + (r + g    ) * 40 + kk + 2*tg + 8);
                a[mt][3] = lds32(As_ + (r + g + 8) * 40 + kk + 2*tg + 8);
            }
            #pragma unroll
            for (int nt = 0; nt < 8; nt++) {
                int n = wn0 + nt * 8 + g;
                b[nt][0] = lds32(Bs_ + n * 40 + kk + 2*tg    );
                b[nt][1] = lds32(Bs_ + n * 40 + kk + 2*tg + 8);
            }
            #pragma unroll
            for (int mt = 0; mt < 2; mt++)
                #pragma unroll
                for (int nt = 0; nt < 8; nt++)
                    MMA_BF16(acc[mt][nt], a[mt], b[nt]);
        }
    };

    constexpr int NKC = KTOT / 32;
    prefetch(0, 0);
    #pragma unroll
    for (int kc = 0; kc < NKC; kc++) {
        if (kc + 1 < NKC) {
            prefetch(kc + 1, (kc + 1) & 1);
            cpa_wait<1>();
        } else {
            cpa_wait<0>();
        }
        __syncthreads();
        compute(kc & 1);
        __syncthreads();
    }

    float* st = (float*)smraw;
    #pragma unroll
    for (int mt = 0; mt < 2; mt++)
        #pragma unroll
        for (int nt = 0; nt < 8; nt++) {
            int r = wm0 + mt * 16;
            int c = wn0 + nt * 8 + tg * 2;
            *(float2*)(st + (r + g    ) * 132 + c) = make_float2(acc[mt][nt][0], acc[mt][nt][1]);
            *(float2*)(st + (r + g + 8) * 132 + c) = make_float2(acc[mt][nt][2], acc[mt][nt][3]);
        }
    __syncthreads();
    epi.apply(st, row0, col0, tid);
}

// ---------------- launcher ----------------
extern "C" void kernel_launch(void* const* d_in, const int* in_sizes, int n_in,
                              void* d_out, int out_size)
{
    const float* x       = (const float*)d_in[0];
    const float* mask    = (const float*)d_in[1];
    const float* n1s     = (const float*)d_in[2];
    const float* n1b     = (const float*)d_in[3];
    const float* qkv_w   = (const float*)d_in[4];
    const float* table   = (const float*)d_in[5];
    const float* proj_w  = (const float*)d_in[6];
    const float* proj_b  = (const float*)d_in[7];
    const float* n2s     = (const float*)d_in[8];
    const float* n2b     = (const float*)d_in[9];
    const float* mlp_w1  = (const float*)d_in[10];
    const float* mlp_b1  = (const float*)d_in[11];
    const float* mlp_w2  = (const float*)d_in[12];
    const float* mlp_b2  = (const float*)d_in[13];
    float* out = (float*)d_out;

    __nv_bfloat16 *p_xn2, *p_hid;
    __nv_bfloat16 *p_wqkv_t, *p_wproj_t, *p_w1_t, *p_w2_t;
    cudaGetSymbolAddress((void**)&p_xn2,    g_xn2);
    cudaGetSymbolAddress((void**)&p_hid,    g_hid);
    cudaGetSymbolAddress((void**)&p_wqkv_t, g_wqkv_t);
    cudaGetSymbolAddress((void**)&p_wproj_t,g_wproj_t);
    cudaGetSymbolAddress((void**)&p_w1_t,   g_w1_t);
    cudaGetSymbolAddress((void**)&p_w2_t,   g_w2_t);

    const int QKV_DSM = 2 * 128 * 136 * 2;   // 69632
    cudaFuncSetAttribute(qkv_fused_kernel, cudaFuncAttributeMaxDynamicSharedMemorySize, QKV_DSM);
    const int ATT_DSM = 59392 + 128 * 136 * 2;  // 94208
    cudaFuncSetAttribute(attn_proj_kernel, cudaFuncAttributeMaxDynamicSharedMemorySize, ATT_DSM);
    const int DSM = 67584;
    cudaFuncSetAttribute((void*)gemm_bf16<128, Mlp1Epi>, cudaFuncAttributeMaxDynamicSharedMemorySize, DSM);
    cudaFuncSetAttribute((void*)gemm_bf16<512, Mlp2Epi>, cudaFuncAttributeMaxDynamicSharedMemorySize, DSM);

    const int ROWBLK = (int)(MROWS / 128);  // 2048

    transpose_kernel<<<dim3(12, 4),  dim3(32, 32)>>>(qkv_w,  p_wqkv_t, 128, 384);
    transpose_kernel<<<dim3(4, 4),   dim3(32, 32)>>>(proj_w, p_wproj_t, 128, 128);
    transpose_kernel<<<dim3(16, 4),  dim3(32, 32)>>>(mlp_w1, p_w1_t,   128, 512);
    transpose_kernel<<<dim3(4, 16),  dim3(32, 32)>>>(mlp_w2, p_w2_t,   512, 128);
    bias_kernel<<<64, 64>>>(table);

    // 1. fused LN1 + shift + QKV projection
    qkv_fused_kernel<<<dim3(3, ROWBLK), 256, QKV_DSM>>>(x, n1s, n1b, p_wqkv_t);
    // 2. attention + proj + residual + LN2
    attn_proj_kernel<<<NWIN, 256, ATT_DSM>>>(mask, p_wproj_t, x, proj_b, n2s, n2b);
    // 3. MLP up + GELU
    gemm_bf16<128, Mlp1Epi><<<dim3(4, ROWBLK), 256, DSM>>>(p_xn2, p_w1_t, Mlp1Epi{mlp_b1});
    // 4. MLP down + residual -> out
    gemm_bf16<512, Mlp2Epi><<<dim3(1, ROWBLK), 256, DSM>>>(p_hid, p_w2_t, Mlp2Epi{mlp_b2, out});
}

// round 10
// speedup vs baseline: 3.2815x; 1.1011x over previous
#include <cuda_runtime.h>
#include <cuda_bf16.h>
#include <cstdint>

// ---------------- problem constants ----------------
constexpr int CH = 128, HEADS = 4, HD = 32, NTOK = 64;
constexpr int NWIN = 4096;
constexpr long long MROWS = 262144;   // 4096 windows * 64 tokens
constexpr int HID = 512;

// ---------------- scratch (static device globals) ----------------
__device__ __align__(16) __nv_bfloat16 g_q   [MROWS * CH];
__device__ __align__(16) __nv_bfloat16 g_k   [MROWS * CH];
__device__ __align__(16) __nv_bfloat16 g_v   [MROWS * CH];
__device__ __align__(16) float g_bias[HEADS * NTOK * NTOK];
__device__ __align__(16) float g_x1  [MROWS * CH];
__device__ __align__(16) __nv_bfloat16 g_xn2 [MROWS * CH];
// transposed bf16 weights [N, K]
__device__ __align__(16) __nv_bfloat16 g_wqkv_t[384 * 128];
__device__ __align__(16) __nv_bfloat16 g_wproj_t[128 * 128];
__device__ __align__(16) __nv_bfloat16 g_w1_t  [512 * 128];
__device__ __align__(16) __nv_bfloat16 g_w2_t  [128 * 512];

__device__ __forceinline__ uint32_t packbf(float lo, float hi) {
    __nv_bfloat162 h = __floats2bfloat162_rn(lo, hi);
    return *(uint32_t*)&h;
}
__device__ __forceinline__ uint32_t lds32(const __nv_bfloat16* p) {
    return *(const uint32_t*)p;
}
__device__ __forceinline__ uint32_t smem_u32(const void* p) {
    uint32_t a;
    asm("{ .reg .u64 t; cvta.to.shared.u64 t, %1; cvt.u32.u64 %0, t; }" : "=r"(a) : "l"(p));
    return a;
}
__device__ __forceinline__ void cpa16(uint32_t dst, const void* src) {
    asm volatile("cp.async.cg.shared.global [%0], [%1], 16;" :: "r"(dst), "l"(src));
}
__device__ __forceinline__ void cpa_commit() { asm volatile("cp.async.commit_group;" ::: "memory"); }
template<int N> __device__ __forceinline__ void cpa_wait() {
    asm volatile("cp.async.wait_group %0;" :: "n"(N) : "memory");
}
#define MMA_BF16(acc, a, b) \
    asm volatile("mma.sync.aligned.m16n8k16.row.col.f32.bf16.bf16.f32 " \
        "{%0,%1,%2,%3}, {%4,%5,%6,%7}, {%8,%9}, {%0,%1,%2,%3};" \
        : "+f"((acc)[0]), "+f"((acc)[1]), "+f"((acc)[2]), "+f"((acc)[3]) \
        : "r"((a)[0]), "r"((a)[1]), "r"((a)[2]), "r"((a)[3]), "r"((b)[0]), "r"((b)[1]))

// XOR-swizzled element index for stride-128 bf16 tiles (16B-chunk swizzle)
__device__ __forceinline__ int sw128i(int r, int c) {
    int ch = c >> 3;
    ch = (ch & 8) | ((ch ^ r) & 7);
    return r * 128 + ch * 8 + (c & 7);
}
// XOR-swizzled element index for stride-512 bf16 tiles
__device__ __forceinline__ int sw512i(int r, int c) {
    int ch = c >> 3;
    ch = (ch & ~7) | ((ch ^ r) & 7);
    return r * 512 + ch * 8 + (c & 7);
}

// window mapping: row m -> gmem row base offset (after reverse+roll)
__device__ __forceinline__ size_t winrow_to_gmem(int m) {
    int t = m & 63, win = m >> 6;
    int b = win >> 11, widx = win & 2047;
    int wd = widx >> 8, wh = (widx >> 4) & 15, ww = widx & 15;
    int td = t >> 4, th = (t >> 2) & 3, tw = t & 3;
    int d = (wd*4 + td + 2) & 31;
    int h = (wh*4 + th + 2) & 63;
    int w = (ww*4 + tw + 2) & 63;
    return (size_t)(((b*32 + d)*64 + h)*64 + w) * CH;
}

// ---------------- merged prep: 4 weight transposes + rel-pos bias (one launch) ----------------
__device__ __forceinline__ void transpose_tile(
    const float* src, __nv_bfloat16* dst, int K, int N, int bx, int by, int tid)
{
    __shared__ float tile[32][33];
    int tx = tid & 31, ty = tid >> 5;
    int n0 = bx * 32, k0 = by * 32;
    tile[ty][tx] = src[(size_t)(k0 + ty) * N + n0 + tx];
    __syncthreads();
    dst[(size_t)(n0 + ty) * K + k0 + tx] = __float2bfloat16(tile[tx][ty]);
}
__global__ __launch_bounds__(1024) void prep_kernel(
    const float* __restrict__ qkv_w, const float* __restrict__ proj_w,
    const float* __restrict__ mlp_w1, const float* __restrict__ mlp_w2,
    const float* __restrict__ table)
{
    int b = blockIdx.x, tid = threadIdx.x;
    if (b < 48)       transpose_tile(qkv_w,  g_wqkv_t,  128, 384, b % 12, b / 12, tid);
    else if (b < 64)  { b -= 48;  transpose_tile(proj_w, g_wproj_t, 128, 128, b % 4,  b / 4,  tid); }
    else if (b < 128) { b -= 64;  transpose_tile(mlp_w1, g_w1_t,   128, 512, b % 16, b / 16, tid); }
    else if (b < 192) { b -= 128; transpose_tile(mlp_w2, g_w2_t,   512, 128, b % 4,  b / 4,  tid); }
    else {
        int idx = (b - 192) * 1024 + tid;   // 0..4095 -> (q,k)
        int q = idx >> 6, k = idx & 63;
        int qd = q >> 4, qh = (q >> 2) & 3, qw = q & 3;
        int kd = k >> 4, kh = (k >> 2) & 3, kw = k & 3;
        int ti = (qh - kh + 3) * 49 + (qd - kd + 3) * 7 + (qw - kw + 3);
        #pragma unroll
        for (int h = 0; h < HEADS; h++)
            g_bias[h * 4096 + q * 64 + k] = table[ti * HEADS + h];
    }
}

// ---------------- fused LN1 + QKV GEMM ----------------
__global__ __launch_bounds__(256) void qkv_fused_kernel(
    const float* __restrict__ x, const float* __restrict__ sc, const float* __restrict__ bi,
    const __nv_bfloat16* __restrict__ BT)
{
    extern __shared__ char smraw[];
    __nv_bfloat16* As = (__nv_bfloat16*)smraw;      // [128][136]
    __nv_bfloat16* Bs = As + 128 * 136;             // [128][136]
    const uint32_t smbB = smem_u32(Bs);
    const int tid = threadIdx.x;
    const int wid = tid >> 5, lane = tid & 31;
    const int row0 = blockIdx.y * 128, col0 = blockIdx.x * 128;
    const int wm0 = (wid >> 1) * 32, wn0 = (wid & 1) * 64;
    const int g = lane >> 2, tg = lane & 3;

    #pragma unroll
    for (int i = 0; i < 8; i++) {
        int idx = tid + i * 256;
        int r = idx >> 4, c8 = (idx & 15) * 8;
        cpa16(smbB + (uint32_t)(r * 136 + c8) * 2u, BT + (size_t)(col0 + r) * 128 + c8);
    }
    cpa_commit();

    float4 g4 = ((const float4*)sc)[lane];
    float4 b4 = ((const float4*)bi)[lane];
    #pragma unroll
    for (int i0 = 0; i0 < 16; i0 += 4) {
        float4 v[4];
        int rr[4];
        #pragma unroll
        for (int j = 0; j < 4; j++) {
            rr[j] = wid * 16 + i0 + j;
            v[j] = ((const float4*)(x + winrow_to_gmem(row0 + rr[j])))[lane];
        }
        #pragma unroll
        for (int j = 0; j < 4; j++) {
            float s  = v[j].x + v[j].y + v[j].z + v[j].w;
            float ss = v[j].x*v[j].x + v[j].y*v[j].y + v[j].z*v[j].z + v[j].w*v[j].w;
            #pragma unroll
            for (int o = 16; o; o >>= 1) {
                s  += __shfl_xor_sync(0xffffffffu, s,  o);
                ss += __shfl_xor_sync(0xffffffffu, ss, o);
            }
            float mean = s * (1.0f/128.0f);
            float var  = ss * (1.0f/128.0f) - mean*mean;
            float rq = rsqrtf(var + 1e-6f);
            uint2 o2;
            o2.x = packbf((v[j].x - mean)*rq*g4.x + b4.x, (v[j].y - mean)*rq*g4.y + b4.y);
            o2.y = packbf((v[j].z - mean)*rq*g4.z + b4.z, (v[j].w - mean)*rq*g4.w + b4.w);
            *(uint2*)(As + rr[j] * 136 + lane * 4) = o2;
        }
    }
    cpa_wait<0>();
    __syncthreads();

    float acc[2][8][4];
    #pragma unroll
    for (int mt = 0; mt < 2; mt++)
        #pragma unroll
        for (int nt = 0; nt < 8; nt++)
            #pragma unroll
            for (int c = 0; c < 4; c++) acc[mt][nt][c] = 0.0f;

    #pragma unroll
    for (int ks = 0; ks < 8; ks++) {
        const int kk = ks * 16;
        uint32_t a[2][4], b[8][2];
        #pragma unroll
        for (int mt = 0; mt < 2; mt++) {
            int r = wm0 + mt * 16;
            a[mt][0] = lds32(As + (r + g    ) * 136 + kk + 2*tg    );
            a[mt][1] = lds32(As + (r + g + 8) * 136 + kk + 2*tg    );
            a[mt][2] = lds32(As + (r + g    ) * 136 + kk + 2*tg + 8);
            a[mt][3] = lds32(As + (r + g + 8) * 136 + kk + 2*tg + 8);
        }
        #pragma unroll
        for (int nt = 0; nt < 8; nt++) {
            int n = wn0 + nt * 8 + g;
            b[nt][0] = lds32(Bs + n * 136 + kk + 2*tg    );
            b[nt][1] = lds32(Bs + n * 136 + kk + 2*tg + 8);
        }
        #pragma unroll
        for (int mt = 0; mt < 2; mt++)
            #pragma unroll
            for (int nt = 0; nt < 8; nt++)
                MMA_BF16(acc[mt][nt], a[mt], b[nt]);
    }
    __syncthreads();

    float* st = (float*)smraw;   // 128 x 132
    #pragma unroll
    for (int mt = 0; mt < 2; mt++)
        #pragma unroll
        for (int nt = 0; nt < 8; nt++) {
            int r = wm0 + mt * 16;
            int c = wn0 + nt * 8 + tg * 2;
            *(float2*)(st + (r + g    ) * 132 + c) = make_float2(acc[mt][nt][0], acc[mt][nt][1]);
            *(float2*)(st + (r + g + 8) * 132 + c) = make_float2(acc[mt][nt][2], acc[mt][nt][3]);
        }
    __syncthreads();
    #pragma unroll
    for (int i = 0; i < 64; i++) {
        int idx = tid + i * 256;
        int m = row0 + (idx >> 7);
        int n = col0 + (idx & 127);
        float v = st[(idx >> 7) * 132 + (idx & 127)];
        int sel = n >> 7, c = n & 127;
        int head = c >> 5, e = c & 31;
        int win = m >> 6, t = m & 63;
        size_t o = (((size_t)win * HEADS + head) * NTOK + t) * HD + e;
        if (sel == 0)      g_q[o] = __float2bfloat16(v * 0.17677669529663687f);
        else if (sel == 1) g_k[o] = __float2bfloat16(v);
        else               g_v[o] = __float2bfloat16(v);
    }
}

// ---------------- attention + proj + residual + LN2 (one block per window) ----------------
__global__ __launch_bounds__(256) void attn_proj_kernel(
    const float* __restrict__ mask, const __nv_bfloat16* __restrict__ Wp,
    const float* __restrict__ x, const float* __restrict__ pb,
    const float* __restrict__ sc2, const float* __restrict__ bi2)
{
    extern __shared__ char smraw[];
    __nv_bfloat16* Qs  = (__nv_bfloat16*)smraw;       // [4][64][40] -> later Os [64][136]
    __nv_bfloat16* Ks  = Qs + 10240;
    __nv_bfloat16* Vt  = Ks + 10240;                  // [4][32][72]
    __nv_bfloat16* Wps = (__nv_bfloat16*)(smraw + 59392);  // [128][136] -> later ps [64][132] f32
    const uint32_t smbW = smem_u32(Wps);

    const int win = blockIdx.x;
    const int tid = threadIdx.x;
    const int wid = tid >> 5, lane = tid & 31;
    const int head = wid >> 1;
    const int r0 = (wid & 1) * 32;
    const int g = lane >> 2, tg = lane & 3;

    #pragma unroll
    for (int i = 0; i < 8; i++) {
        int idx = tid + i * 256;
        int r = idx >> 4, c8 = (idx & 15) * 8;
        cpa16(smbW + (uint32_t)(r * 136 + c8) * 2u, Wp + (size_t)r * 128 + c8);
    }
    cpa_commit();

    const uint4* bq = (const uint4*)(g_q + (size_t)win * 8192);
    const uint4* bk = (const uint4*)(g_k + (size_t)win * 8192);
    const uint4* bv = (const uint4*)(g_v + (size_t)win * 8192);
    #pragma unroll
    for (int i = 0; i < 4; i++) {
        int f = tid + i * 256;
        int h = f >> 8;
        int tok = (f >> 2) & 63;
        int q8 = (f & 3) * 8;
        *(uint4*)(Qs + h*2560 + tok*40 + q8) = bq[f];
        *(uint4*)(Ks + h*2560 + tok*40 + q8) = bk[f];
        uint4 vv = bv[f];
        __nv_bfloat16 tmp[8];
        *(uint4*)tmp = vv;
        #pragma unroll
        for (int j = 0; j < 8; j++)
            Vt[h*2304 + (q8 + j)*72 + tok] = tmp[j];
    }
    __syncthreads();

    const __nv_bfloat16* Qh = Qs + head * 2560;
    const __nv_bfloat16* Kh = Ks + head * 2560;
    const __nv_bfloat16* Vh = Vt + head * 2304;

    float scf[2][8][4];
    #pragma unroll
    for (int mt = 0; mt < 2; mt++)
        #pragma unroll
        for (int nt = 0; nt < 8; nt++)
            #pragma unroll
            for (int c = 0; c < 4; c++) scf[mt][nt][c] = 0.0f;

    #pragma unroll
    for (int ks = 0; ks < 2; ks++) {
        const int kk = ks * 16;
        uint32_t a[2][4], b[8][2];
        #pragma unroll
        for (int mt = 0; mt < 2; mt++) {
            int r = r0 + mt * 16;
            a[mt][0] = lds32(Qh + (r + g    ) * 40 + kk + 2*tg    );
            a[mt][1] = lds32(Qh + (r + g + 8) * 40 + kk + 2*tg    );
            a[mt][2] = lds32(Qh + (r + g    ) * 40 + kk + 2*tg + 8);
            a[mt][3] = lds32(Qh + (r + g + 8) * 40 + kk + 2*tg + 8);
        }
        #pragma unroll
        for (int nt = 0; nt < 8; nt++) {
            int n = nt * 8 + g;
            b[nt][0] = lds32(Kh + n * 40 + kk + 2*tg    );
            b[nt][1] = lds32(Kh + n * 40 + kk + 2*tg + 8);
        }
        #pragma unroll
        for (int mt = 0; mt < 2; mt++)
            #pragma unroll
            for (int nt = 0; nt < 8; nt++)
                MMA_BF16(scf[mt][nt], a[mt], b[nt]);
    }

    const float* brow = g_bias + head * 4096;
    const float* mrow = mask + (size_t)(win & 2047) * 4096;
    float rs[2][2] = {{0.f, 0.f}, {0.f, 0.f}};
    #pragma unroll
    for (int mt = 0; mt < 2; mt++) {
        int ra_ = r0 + mt*16 + g, rb_ = ra_ + 8;
        #pragma unroll
        for (int nt = 0; nt < 8; nt++) {
            int c0 = nt*8 + 2*tg;
            float2 ba = *(const float2*)(brow + ra_*64 + c0);
            float2 bb = *(const float2*)(brow + rb_*64 + c0);
            float2 ma = *(const float2*)(mrow + ra_*64 + c0);
            float2 mb = *(const float2*)(mrow + rb_*64 + c0);
            scf[mt][nt][0] = __expf(scf[mt][nt][0] + ba.x + ma.x);
            scf[mt][nt][1] = __expf(scf[mt][nt][1] + ba.y + ma.y);
            scf[mt][nt][2] = __expf(scf[mt][nt][2] + bb.x + mb.x);
            scf[mt][nt][3] = __expf(scf[mt][nt][3] + bb.y + mb.y);
            rs[mt][0] += scf[mt][nt][0] + scf[mt][nt][1];
            rs[mt][1] += scf[mt][nt][2] + scf[mt][nt][3];
        }
    }
    float inv[2][2];
    #pragma unroll
    for (int mt = 0; mt < 2; mt++) {
        #pragma unroll
        for (int hh = 0; hh < 2; hh++) {
            float v = rs[mt][hh];
            v += __shfl_xor_sync(0xffffffffu, v, 1);
            v += __shfl_xor_sync(0xffffffffu, v, 2);
            inv[mt][hh] = 1.0f / v;
        }
    }

    float oa[2][4][4];
    #pragma unroll
    for (int mt = 0; mt < 2; mt++)
        #pragma unroll
        for (int nt = 0; nt < 4; nt++)
            #pragma unroll
            for (int c = 0; c < 4; c++) oa[mt][nt][c] = 0.0f;

    #pragma unroll
    for (int ks = 0; ks < 4; ks++) {
        uint32_t pa[2][4];
        #pragma unroll
        for (int mt = 0; mt < 2; mt++) {
            pa[mt][0] = packbf(scf[mt][2*ks  ][0], scf[mt][2*ks  ][1]);
            pa[mt][1] = packbf(scf[mt][2*ks  ][2], scf[mt][2*ks  ][3]);
            pa[mt][2] = packbf(scf[mt][2*ks+1][0], scf[mt][2*ks+1][1]);
            pa[mt][3] = packbf(scf[mt][2*ks+1][2], scf[mt][2*ks+1][3]);
        }
        uint32_t vb[4][2];
        #pragma unroll
        for (int nt = 0; nt < 4; nt++) {
            int n = nt * 8 + g;
            vb[nt][0] = lds32(Vh + n * 72 + ks*16 + 2*tg    );
            vb[nt][1] = lds32(Vh + n * 72 + ks*16 + 2*tg + 8);
        }
        #pragma unroll
        for (int mt = 0; mt < 2; mt++)
            #pragma unroll
            for (int nt = 0; nt < 4; nt++)
                MMA_BF16(oa[mt][nt], pa[mt], vb[nt]);
    }

    __syncthreads();
    __nv_bfloat16* Os = Qs;
    #pragma unroll
    for (int mt = 0; mt < 2; mt++) {
        int ra_ = r0 + mt*16 + g;
        #pragma unroll
        for (int nt = 0; nt < 4; nt++) {
            int c0 = head*32 + nt*8 + 2*tg;
            *(uint32_t*)(Os + ra_*136 + c0)     = packbf(oa[mt][nt][0]*inv[mt][0], oa[mt][nt][1]*inv[mt][0]);
            *(uint32_t*)(Os + (ra_+8)*136 + c0) = packbf(oa[mt][nt][2]*inv[mt][1], oa[mt][nt][3]*inv[mt][1]);
        }
    }
    cpa_wait<0>();
    __syncthreads();

    const int pm0 = (wid & 1) * 32;
    const int pn0 = (wid >> 1) * 32;
    float pacc[2][4][4];
    #pragma unroll
    for (int mt = 0; mt < 2; mt++)
        #pragma unroll
        for (int nt = 0; nt < 4; nt++)
            #pragma unroll
            for (int c = 0; c < 4; c++) pacc[mt][nt][c] = 0.0f;

    #pragma unroll
    for (int ks = 0; ks < 8; ks++) {
        const int kk = ks * 16;
        uint32_t a[2][4], b[4][2];
        #pragma unroll
        for (int mt = 0; mt < 2; mt++) {
            int r = pm0 + mt * 16;
            a[mt][0] = lds32(Os + (r + g    ) * 136 + kk + 2*tg    );
            a[mt][1] = lds32(Os + (r + g + 8) * 136 + kk + 2*tg    );
            a[mt][2] = lds32(Os + (r + g    ) * 136 + kk + 2*tg + 8);
            a[mt][3] = lds32(Os + (r + g + 8) * 136 + kk + 2*tg + 8);
        }
        #pragma unroll
        for (int nt = 0; nt < 4; nt++) {
            int n = pn0 + nt * 8 + g;
            b[nt][0] = lds32(Wps + n * 136 + kk + 2*tg    );
            b[nt][1] = lds32(Wps + n * 136 + kk + 2*tg + 8);
        }
        #pragma unroll
        for (int mt = 0; mt < 2; mt++)
            #pragma unroll
            for (int nt = 0; nt < 4; nt++)
                MMA_BF16(pacc[mt][nt], a[mt], b[nt]);
    }
    __syncthreads();

    float* ps = (float*)Wps;
    #pragma unroll
    for (int mt = 0; mt < 2; mt++)
        #pragma unroll
        for (int nt = 0; nt < 4; nt++) {
            int r = pm0 + mt * 16;
            int c = pn0 + nt * 8 + tg * 2;
            *(float2*)(ps + (r + g    ) * 132 + c) = make_float2(pacc[mt][nt][0], pacc[mt][nt][1]);
            *(float2*)(ps + (r + g + 8) * 132 + c) = make_float2(pacc[mt][nt][2], pacc[mt][nt][3]);
        }
    __syncthreads();

    {
        float4 pb4 = ((const float4*)pb)[lane];
        float4 g4  = ((const float4*)sc2)[lane];
        float4 b4  = ((const float4*)bi2)[lane];
        #pragma unroll
        for (int j = 0; j < 8; j++) {
            int row = wid * 8 + j;
            size_t ob = winrow_to_gmem(win * 64 + row);
            float4 v  = *(const float4*)(ps + row * 132 + lane * 4);
            float4 xv = ((const float4*)(x + ob))[lane];
            float4 x1;
            x1.x = v.x + pb4.x + xv.x;
            x1.y = v.y + pb4.y + xv.y;
            x1.z = v.z + pb4.z + xv.z;
            x1.w = v.w + pb4.w + xv.w;
            ((float4*)(g_x1 + ob))[lane] = x1;
            float s  = x1.x + x1.y + x1.z + x1.w;
            float ss = x1.x*x1.x + x1.y*x1.y + x1.z*x1.z + x1.w*x1.w;
            #pragma unroll
            for (int o = 16; o; o >>= 1) {
                s  += __shfl_xor_sync(0xffffffffu, s,  o);
                ss += __shfl_xor_sync(0xffffffffu, ss, o);
            }
            float mean = s * (1.0f/128.0f);
            float var  = ss * (1.0f/128.0f) - mean*mean;
            float rr = rsqrtf(var + 1e-6f);
            uint2 o2;
            o2.x = packbf((x1.x - mean)*rr*g4.x + b4.x, (x1.y - mean)*rr*g4.y + b4.y);
            o2.y = packbf((x1.z - mean)*rr*g4.z + b4.z, (x1.w - mean)*rr*g4.w + b4.w);
            ((uint2*)(g_xn2 + ob))[lane] = o2;
        }
    }
}

// ---------------- fused MLP: hidden lives in smem (no g_hid round-trip) ----------------
// grid (2048): one CTA per 128-row block.
// smem: hidS 128x512 bf16 swizzled (131072) + Ats 128x128 sw (32768) + 2x W buf (65536) = 229376
__global__ __launch_bounds__(256) void mlp_fused_kernel(
    const __nv_bfloat16* __restrict__ xn2, const __nv_bfloat16* __restrict__ W1T,
    const float* __restrict__ b1, const __nv_bfloat16* __restrict__ W2T,
    const float* __restrict__ b2, const float* __restrict__ x1g, float* __restrict__ out)
{
    extern __shared__ char smraw[];
    __nv_bfloat16* hidS = (__nv_bfloat16*)smraw;     // 128*512
    __nv_bfloat16* Ats  = hidS + 128 * 512;          // 128*128
    __nv_bfloat16* Wb   = Ats + 128 * 128;           // 2 x 128*128
    const uint32_t smbA = smem_u32(Ats);
    const uint32_t smbW = smem_u32(Wb);
    const int tid = threadIdx.x;
    const int wid = tid >> 5, lane = tid & 31;
    const int row0 = blockIdx.x * 128;
    const int wm0 = (wid >> 1) * 32, wn0 = (wid & 1) * 64;
    const int g = lane >> 2, tg = lane & 3;

    auto stageW = [&](const __nv_bfloat16* src, int ldk, int buf) {
        uint32_t base = smbW + (uint32_t)buf * 32768u;
        #pragma unroll
        for (int i = 0; i < 8; i++) {
            int idx = tid + i * 256;
            int r = idx >> 4, c8 = (idx & 15) * 8;
            cpa16(base + (uint32_t)sw128i(r, c8) * 2u, src + (size_t)r * ldk + c8);
        }
    };

    // prologue: A tile + W1 chunk 0
    #pragma unroll
    for (int i = 0; i < 8; i++) {
        int idx = tid + i * 256;
        int r = idx >> 4, c8 = (idx & 15) * 8;
        cpa16(smbA + (uint32_t)sw128i(r, c8) * 2u, xn2 + (size_t)(row0 + r) * 128 + c8);
    }
    stageW(W1T, 128, 0);
    cpa_commit();

    float acc2[2][8][4];
    #pragma unroll
    for (int mt = 0; mt < 2; mt++)
        #pragma unroll
        for (int nt = 0; nt < 8; nt++)
            #pragma unroll
            for (int c = 0; c < 4; c++) acc2[mt][nt][c] = 0.0f;

    #pragma unroll
    for (int stage = 0; stage < 8; stage++) {
        if (stage + 1 < 8) {
            if (stage + 1 < 4) stageW(W1T + (size_t)(stage + 1) * 128 * 128, 128, (stage + 1) & 1);
            else               stageW(W2T + (size_t)(stage + 1 - 4) * 128,   512, (stage + 1) & 1);
            cpa_commit();
            cpa_wait<1>();
        } else {
            cpa_wait<0>();
        }
        __syncthreads();
        const __nv_bfloat16* Wc = Wb + (stage & 1) * 16384;

        if (stage < 4) {
            // phase A: hid chunk = xn2 @ W1c^T, GELU, -> hidS
            float acc[2][8][4];
            #pragma unroll
            for (int mt = 0; mt < 2; mt++)
                #pragma unroll
                for (int nt = 0; nt < 8; nt++)
                    #pragma unroll
                    for (int c = 0; c < 4; c++) acc[mt][nt][c] = 0.0f;
            #pragma unroll
            for (int ks = 0; ks < 8; ks++) {
                const int kk = ks * 16;
                uint32_t a[2][4], b[8][2];
                #pragma unroll
                for (int mt = 0; mt < 2; mt++) {
                    int r = wm0 + mt * 16;
                    a[mt][0] = lds32(Ats + sw128i(r + g,     kk + 2*tg    ));
                    a[mt][1] = lds32(Ats + sw128i(r + g + 8, kk + 2*tg    ));
                    a[mt][2] = lds32(Ats + sw128i(r + g,     kk + 2*tg + 8));
                    a[mt][3] = lds32(Ats + sw128i(r + g + 8, kk + 2*tg + 8));
                }
                #pragma unroll
                for (int nt = 0; nt < 8; nt++) {
                    int n = wn0 + nt * 8 + g;
                    b[nt][0] = lds32(Wc + sw128i(n, kk + 2*tg    ));
                    b[nt][1] = lds32(Wc + sw128i(n, kk + 2*tg + 8));
                }
                #pragma unroll
                for (int mt = 0; mt < 2; mt++)
                    #pragma unroll
                    for (int nt = 0; nt < 8; nt++)
                        MMA_BF16(acc[mt][nt], a[mt], b[nt]);
            }
            // GELU + bias -> hidS (swizzled)
            #pragma unroll
            for (int mt = 0; mt < 2; mt++) {
                int ra_ = wm0 + mt*16 + g, rb_ = ra_ + 8;
                #pragma unroll
                for (int nt = 0; nt < 8; nt++) {
                    int c0 = wn0 + nt*8 + 2*tg;
                    int n = stage * 128 + c0;
                    float bb0 = b1[n], bb1 = b1[n + 1];
                    float u0 = acc[mt][nt][0] + bb0;
                    float u1 = acc[mt][nt][1] + bb1;
                    float u2 = acc[mt][nt][2] + bb0;
                    float u3 = acc[mt][nt][3] + bb1;
                    float g0 = u0 / (1.0f + __expf(-1.5957691216057308f * (u0 + 0.044715f*u0*u0*u0)));
                    float g1 = u1 / (1.0f + __expf(-1.5957691216057308f * (u1 + 0.044715f*u1*u1*u1)));
                    float g2 = u2 / (1.0f + __expf(-1.5957691216057308f * (u2 + 0.044715f*u2*u2*u2)));
                    float g3 = u3 / (1.0f + __expf(-1.5957691216057308f * (u3 + 0.044715f*u3*u3*u3)));
                    *(uint32_t*)(hidS + sw512i(ra_, n)) = packbf(g0, g1);
                    *(uint32_t*)(hidS + sw512i(rb_, n)) = packbf(g2, g3);
                }
            }
            __syncthreads();
        } else {
            // phase B: out += hid chunk @ W2c^T
            const int kc = stage - 4;
            #pragma unroll
            for (int ks = 0; ks < 8; ks++) {
                const int kk = ks * 16;
                const int kh = kc * 128 + kk;
                uint32_t a[2][4], b[8][2];
                #pragma unroll
                for (int mt = 0; mt < 2; mt++) {
                    int r = wm0 + mt * 16;
                    a[mt][0] = lds32(hidS + sw512i(r + g,     kh + 2*tg    ));
                    a[mt][1] = lds32(hidS + sw512i(r + g + 8, kh + 2*tg    ));
                    a[mt][2] = lds32(hidS + sw512i(r + g,     kh + 2*tg + 8));
                    a[mt][3] = lds32(hidS + sw512i(r + g + 8, kh + 2*tg + 8));
                }
                #pragma unroll
                for (int nt = 0; nt < 8; nt++) {
                    int n = wn0 + nt * 8 + g;
                    b[nt][0] = lds32(Wc + sw128i(n, kk + 2*tg    ));
                    b[nt][1] = lds32(Wc + sw128i(n, kk + 2*tg + 8));
                }
                #pragma unroll
                for (int mt = 0; mt < 2; mt++)
                    #pragma unroll
                    for (int nt = 0; nt < 8; nt++)
                        MMA_BF16(acc2[mt][nt], a[mt], b[nt]);
            }
            __syncthreads();
        }
    }

    // epilogue: stage fp32 into smem (reuse hidS region), residual + bias -> out
    float* st = (float*)smraw;   // 128 x 132
    #pragma unroll
    for (int mt = 0; mt < 2; mt++)
        #pragma unroll
        for (int nt = 0; nt < 8; nt++) {
            int r = wm0 + mt * 16;
            int c = wn0 + nt * 8 + tg * 2;
            *(float2*)(st + (r + g    ) * 132 + c) = make_float2(acc2[mt][nt][0], acc2[mt][nt][1]);
            *(float2*)(st + (r + g + 8) * 132 + c) = make_float2(acc2[mt][nt][2], acc2[mt][nt][3]);
        }
    __syncthreads();
    #pragma unroll
    for (int i = 0; i < 64; i++) {
        int idx = tid + i * 256;
        int m = row0 + (idx >> 7);
        int n = idx & 127;
        size_t o = (size_t)m * CH + n;
        out[o] = st[(idx >> 7) * 132 + n] + b2[n] + x1g[o];
    }
}

// ---------------- launcher ----------------
extern "C" void kernel_launch(void* const* d_in, const int* in_sizes, int n_in,
                              void* d_out, int out_size)
{
    const float* x       = (const float*)d_in[0];
    const float* mask    = (const float*)d_in[1];
    const float* n1s     = (const float*)d_in[2];
    const float* n1b     = (const float*)d_in[3];
    const float* qkv_w   = (const float*)d_in[4];
    const float* table   = (const float*)d_in[5];
    const float* proj_w  = (const float*)d_in[6];
    const float* proj_b  = (const float*)d_in[7];
    const float* n2s     = (const float*)d_in[8];
    const float* n2b     = (const float*)d_in[9];
    const float* mlp_w1  = (const float*)d_in[10];
    const float* mlp_b1  = (const float*)d_in[11];
    const float* mlp_w2  = (const float*)d_in[12];
    const float* mlp_b2  = (const float*)d_in[13];
    float* out = (float*)d_out;

    __nv_bfloat16 *p_xn2;
    float *p_x1;
    __nv_bfloat16 *p_wqkv_t, *p_wproj_t, *p_w1_t, *p_w2_t;
    cudaGetSymbolAddress((void**)&p_xn2,    g_xn2);
    cudaGetSymbolAddress((void**)&p_x1,     g_x1);
    cudaGetSymbolAddress((void**)&p_wqkv_t, g_wqkv_t);
    cudaGetSymbolAddress((void**)&p_wproj_t,g_wproj_t);
    cudaGetSymbolAddress((void**)&p_w1_t,   g_w1_t);
    cudaGetSymbolAddress((void**)&p_w2_t,   g_w2_t);

    const int QKV_DSM = 2 * 128 * 136 * 2;   // 69632
    cudaFuncSetAttribute(qkv_fused_kernel, cudaFuncAttributeMaxDynamicSharedMemorySize, QKV_DSM);
    const int ATT_DSM = 59392 + 128 * 136 * 2;  // 94208
    cudaFuncSetAttribute(attn_proj_kernel, cudaFuncAttributeMaxDynamicSharedMemorySize, ATT_DSM);
    const int MLP_DSM = 131072 + 32768 + 65536;  // 229376
    cudaFuncSetAttribute(mlp_fused_kernel, cudaFuncAttributeMaxDynamicSharedMemorySize, MLP_DSM);

    const int ROWBLK = (int)(MROWS / 128);  // 2048

    // 0. merged prep: weight transposes + relative-position bias
    prep_kernel<<<196, 1024>>>(qkv_w, proj_w, mlp_w1, mlp_w2, table);
    // 1. fused LN1 + shift + QKV projection
    qkv_fused_kernel<<<dim3(3, ROWBLK), 256, QKV_DSM>>>(x, n1s, n1b, p_wqkv_t);
    // 2. attention + proj + residual + LN2
    attn_proj_kernel<<<NWIN, 256, ATT_DSM>>>(mask, p_wproj_t, x, proj_b, n2s, n2b);
    // 3. fused MLP (hidden in smem)
    mlp_fused_kernel<<<ROWBLK, 256, MLP_DSM>>>(p_xn2, p_w1_t, mlp_b1, p_w2_t, mlp_b2, p_x1, out);
}

// round 11
// speedup vs baseline: 4.0406x; 1.2313x over previous
#include <cuda_runtime.h>
#include <cuda_bf16.h>
#include <cstdint>

// ---------------- problem constants ----------------
constexpr int CH = 128, HEADS = 4, HD = 32, NTOK = 64;
constexpr int NWIN = 4096;
constexpr long long MROWS = 262144;   // 4096 windows * 64 tokens
constexpr int HID = 512;

// ---------------- scratch (static device globals) ----------------
__device__ __align__(16) __nv_bfloat16 g_q   [MROWS * CH];
__device__ __align__(16) __nv_bfloat16 g_k   [MROWS * CH];
__device__ __align__(16) __nv_bfloat16 g_v   [MROWS * CH];
__device__ __align__(16) float g_bias[HEADS * NTOK * NTOK];
__device__ __align__(16) float g_x1  [MROWS * CH];
__device__ __align__(16) __nv_bfloat16 g_xn2 [MROWS * CH];
// transposed bf16 weights [N, K]
__device__ __align__(16) __nv_bfloat16 g_wqkv_t[384 * 128];
__device__ __align__(16) __nv_bfloat16 g_wproj_t[128 * 128];
__device__ __align__(16) __nv_bfloat16 g_w1_t  [512 * 128];
__device__ __align__(16) __nv_bfloat16 g_w2_t  [128 * 512];

__device__ __forceinline__ uint32_t packbf(float lo, float hi) {
    __nv_bfloat162 h = __floats2bfloat162_rn(lo, hi);
    return *(uint32_t*)&h;
}
__device__ __forceinline__ uint32_t lds32(const __nv_bfloat16* p) {
    return *(const uint32_t*)p;
}
__device__ __forceinline__ uint32_t smem_u32(const void* p) {
    uint32_t a;
    asm("{ .reg .u64 t; cvta.to.shared.u64 t, %1; cvt.u32.u64 %0, t; }" : "=r"(a) : "l"(p));
    return a;
}
__device__ __forceinline__ void cpa16(uint32_t dst, const void* src) {
    asm volatile("cp.async.cg.shared.global [%0], [%1], 16;" :: "r"(dst), "l"(src));
}
__device__ __forceinline__ void cpa_commit() { asm volatile("cp.async.commit_group;" ::: "memory"); }
template<int N> __device__ __forceinline__ void cpa_wait() {
    asm volatile("cp.async.wait_group %0;" :: "n"(N) : "memory");
}
#define MMA_BF16(acc, a, b) \
    asm volatile("mma.sync.aligned.m16n8k16.row.col.f32.bf16.bf16.f32 " \
        "{%0,%1,%2,%3}, {%4,%5,%6,%7}, {%8,%9}, {%0,%1,%2,%3};" \
        : "+f"((acc)[0]), "+f"((acc)[1]), "+f"((acc)[2]), "+f"((acc)[3]) \
        : "r"((a)[0]), "r"((a)[1]), "r"((a)[2]), "r"((a)[3]), "r"((b)[0]), "r"((b)[1]))

// XOR-swizzled element index for stride-128 bf16 tiles (16B-chunk swizzle)
__device__ __forceinline__ int sw128i(int r, int c) {
    int ch = c >> 3;
    ch = (ch & 8) | ((ch ^ r) & 7);
    return r * 128 + ch * 8 + (c & 7);
}
// XOR-swizzled element index for stride-512 bf16 tiles
__device__ __forceinline__ int sw512i(int r, int c) {
    int ch = c >> 3;
    ch = (ch & ~7) | ((ch ^ r) & 7);
    return r * 512 + ch * 8 + (c & 7);
}

// window mapping: row m -> gmem row base offset (after reverse+roll)
__device__ __forceinline__ size_t winrow_to_gmem(int m) {
    int t = m & 63, win = m >> 6;
    int b = win >> 11, widx = win & 2047;
    int wd = widx >> 8, wh = (widx >> 4) & 15, ww = widx & 15;
    int td = t >> 4, th = (t >> 2) & 3, tw = t & 3;
    int d = (wd*4 + td + 2) & 31;
    int h = (wh*4 + th + 2) & 63;
    int w = (ww*4 + tw + 2) & 63;
    return (size_t)(((b*32 + d)*64 + h)*64 + w) * CH;
}

// ---------------- merged prep: 4 weight transposes + rel-pos bias (one launch) ----------------
__device__ __forceinline__ void transpose_tile(
    const float* src, __nv_bfloat16* dst, int K, int N, int bx, int by, int tid)
{
    __shared__ float tile[32][33];
    int tx = tid & 31, ty = tid >> 5;
    int n0 = bx * 32, k0 = by * 32;
    tile[ty][tx] = src[(size_t)(k0 + ty) * N + n0 + tx];
    __syncthreads();
    dst[(size_t)(n0 + ty) * K + k0 + tx] = __float2bfloat16(tile[tx][ty]);
}
__global__ __launch_bounds__(1024) void prep_kernel(
    const float* __restrict__ qkv_w, const float* __restrict__ proj_w,
    const float* __restrict__ mlp_w1, const float* __restrict__ mlp_w2,
    const float* __restrict__ table)
{
    int b = blockIdx.x, tid = threadIdx.x;
    if (b < 48)       transpose_tile(qkv_w,  g_wqkv_t,  128, 384, b % 12, b / 12, tid);
    else if (b < 64)  { b -= 48;  transpose_tile(proj_w, g_wproj_t, 128, 128, b % 4,  b / 4,  tid); }
    else if (b < 128) { b -= 64;  transpose_tile(mlp_w1, g_w1_t,   128, 512, b % 16, b / 16, tid); }
    else if (b < 192) { b -= 128; transpose_tile(mlp_w2, g_w2_t,   512, 128, b % 4,  b / 4,  tid); }
    else {
        int idx = (b - 192) * 1024 + tid;
        int q = idx >> 6, k = idx & 63;
        int qd = q >> 4, qh = (q >> 2) & 3, qw = q & 3;
        int kd = k >> 4, kh = (k >> 2) & 3, kw = k & 3;
        int ti = (qh - kh + 3) * 49 + (qd - kd + 3) * 7 + (qw - kw + 3);
        #pragma unroll
        for (int h = 0; h < HEADS; h++)
            g_bias[h * 4096 + q * 64 + k] = table[ti * HEADS + h];
    }
}

// ---------------- fused LN1 + QKV GEMM ----------------
__global__ __launch_bounds__(256) void qkv_fused_kernel(
    const float* __restrict__ x, const float* __restrict__ sc, const float* __restrict__ bi,
    const __nv_bfloat16* __restrict__ BT)
{
    extern __shared__ char smraw[];
    __nv_bfloat16* As = (__nv_bfloat16*)smraw;      // [128][136]
    __nv_bfloat16* Bs = As + 128 * 136;             // [128][136]
    const uint32_t smbB = smem_u32(Bs);
    const int tid = threadIdx.x;
    const int wid = tid >> 5, lane = tid & 31;
    const int row0 = blockIdx.y * 128, col0 = blockIdx.x * 128;
    const int wm0 = (wid >> 1) * 32, wn0 = (wid & 1) * 64;
    const int g = lane >> 2, tg = lane & 3;

    #pragma unroll
    for (int i = 0; i < 8; i++) {
        int idx = tid + i * 256;
        int r = idx >> 4, c8 = (idx & 15) * 8;
        cpa16(smbB + (uint32_t)(r * 136 + c8) * 2u, BT + (size_t)(col0 + r) * 128 + c8);
    }
    cpa_commit();

    float4 g4 = ((const float4*)sc)[lane];
    float4 b4 = ((const float4*)bi)[lane];
    #pragma unroll
    for (int i0 = 0; i0 < 16; i0 += 4) {
        float4 v[4];
        int rr[4];
        #pragma unroll
        for (int j = 0; j < 4; j++) {
            rr[j] = wid * 16 + i0 + j;
            v[j] = ((const float4*)(x + winrow_to_gmem(row0 + rr[j])))[lane];
        }
        #pragma unroll
        for (int j = 0; j < 4; j++) {
            float s  = v[j].x + v[j].y + v[j].z + v[j].w;
            float ss = v[j].x*v[j].x + v[j].y*v[j].y + v[j].z*v[j].z + v[j].w*v[j].w;
            #pragma unroll
            for (int o = 16; o; o >>= 1) {
                s  += __shfl_xor_sync(0xffffffffu, s,  o);
                ss += __shfl_xor_sync(0xffffffffu, ss, o);
            }
            float mean = s * (1.0f/128.0f);
            float var  = ss * (1.0f/128.0f) - mean*mean;
            float rq = rsqrtf(var + 1e-6f);
            uint2 o2;
            o2.x = packbf((v[j].x - mean)*rq*g4.x + b4.x, (v[j].y - mean)*rq*g4.y + b4.y);
            o2.y = packbf((v[j].z - mean)*rq*g4.z + b4.z, (v[j].w - mean)*rq*g4.w + b4.w);
            *(uint2*)(As + rr[j] * 136 + lane * 4) = o2;
        }
    }
    cpa_wait<0>();
    __syncthreads();

    float acc[2][8][4];
    #pragma unroll
    for (int mt = 0; mt < 2; mt++)
        #pragma unroll
        for (int nt = 0; nt < 8; nt++)
            #pragma unroll
            for (int c = 0; c < 4; c++) acc[mt][nt][c] = 0.0f;

    #pragma unroll
    for (int ks = 0; ks < 8; ks++) {
        const int kk = ks * 16;
        uint32_t a[2][4], b[8][2];
        #pragma unroll
        for (int mt = 0; mt < 2; mt++) {
            int r = wm0 + mt * 16;
            a[mt][0] = lds32(As + (r + g    ) * 136 + kk + 2*tg    );
            a[mt][1] = lds32(As + (r + g + 8) * 136 + kk + 2*tg    );
            a[mt][2] = lds32(As + (r + g    ) * 136 + kk + 2*tg + 8);
            a[mt][3] = lds32(As + (r + g + 8) * 136 + kk + 2*tg + 8);
        }
        #pragma unroll
        for (int nt = 0; nt < 8; nt++) {
            int n = wn0 + nt * 8 + g;
            b[nt][0] = lds32(Bs + n * 136 + kk + 2*tg    );
            b[nt][1] = lds32(Bs + n * 136 + kk + 2*tg + 8);
        }
        #pragma unroll
        for (int mt = 0; mt < 2; mt++)
            #pragma unroll
            for (int nt = 0; nt < 8; nt++)
                MMA_BF16(acc[mt][nt], a[mt], b[nt]);
    }
    __syncthreads();

    float* st = (float*)smraw;   // 128 x 132
    #pragma unroll
    for (int mt = 0; mt < 2; mt++)
        #pragma unroll
        for (int nt = 0; nt < 8; nt++) {
            int r = wm0 + mt * 16;
            int c = wn0 + nt * 8 + tg * 2;
            *(float2*)(st + (r + g    ) * 132 + c) = make_float2(acc[mt][nt][0], acc[mt][nt][1]);
            *(float2*)(st + (r + g + 8) * 132 + c) = make_float2(acc[mt][nt][2], acc[mt][nt][3]);
        }
    __syncthreads();
    #pragma unroll
    for (int i = 0; i < 64; i++) {
        int idx = tid + i * 256;
        int m = row0 + (idx >> 7);
        int n = col0 + (idx & 127);
        float v = st[(idx >> 7) * 132 + (idx & 127)];
        int sel = n >> 7, c = n & 127;
        int head = c >> 5, e = c & 31;
        int win = m >> 6, t = m & 63;
        size_t o = (((size_t)win * HEADS + head) * NTOK + t) * HD + e;
        if (sel == 0)      g_q[o] = __float2bfloat16(v * 0.17677669529663687f);
        else if (sel == 1) g_k[o] = __float2bfloat16(v);
        else               g_v[o] = __float2bfloat16(v);
    }
}

// ---------------- attention + proj + residual + LN2 (one block per window) ----------------
__global__ __launch_bounds__(256) void attn_proj_kernel(
    const float* __restrict__ mask, const __nv_bfloat16* __restrict__ Wp,
    const float* __restrict__ x, const float* __restrict__ pb,
    const float* __restrict__ sc2, const float* __restrict__ bi2)
{
    extern __shared__ char smraw[];
    __nv_bfloat16* Qs  = (__nv_bfloat16*)smraw;       // [4][64][40] -> later Os [64][136]
    __nv_bfloat16* Ks  = Qs + 10240;
    __nv_bfloat16* Vt  = Ks + 10240;                  // [4][32][72]
    __nv_bfloat16* Wps = (__nv_bfloat16*)(smraw + 59392);  // [128][136] -> later ps [64][132] f32
    const uint32_t smbW = smem_u32(Wps);

    const int win = blockIdx.x;
    const int tid = threadIdx.x;
    const int wid = tid >> 5, lane = tid & 31;
    const int head = wid >> 1;
    const int r0 = (wid & 1) * 32;
    const int g = lane >> 2, tg = lane & 3;

    #pragma unroll
    for (int i = 0; i < 8; i++) {
        int idx = tid + i * 256;
        int r = idx >> 4, c8 = (idx & 15) * 8;
        cpa16(smbW + (uint32_t)(r * 136 + c8) * 2u, Wp + (size_t)r * 128 + c8);
    }
    cpa_commit();

    const uint4* bq = (const uint4*)(g_q + (size_t)win * 8192);
    const uint4* bk = (const uint4*)(g_k + (size_t)win * 8192);
    const uint4* bv = (const uint4*)(g_v + (size_t)win * 8192);
    #pragma unroll
    for (int i = 0; i < 4; i++) {
        int f = tid + i * 256;
        int h = f >> 8;
        int tok = (f >> 2) & 63;
        int q8 = (f & 3) * 8;
        *(uint4*)(Qs + h*2560 + tok*40 + q8) = bq[f];
        *(uint4*)(Ks + h*2560 + tok*40 + q8) = bk[f];
        uint4 vv = bv[f];
        __nv_bfloat16 tmp[8];
        *(uint4*)tmp = vv;
        #pragma unroll
        for (int j = 0; j < 8; j++)
            Vt[h*2304 + (q8 + j)*72 + tok] = tmp[j];
    }
    __syncthreads();

    const __nv_bfloat16* Qh = Qs + head * 2560;
    const __nv_bfloat16* Kh = Ks + head * 2560;
    const __nv_bfloat16* Vh = Vt + head * 2304;

    float scf[2][8][4];
    #pragma unroll
    for (int mt = 0; mt < 2; mt++)
        #pragma unroll
        for (int nt = 0; nt < 8; nt++)
            #pragma unroll
            for (int c = 0; c < 4; c++) scf[mt][nt][c] = 0.0f;

    #pragma unroll
    for (int ks = 0; ks < 2; ks++) {
        const int kk = ks * 16;
        uint32_t a[2][4], b[8][2];
        #pragma unroll
        for (int mt = 0; mt < 2; mt++) {
            int r = r0 + mt * 16;
            a[mt][0] = lds32(Qh + (r + g    ) * 40 + kk + 2*tg    );
            a[mt][1] = lds32(Qh + (r + g + 8) * 40 + kk + 2*tg    );
            a[mt][2] = lds32(Qh + (r + g    ) * 40 + kk + 2*tg + 8);
            a[mt][3] = lds32(Qh + (r + g + 8) * 40 + kk + 2*tg + 8);
        }
        #pragma unroll
        for (int nt = 0; nt < 8; nt++) {
            int n = nt * 8 + g;
            b[nt][0] = lds32(Kh + n * 40 + kk + 2*tg    );
            b[nt][1] = lds32(Kh + n * 40 + kk + 2*tg + 8);
        }
        #pragma unroll
        for (int mt = 0; mt < 2; mt++)
            #pragma unroll
            for (int nt = 0; nt < 8; nt++)
                MMA_BF16(scf[mt][nt], a[mt], b[nt]);
    }

    const float* brow = g_bias + head * 4096;
    const float* mrow = mask + (size_t)(win & 2047) * 4096;
    float rs[2][2] = {{0.f, 0.f}, {0.f, 0.f}};
    #pragma unroll
    for (int mt = 0; mt < 2; mt++) {
        int ra_ = r0 + mt*16 + g, rb_ = ra_ + 8;
        #pragma unroll
        for (int nt = 0; nt < 8; nt++) {
            int c0 = nt*8 + 2*tg;
            float2 ba = *(const float2*)(brow + ra_*64 + c0);
            float2 bb = *(const float2*)(brow + rb_*64 + c0);
            float2 ma = *(const float2*)(mrow + ra_*64 + c0);
            float2 mb = *(const float2*)(mrow + rb_*64 + c0);
            scf[mt][nt][0] = __expf(scf[mt][nt][0] + ba.x + ma.x);
            scf[mt][nt][1] = __expf(scf[mt][nt][1] + ba.y + ma.y);
            scf[mt][nt][2] = __expf(scf[mt][nt][2] + bb.x + mb.x);
            scf[mt][nt][3] = __expf(scf[mt][nt][3] + bb.y + mb.y);
            rs[mt][0] += scf[mt][nt][0] + scf[mt][nt][1];
            rs[mt][1] += scf[mt][nt][2] + scf[mt][nt][3];
        }
    }
    float inv[2][2];
    #pragma unroll
    for (int mt = 0; mt < 2; mt++) {
        #pragma unroll
        for (int hh = 0; hh < 2; hh++) {
            float v = rs[mt][hh];
            v += __shfl_xor_sync(0xffffffffu, v, 1);
            v += __shfl_xor_sync(0xffffffffu, v, 2);
            inv[mt][hh] = 1.0f / v;
        }
    }

    float oa[2][4][4];
    #pragma unroll
    for (int mt = 0; mt < 2; mt++)
        #pragma unroll
        for (int nt = 0; nt < 4; nt++)
            #pragma unroll
            for (int c = 0; c < 4; c++) oa[mt][nt][c] = 0.0f;

    #pragma unroll
    for (int ks = 0; ks < 4; ks++) {
        uint32_t pa[2][4];
        #pragma unroll
        for (int mt = 0; mt < 2; mt++) {
            pa[mt][0] = packbf(scf[mt][2*ks  ][0], scf[mt][2*ks  ][1]);
            pa[mt][1] = packbf(scf[mt][2*ks  ][2], scf[mt][2*ks  ][3]);
            pa[mt][2] = packbf(scf[mt][2*ks+1][0], scf[mt][2*ks+1][1]);
            pa[mt][3] = packbf(scf[mt][2*ks+1][2], scf[mt][2*ks+1][3]);
        }
        uint32_t vb[4][2];
        #pragma unroll
        for (int nt = 0; nt < 4; nt++) {
            int n = nt * 8 + g;
            vb[nt][0] = lds32(Vh + n * 72 + ks*16 + 2*tg    );
            vb[nt][1] = lds32(Vh + n * 72 + ks*16 + 2*tg + 8);
        }
        #pragma unroll
        for (int mt = 0; mt < 2; mt++)
            #pragma unroll
            for (int nt = 0; nt < 4; nt++)
                MMA_BF16(oa[mt][nt], pa[mt], vb[nt]);
    }

    __syncthreads();
    __nv_bfloat16* Os = Qs;
    #pragma unroll
    for (int mt = 0; mt < 2; mt++) {
        int ra_ = r0 + mt*16 + g;
        #pragma unroll
        for (int nt = 0; nt < 4; nt++) {
            int c0 = head*32 + nt*8 + 2*tg;
            *(uint32_t*)(Os + ra_*136 + c0)     = packbf(oa[mt][nt][0]*inv[mt][0], oa[mt][nt][1]*inv[mt][0]);
            *(uint32_t*)(Os + (ra_+8)*136 + c0) = packbf(oa[mt][nt][2]*inv[mt][1], oa[mt][nt][3]*inv[mt][1]);
        }
    }
    cpa_wait<0>();
    __syncthreads();

    const int pm0 = (wid & 1) * 32;
    const int pn0 = (wid >> 1) * 32;
    float pacc[2][4][4];
    #pragma unroll
    for (int mt = 0; mt < 2; mt++)
        #pragma unroll
        for (int nt = 0; nt < 4; nt++)
            #pragma unroll
            for (int c = 0; c < 4; c++) pacc[mt][nt][c] = 0.0f;

    #pragma unroll
    for (int ks = 0; ks < 8; ks++) {
        const int kk = ks * 16;
        uint32_t a[2][4], b[4][2];
        #pragma unroll
        for (int mt = 0; mt < 2; mt++) {
            int r = pm0 + mt * 16;
            a[mt][0] = lds32(Os + (r + g    ) * 136 + kk + 2*tg    );
            a[mt][1] = lds32(Os + (r + g + 8) * 136 + kk + 2*tg    );
            a[mt][2] = lds32(Os + (r + g    ) * 136 + kk + 2*tg + 8);
            a[mt][3] = lds32(Os + (r + g + 8) * 136 + kk + 2*tg + 8);
        }
        #pragma unroll
        for (int nt = 0; nt < 4; nt++) {
            int n = pn0 + nt * 8 + g;
            b[nt][0] = lds32(Wps + n * 136 + kk + 2*tg    );
            b[nt][1] = lds32(Wps + n * 136 + kk + 2*tg + 8);
        }
        #pragma unroll
        for (int mt = 0; mt < 2; mt++)
            #pragma unroll
            for (int nt = 0; nt < 4; nt++)
                MMA_BF16(pacc[mt][nt], a[mt], b[nt]);
    }
    __syncthreads();

    float* ps = (float*)Wps;
    #pragma unroll
    for (int mt = 0; mt < 2; mt++)
        #pragma unroll
        for (int nt = 0; nt < 4; nt++) {
            int r = pm0 + mt * 16;
            int c = pn0 + nt * 8 + tg * 2;
            *(float2*)(ps + (r + g    ) * 132 + c) = make_float2(pacc[mt][nt][0], pacc[mt][nt][1]);
            *(float2*)(ps + (r + g + 8) * 132 + c) = make_float2(pacc[mt][nt][2], pacc[mt][nt][3]);
        }
    __syncthreads();

    {
        float4 pb4 = ((const float4*)pb)[lane];
        float4 g4  = ((const float4*)sc2)[lane];
        float4 b4  = ((const float4*)bi2)[lane];
        #pragma unroll
        for (int j = 0; j < 8; j++) {
            int row = wid * 8 + j;
            size_t ob = winrow_to_gmem(win * 64 + row);
            float4 v  = *(const float4*)(ps + row * 132 + lane * 4);
            float4 xv = ((const float4*)(x + ob))[lane];
            float4 x1;
            x1.x = v.x + pb4.x + xv.x;
            x1.y = v.y + pb4.y + xv.y;
            x1.z = v.z + pb4.z + xv.z;
            x1.w = v.w + pb4.w + xv.w;
            ((float4*)(g_x1 + ob))[lane] = x1;
            float s  = x1.x + x1.y + x1.z + x1.w;
            float ss = x1.x*x1.x + x1.y*x1.y + x1.z*x1.z + x1.w*x1.w;
            #pragma unroll
            for (int o = 16; o; o >>= 1) {
                s  += __shfl_xor_sync(0xffffffffu, s,  o);
                ss += __shfl_xor_sync(0xffffffffu, ss, o);
            }
            float mean = s * (1.0f/128.0f);
            float var  = ss * (1.0f/128.0f) - mean*mean;
            float rr = rsqrtf(var + 1e-6f);
            uint2 o2;
            o2.x = packbf((x1.x - mean)*rr*g4.x + b4.x, (x1.y - mean)*rr*g4.y + b4.y);
            o2.y = packbf((x1.z - mean)*rr*g4.z + b4.z, (x1.w - mean)*rr*g4.w + b4.w);
            ((uint2*)(g_xn2 + ob))[lane] = o2;
        }
    }
}

// ---------------- fused MLP (16 warps, warp tile 32x32): hidden in smem ----------------
// grid (2048) x 512 threads. smem: hidS 128x512 bf16 sw (131072) + Ats 128x128 sw (32768)
// + 2x W buf (65536) = 229376.
__global__ __launch_bounds__(512) void mlp_fused_kernel(
    const __nv_bfloat16* __restrict__ xn2, const __nv_bfloat16* __restrict__ W1T,
    const float* __restrict__ b1, const __nv_bfloat16* __restrict__ W2T,
    const float* __restrict__ b2, const float* __restrict__ x1g, float* __restrict__ out)
{
    extern __shared__ char smraw[];
    __nv_bfloat16* hidS = (__nv_bfloat16*)smraw;     // 128*512
    __nv_bfloat16* Ats  = hidS + 128 * 512;          // 128*128
    __nv_bfloat16* Wb   = Ats + 128 * 128;           // 2 x 128*128
    const uint32_t smbA = smem_u32(Ats);
    const uint32_t smbW = smem_u32(Wb);
    const int tid = threadIdx.x;
    const int wid = tid >> 5, lane = tid & 31;
    const int row0 = blockIdx.x * 128;
    const int wm0 = (wid >> 2) * 32;     // 4 M groups
    const int wn0 = (wid & 3) * 32;      // 4 N groups
    const int g = lane >> 2, tg = lane & 3;

    auto stageW = [&](const __nv_bfloat16* src, int ldk, int buf) {
        uint32_t base = smbW + (uint32_t)buf * 32768u;
        #pragma unroll
        for (int i = 0; i < 4; i++) {
            int idx = tid + i * 512;
            int r = idx >> 4, c8 = (idx & 15) * 8;
            cpa16(base + (uint32_t)sw128i(r, c8) * 2u, src + (size_t)r * ldk + c8);
        }
    };

    // prologue: A tile + W1 chunk 0
    #pragma unroll
    for (int i = 0; i < 4; i++) {
        int idx = tid + i * 512;
        int r = idx >> 4, c8 = (idx & 15) * 8;
        cpa16(smbA + (uint32_t)sw128i(r, c8) * 2u, xn2 + (size_t)(row0 + r) * 128 + c8);
    }
    stageW(W1T, 128, 0);
    cpa_commit();

    float acc2[2][4][4];
    #pragma unroll
    for (int mt = 0; mt < 2; mt++)
        #pragma unroll
        for (int nt = 0; nt < 4; nt++)
            #pragma unroll
            for (int c = 0; c < 4; c++) acc2[mt][nt][c] = 0.0f;

    #pragma unroll
    for (int stage = 0; stage < 8; stage++) {
        if (stage + 1 < 8) {
            if (stage + 1 < 4) stageW(W1T + (size_t)(stage + 1) * 128 * 128, 128, (stage + 1) & 1);
            else               stageW(W2T + (size_t)(stage + 1 - 4) * 128,   512, (stage + 1) & 1);
            cpa_commit();
            cpa_wait<1>();
        } else {
            cpa_wait<0>();
        }
        __syncthreads();
        const __nv_bfloat16* Wc = Wb + (stage & 1) * 16384;

        if (stage < 4) {
            // phase A: hid chunk = xn2 @ W1c^T, GELU -> hidS
            float acc[2][4][4];
            #pragma unroll
            for (int mt = 0; mt < 2; mt++)
                #pragma unroll
                for (int nt = 0; nt < 4; nt++)
                    #pragma unroll
                    for (int c = 0; c < 4; c++) acc[mt][nt][c] = 0.0f;
            #pragma unroll
            for (int ks = 0; ks < 8; ks++) {
                const int kk = ks * 16;
                uint32_t a[2][4], b[4][2];
                #pragma unroll
                for (int mt = 0; mt < 2; mt++) {
                    int r = wm0 + mt * 16;
                    a[mt][0] = lds32(Ats + sw128i(r + g,     kk + 2*tg    ));
                    a[mt][1] = lds32(Ats + sw128i(r + g + 8, kk + 2*tg    ));
                    a[mt][2] = lds32(Ats + sw128i(r + g,     kk + 2*tg + 8));
                    a[mt][3] = lds32(Ats + sw128i(r + g + 8, kk + 2*tg + 8));
                }
                #pragma unroll
                for (int nt = 0; nt < 4; nt++) {
                    int n = wn0 + nt * 8 + g;
                    b[nt][0] = lds32(Wc + sw128i(n, kk + 2*tg    ));
                    b[nt][1] = lds32(Wc + sw128i(n, kk + 2*tg + 8));
                }
                #pragma unroll
                for (int mt = 0; mt < 2; mt++)
                    #pragma unroll
                    for (int nt = 0; nt < 4; nt++)
                        MMA_BF16(acc[mt][nt], a[mt], b[nt]);
            }
            // GELU + bias -> hidS (swizzled)
            #pragma unroll
            for (int mt = 0; mt < 2; mt++) {
                int ra_ = wm0 + mt*16 + g, rb_ = ra_ + 8;
                #pragma unroll
                for (int nt = 0; nt < 4; nt++) {
                    int c0 = wn0 + nt*8 + 2*tg;
                    int n = stage * 128 + c0;
                    float bb0 = b1[n], bb1 = b1[n + 1];
                    float u0 = acc[mt][nt][0] + bb0;
                    float u1 = acc[mt][nt][1] + bb1;
                    float u2 = acc[mt][nt][2] + bb0;
                    float u3 = acc[mt][nt][3] + bb1;
                    float g0 = u0 / (1.0f + __expf(-1.5957691216057308f * (u0 + 0.044715f*u0*u0*u0)));
                    float g1 = u1 / (1.0f + __expf(-1.5957691216057308f * (u1 + 0.044715f*u1*u1*u1)));
                    float g2 = u2 / (1.0f + __expf(-1.5957691216057308f * (u2 + 0.044715f*u2*u2*u2)));
                    float g3 = u3 / (1.0f + __expf(-1.5957691216057308f * (u3 + 0.044715f*u3*u3*u3)));
                    *(uint32_t*)(hidS + sw512i(ra_, n)) = packbf(g0, g1);
                    *(uint32_t*)(hidS + sw512i(rb_, n)) = packbf(g2, g3);
                }
            }
            __syncthreads();
        } else {
            // phase B: out += hid chunk @ W2c^T
            const int kc = stage - 4;
            #pragma unroll
            for (int ks = 0; ks < 8; ks++) {
                const int kk = ks * 16;
                const int kh = kc * 128 + kk;
                uint32_t a[2][4], b[4][2];
                #pragma unroll
                for (int mt = 0; mt < 2; mt++) {
                    int r = wm0 + mt * 16;
                    a[mt][0] = lds32(hidS + sw512i(r + g,     kh + 2*tg    ));
                    a[mt][1] = lds32(hidS + sw512i(r + g + 8, kh + 2*tg    ));
                    a[mt][2] = lds32(hidS + sw512i(r + g,     kh + 2*tg + 8));
                    a[mt][3] = lds32(hidS + sw512i(r + g + 8, kh + 2*tg + 8));
                }
                #pragma unroll
                for (int nt = 0; nt < 4; nt++) {
                    int n = wn0 + nt * 8 + g;
                    b[nt][0] = lds32(Wc + sw128i(n, kk + 2*tg    ));
                    b[nt][1] = lds32(Wc + sw128i(n, kk + 2*tg + 8));
                }
                #pragma unroll
                for (int mt = 0; mt < 2; mt++)
                    #pragma unroll
                    for (int nt = 0; nt < 4; nt++)
                        MMA_BF16(acc2[mt][nt], a[mt], b[nt]);
            }
            __syncthreads();
        }
    }

    // epilogue: stage fp32 into smem (reuse hidS region), residual + bias -> out
    float* st = (float*)smraw;   // 128 x 132
    #pragma unroll
    for (int mt = 0; mt < 2; mt++)
        #pragma unroll
        for (int nt = 0; nt < 4; nt++) {
            int r = wm0 + mt * 16;
            int c = wn0 + nt * 8 + tg * 2;
            *(float2*)(st + (r + g    ) * 132 + c) = make_float2(acc2[mt][nt][0], acc2[mt][nt][1]);
            *(float2*)(st + (r + g + 8) * 132 + c) = make_float2(acc2[mt][nt][2], acc2[mt][nt][3]);
        }
    __syncthreads();
    #pragma unroll
    for (int i = 0; i < 32; i++) {
        int idx = tid + i * 512;
        int m = row0 + (idx >> 7);
        int n = idx & 127;
        size_t o = (size_t)m * CH + n;
        out[o] = st[(idx >> 7) * 132 + n] + b2[n] + x1g[o];
    }
}

// ---------------- launcher ----------------
extern "C" void kernel_launch(void* const* d_in, const int* in_sizes, int n_in,
                              void* d_out, int out_size)
{
    const float* x       = (const float*)d_in[0];
    const float* mask    = (const float*)d_in[1];
    const float* n1s     = (const float*)d_in[2];
    const float* n1b     = (const float*)d_in[3];
    const float* qkv_w   = (const float*)d_in[4];
    const float* table   = (const float*)d_in[5];
    const float* proj_w  = (const float*)d_in[6];
    const float* proj_b  = (const float*)d_in[7];
    const float* n2s     = (const float*)d_in[8];
    const float* n2b     = (const float*)d_in[9];
    const float* mlp_w1  = (const float*)d_in[10];
    const float* mlp_b1  = (const float*)d_in[11];
    const float* mlp_w2  = (const float*)d_in[12];
    const float* mlp_b2  = (const float*)d_in[13];
    float* out = (float*)d_out;

    __nv_bfloat16 *p_xn2;
    float *p_x1;
    __nv_bfloat16 *p_wqkv_t, *p_wproj_t, *p_w1_t, *p_w2_t;
    cudaGetSymbolAddress((void**)&p_xn2,    g_xn2);
    cudaGetSymbolAddress((void**)&p_x1,     g_x1);
    cudaGetSymbolAddress((void**)&p_wqkv_t, g_wqkv_t);
    cudaGetSymbolAddress((void**)&p_wproj_t,g_wproj_t);
    cudaGetSymbolAddress((void**)&p_w1_t,   g_w1_t);
    cudaGetSymbolAddress((void**)&p_w2_t,   g_w2_t);

    const int QKV_DSM = 2 * 128 * 136 * 2;   // 69632
    cudaFuncSetAttribute(qkv_fused_kernel, cudaFuncAttributeMaxDynamicSharedMemorySize, QKV_DSM);
    const int ATT_DSM = 59392 + 128 * 136 * 2;  // 94208
    cudaFuncSetAttribute(attn_proj_kernel, cudaFuncAttributeMaxDynamicSharedMemorySize, ATT_DSM);
    const int MLP_DSM = 131072 + 32768 + 65536;  // 229376
    cudaFuncSetAttribute(mlp_fused_kernel, cudaFuncAttributeMaxDynamicSharedMemorySize, MLP_DSM);

    const int ROWBLK = (int)(MROWS / 128);  // 2048

    // 0. merged prep
    prep_kernel<<<196, 1024>>>(qkv_w, proj_w, mlp_w1, mlp_w2, table);
    // 1. fused LN1 + shift + QKV projection
    qkv_fused_kernel<<<dim3(3, ROWBLK), 256, QKV_DSM>>>(x, n1s, n1b, p_wqkv_t);
    // 2. attention + proj + residual + LN2
    attn_proj_kernel<<<NWIN, 256, ATT_DSM>>>(mask, p_wproj_t, x, proj_b, n2s, n2b);
    // 3. fused MLP (hidden in smem, 16 warps)
    mlp_fused_kernel<<<ROWBLK, 512, MLP_DSM>>>(p_xn2, p_w1_t, mlp_b1, p_w2_t, mlp_b2, p_x1, out);
}